// round 8
// baseline (speedup 1.0000x reference)
#include <cuda_runtime.h>
#include <cuda_bf16.h>
#include <math.h>
#include <stdint.h>

// ---------------------------------------------------------------------------
// Problem constants (B=2, N=2048, C=1024, H=16, R1=4, R2=8, HEAD_DIM=64)
// ---------------------------------------------------------------------------
#define BATCH 2
#define SEQ   2048
#define CH    1024
#define NH    16
#define RR1   4
#define RR2   8
#define HD    64
#define RKD   32
#define MROWS (BATCH*SEQ)     // 4096
#define PROJC 384
#define BH    (BATCH*NH)      // 32

#define L2E  1.44269504088896341f
__device__ __constant__ float kQSCALE = 0.17677669529663687f * 1.44269504088896341f;

// ---------------------------------------------------------------------------
// Scratch
// ---------------------------------------------------------------------------
__device__ __nv_bfloat16 g_xh [MROWS * CH];
__device__ __nv_bfloat16 g_xl [MROWS * CH];
__device__ __nv_bfloat16 g_wch[PROJC * CH];
__device__ __nv_bfloat16 g_wcl[PROJC * CH];
__device__ __nv_bfloat16 g_wvh[CH * CH];
__device__ __nv_bfloat16 g_wvl[CH * CH];
__device__ __nv_bfloat16 g_woh[CH * CH];
__device__ __nv_bfloat16 g_wol[CH * CH];
__device__ __nv_bfloat16 g_aoh[MROWS * CH];
__device__ __nv_bfloat16 g_aol[MROWS * CH];

__device__ float g_proj[MROWS * PROJC];
__device__ float g_v  [MROWS * CH];

__device__ __nv_bfloat16 g_qkh[(size_t)BH * SEQ * RKD];
__device__ __nv_bfloat16 g_qkl[(size_t)BH * SEQ * RKD];
__device__ __nv_bfloat16 g_kkh[(size_t)BH * SEQ * RKD];
__device__ __nv_bfloat16 g_kkl[(size_t)BH * SEQ * RKD];
__device__ __nv_bfloat16 g_vth[(size_t)BH * HD * SEQ];
__device__ __nv_bfloat16 g_vtl[(size_t)BH * HD * SEQ];

// ---------------------------------------------------------------------------
// Helpers
// ---------------------------------------------------------------------------
__device__ __forceinline__ uint32_t smem_u32(const void* p) {
    uint32_t a;
    asm("{ .reg .u64 t; cvta.to.shared.u64 t, %1; cvt.u32.u64 %0, t; }"
        : "=r"(a) : "l"(p));
    return a;
}

__device__ __forceinline__ void ldsm_x4(uint32_t addr, uint32_t& r0, uint32_t& r1,
                                        uint32_t& r2, uint32_t& r3) {
    asm volatile("ldmatrix.sync.aligned.m8n8.x4.shared.b16 {%0,%1,%2,%3}, [%4];"
                 : "=r"(r0), "=r"(r1), "=r"(r2), "=r"(r3) : "r"(addr));
}

__device__ __forceinline__ void mma16816(float* c, uint32_t a0, uint32_t a1,
                                         uint32_t a2, uint32_t a3,
                                         uint32_t b0, uint32_t b1) {
    asm volatile(
        "mma.sync.aligned.m16n8k16.row.col.f32.bf16.bf16.f32 "
        "{%0,%1,%2,%3}, {%4,%5,%6,%7}, {%8,%9}, {%0,%1,%2,%3};"
        : "+f"(c[0]), "+f"(c[1]), "+f"(c[2]), "+f"(c[3])
        : "r"(a0), "r"(a1), "r"(a2), "r"(a3), "r"(b0), "r"(b1));
}

__device__ __forceinline__ uint32_t pack_bf16(float x, float y) {
    __nv_bfloat162 t = __floats2bfloat162_rn(x, y);
    return *reinterpret_cast<uint32_t*>(&t);
}

#define CP16(sm, gp) \
    asm volatile("cp.async.cg.shared.global [%0], [%1], 16;" \
                 :: "r"(sm), "l"(gp) : "memory")
#define CP_COMMIT() asm volatile("cp.async.commit_group;" ::: "memory")
#define CP_WAIT0()  asm volatile("cp.async.wait_group 0;" ::: "memory")
#define CP_WAIT1()  asm volatile("cp.async.wait_group 1;" ::: "memory")

// ---------------------------------------------------------------------------
// Split fp32 -> bf16 hi/lo
// ---------------------------------------------------------------------------
__global__ void split_kernel(const float* __restrict__ src,
                             __nv_bfloat16* __restrict__ hi,
                             __nv_bfloat16* __restrict__ lo, int n)
{
    int i = blockIdx.x * blockDim.x + threadIdx.x;
    if (i < n) {
        float v = src[i];
        __nv_bfloat16 h = __float2bfloat16(v);
        hi[i] = h;
        lo[i] = __float2bfloat16(v - __bfloat162float(h));
    }
}

// ---------------------------------------------------------------------------
// bf16x3 NT GEMM, cp.async double-buffered.
// Dynamic smem: 2 buffers x 4 operand tiles x 10240 B = 81920 B.
// ---------------------------------------------------------------------------
#define TM 128
#define TN 128
#define TKC 32
#define GT 256
#define SPAD 40
#define OPB   10240u            // one operand tile bytes (128*40*2)
#define BUFB  (4u*OPB)          // one buffer (Ah|Al|Bh|Bl)
#define GEMM_SMEM_BYTES (2*BUFB)

__global__ __launch_bounds__(GT)
void gemm_bf16x3(const __nv_bfloat16* __restrict__ Ahi,
                 const __nv_bfloat16* __restrict__ Alo,
                 const __nv_bfloat16* __restrict__ Bhi,
                 const __nv_bfloat16* __restrict__ Blo,
                 const float* __restrict__ bias,
                 float* __restrict__ C, int Nc, int K)
{
    extern __shared__ __align__(16) char gsm[];
    const uint32_t sbase = smem_u32(gsm);

    const int tid  = threadIdx.x;
    const int wid  = tid >> 5;
    const int lane = tid & 31;
    const int wm   = wid >> 2;
    const int wn   = wid & 3;

    const int m0 = blockIdx.x * TM;
    const int n0 = blockIdx.y * TN;

    float acc[4][4][4] = {};

    const int a_r = lane & 15, a_c = (lane >> 4) * 8;
    const int b_r = (lane & 7) + ((lane >> 4) << 3), b_c = ((lane >> 3) & 1) * 8;

    auto issue = [&](int k0, int buf) {
        const uint32_t bb = sbase + (uint32_t)buf * BUFB;
        #pragma unroll
        for (int i = tid; i < TM * 4; i += GT) {
            const int row = i >> 2, seg = (i & 3) * 8;
            const uint32_t so = (uint32_t)(row * SPAD + seg) * 2;
            const size_t ga = (size_t)(m0 + row) * K + k0 + seg;
            const size_t gb = (size_t)(n0 + row) * K + k0 + seg;
            CP16(bb + 0*OPB + so, Ahi + ga);
            CP16(bb + 1*OPB + so, Alo + ga);
            CP16(bb + 2*OPB + so, Bhi + gb);
            CP16(bb + 3*OPB + so, Blo + gb);
        }
        CP_COMMIT();
    };

    const int nk = K / TKC;
    issue(0, 0);

    for (int k = 0; k < nk; k++) {
        if (k + 1 < nk) { issue((k + 1) * TKC, (k + 1) & 1); CP_WAIT1(); }
        else            { CP_WAIT0(); }
        __syncthreads();

        const uint32_t bb = sbase + (uint32_t)(k & 1) * BUFB;
        const uint32_t uAh = bb, uAl = bb + OPB, uBh = bb + 2*OPB, uBl = bb + 3*OPB;

        #pragma unroll
        for (int kp = 0; kp < 2; kp++) {
            const int kb = kp * 16;
            uint32_t ah[4][4], al[4][4], bh[2][4], bl[2][4];

            #pragma unroll
            for (int mt = 0; mt < 4; mt++) {
                const uint32_t off =
                    (uint32_t)((wm * 64 + mt * 16 + a_r) * SPAD + kb + a_c) * 2;
                ldsm_x4(uAh + off, ah[mt][0], ah[mt][1], ah[mt][2], ah[mt][3]);
                ldsm_x4(uAl + off, al[mt][0], al[mt][1], al[mt][2], al[mt][3]);
            }
            #pragma unroll
            for (int ng = 0; ng < 2; ng++) {
                const uint32_t off =
                    (uint32_t)((wn * 32 + ng * 16 + b_r) * SPAD + kb + b_c) * 2;
                ldsm_x4(uBh + off, bh[ng][0], bh[ng][1], bh[ng][2], bh[ng][3]);
                ldsm_x4(uBl + off, bl[ng][0], bl[ng][1], bl[ng][2], bl[ng][3]);
            }

            #pragma unroll
            for (int mt = 0; mt < 4; mt++) {
                #pragma unroll
                for (int nt = 0; nt < 4; nt++) {
                    const int ng = nt >> 1, hp = (nt & 1) * 2;
                    mma16816(acc[mt][nt], ah[mt][0], ah[mt][1], ah[mt][2], ah[mt][3],
                             bh[ng][hp], bh[ng][hp + 1]);
                    mma16816(acc[mt][nt], ah[mt][0], ah[mt][1], ah[mt][2], ah[mt][3],
                             bl[ng][hp], bl[ng][hp + 1]);
                    mma16816(acc[mt][nt], al[mt][0], al[mt][1], al[mt][2], al[mt][3],
                             bh[ng][hp], bh[ng][hp + 1]);
                }
            }
        }
        __syncthreads();   // all warps done with this buffer before it is refilled
    }

    const int er = lane >> 2, ec = (lane & 3) * 2;
    #pragma unroll
    for (int mt = 0; mt < 4; mt++) {
        #pragma unroll
        for (int nt = 0; nt < 4; nt++) {
            const int row = m0 + wm * 64 + mt * 16 + er;
            const int col = n0 + wn * 32 + nt * 8 + ec;
            float b0 = bias ? bias[col] : 0.f;
            float b1 = bias ? bias[col + 1] : 0.f;
            C[(size_t)row * Nc + col]           = acc[mt][nt][0] + b0;
            C[(size_t)row * Nc + col + 1]       = acc[mt][nt][1] + b1;
            C[(size_t)(row + 8) * Nc + col]     = acc[mt][nt][2] + b0;
            C[(size_t)(row + 8) * Nc + col + 1] = acc[mt][nt][3] + b1;
        }
    }
}

// ---------------------------------------------------------------------------
// Form qk/kk outer products -> bf16 hi/lo
// ---------------------------------------------------------------------------
__global__ void form_qkkk_kernel()
{
    const int idx = blockIdx.x * blockDim.x + threadIdx.x;
    if (idx >= MROWS * NH) return;
    const int h  = idx % NH;
    const int bn = idx / NH;
    const int b  = bn / SEQ;
    const int n  = bn % SEQ;

    const float* pr = &g_proj[(size_t)bn * PROJC];
    float a1[RR1], a2[RR2];
    #pragma unroll
    for (int r = 0; r < RR1; r++) a1[r] = pr[h * RR1 + r];
    #pragma unroll
    for (int r = 0; r < RR2; r++) a2[r] = pr[128 + h * RR2 + r];

    const size_t base = (((size_t)b * NH + h) * SEQ + n) * RKD;
    #pragma unroll
    for (int r1 = 0; r1 < RR1; r1++)
        #pragma unroll
        for (int r2 = 0; r2 < RR2; r2++) {
            float v = a1[r1] * a2[r2] * kQSCALE;
            __nv_bfloat16 hh = __float2bfloat16(v);
            g_qkh[base + r1 * RR2 + r2] = hh;
            g_qkl[base + r1 * RR2 + r2] = __float2bfloat16(v - __bfloat162float(hh));
        }

    #pragma unroll
    for (int r = 0; r < RR1; r++) a1[r] = pr[64 + h * RR1 + r];
    #pragma unroll
    for (int r = 0; r < RR2; r++) a2[r] = pr[256 + h * RR2 + r];

    #pragma unroll
    for (int r1 = 0; r1 < RR1; r1++)
        #pragma unroll
        for (int r2 = 0; r2 < RR2; r2++) {
            float v = a1[r1] * a2[r2];
            __nv_bfloat16 hh = __float2bfloat16(v);
            g_kkh[base + r1 * RR2 + r2] = hh;
            g_kkl[base + r1 * RR2 + r2] = __float2bfloat16(v - __bfloat162float(hh));
        }
}

// ---------------------------------------------------------------------------
// V transpose+split (scalar smem stores — 65-stride rows aren't 16B-aligned)
// ---------------------------------------------------------------------------
__global__ __launch_bounds__(256)
void vt_convert_kernel()
{
    __shared__ float sm[64][65];
    const int bh = blockIdx.y;
    const int b = bh / NH, h = bh % NH;
    const int n0 = blockIdx.x * 64;
    const int tid = threadIdx.x;

    for (int i = tid; i < 64 * 16; i += 256) {
        const int n = i >> 4, seg = (i & 15) * 4;
        const float4 v4 = *reinterpret_cast<const float4*>(
            &g_v[((size_t)(b * SEQ + n0 + n)) * CH + h * HD + seg]);
        sm[n][seg + 0] = v4.x;
        sm[n][seg + 1] = v4.y;
        sm[n][seg + 2] = v4.z;
        sm[n][seg + 3] = v4.w;
    }
    __syncthreads();

    for (int i = tid; i < 64 * 64; i += 256) {
        const int d = i >> 6, n = i & 63;
        const float v = sm[n][d];
        const __nv_bfloat16 hh = __float2bfloat16(v);
        const size_t o = ((size_t)bh * HD + d) * SEQ + n0 + n;
        g_vth[o] = hh;
        g_vtl[o] = __float2bfloat16(v - __bfloat162float(hh));
    }
}

// ---------------------------------------------------------------------------
// MMA flash attention. Block: 128 q-rows, 8 warps x 16 rows, K tiles of 64.
// Dynamic smem 49152 B. Epilogue writes bf16 hi/lo directly (ao split fused).
// ---------------------------------------------------------------------------
#define FQ 128
#define FK 64
#define KSP 40
#define VSP 72
#define AQH_OFF 0u
#define AQL_OFF 10240u
#define AKH_OFF 20480u
#define AKL_OFF 25600u
#define AVH_OFF 30720u
#define AVL_OFF 39936u
#define ATTN_SMEM_BYTES 49152

__global__ __launch_bounds__(256)
void attn_mma_kernel()
{
    extern __shared__ __align__(16) char asm_[];
    const uint32_t sbase = smem_u32(asm_);
    __nv_bfloat16* sQh = reinterpret_cast<__nv_bfloat16*>(asm_ + AQH_OFF);
    __nv_bfloat16* sQl = reinterpret_cast<__nv_bfloat16*>(asm_ + AQL_OFF);
    __nv_bfloat16* sKh = reinterpret_cast<__nv_bfloat16*>(asm_ + AKH_OFF);
    __nv_bfloat16* sKl = reinterpret_cast<__nv_bfloat16*>(asm_ + AKL_OFF);
    __nv_bfloat16* sVh = reinterpret_cast<__nv_bfloat16*>(asm_ + AVH_OFF);
    __nv_bfloat16* sVl = reinterpret_cast<__nv_bfloat16*>(asm_ + AVL_OFF);

    const int bh  = blockIdx.y;
    const int b   = bh / NH, h = bh % NH;
    const int qt  = blockIdx.x;
    const int q0  = qt * FQ;
    const int tid = threadIdx.x;
    const int wid = tid >> 5;
    const int lane = tid & 31;

    const __nv_bfloat16* qkh = &g_qkh[(size_t)bh * SEQ * RKD];
    const __nv_bfloat16* qkl = &g_qkl[(size_t)bh * SEQ * RKD];
    const __nv_bfloat16* kkh = &g_kkh[(size_t)bh * SEQ * RKD];
    const __nv_bfloat16* kkl = &g_kkl[(size_t)bh * SEQ * RKD];
    const __nv_bfloat16* vth = &g_vth[(size_t)bh * HD * SEQ];
    const __nv_bfloat16* vtl = &g_vtl[(size_t)bh * HD * SEQ];

    // stage Q tile (persistent)
    for (int i = tid; i < FQ * 4; i += 256) {
        const int row = i >> 2, seg = (i & 3) * 8;
        *reinterpret_cast<float4*>(&sQh[row * KSP + seg]) =
            *reinterpret_cast<const float4*>(&qkh[(size_t)(q0 + row) * RKD + seg]);
        *reinterpret_cast<float4*>(&sQl[row * KSP + seg]) =
            *reinterpret_cast<const float4*>(&qkl[(size_t)(q0 + row) * RKD + seg]);
    }
    __syncthreads();

    const int a_r = lane & 15, a_c = (lane >> 4) * 8;
    const int b_r = (lane & 7) + ((lane >> 4) << 3), b_c = ((lane >> 3) & 1) * 8;

    const uint32_t sQh_u = sbase + AQH_OFF, sQl_u = sbase + AQL_OFF;
    const uint32_t sKh_u = sbase + AKH_OFF, sKl_u = sbase + AKL_OFF;
    const uint32_t sVh_u = sbase + AVH_OFF, sVl_u = sbase + AVL_OFF;

    uint32_t qh[2][4], ql[2][4];
    #pragma unroll
    for (int kc = 0; kc < 2; kc++) {
        const uint32_t off = (uint32_t)((wid * 16 + a_r) * KSP + kc * 16 + a_c) * 2;
        ldsm_x4(sQh_u + off, qh[kc][0], qh[kc][1], qh[kc][2], qh[kc][3]);
        ldsm_x4(sQl_u + off, ql[kc][0], ql[kc][1], ql[kc][2], ql[kc][3]);
    }

    float Od[8][4] = {};
    float m0 = -1e30f, m1 = -1e30f, l0 = 0.f, l1 = 0.f;
    const int wrow0 = q0 + wid * 16;          // warp's min row
    const int myrow = wrow0 + (lane >> 2);

    const int nkt = 2 * qt + 2;               // K tiles of 64 covering q0+FQ keys

    for (int kt = 0; kt < nkt; kt++) {
        const int j0 = kt * FK;

        __syncthreads();
        for (int i = tid; i < FK * 4; i += 256) {
            const int row = i >> 2, seg = (i & 3) * 8;
            *reinterpret_cast<float4*>(&sKh[row * KSP + seg]) =
                *reinterpret_cast<const float4*>(&kkh[(size_t)(j0 + row) * RKD + seg]);
            *reinterpret_cast<float4*>(&sKl[row * KSP + seg]) =
                *reinterpret_cast<const float4*>(&kkl[(size_t)(j0 + row) * RKD + seg]);
        }
        for (int i = tid; i < HD * 8; i += 256) {
            const int row = i >> 3, seg = (i & 7) * 8;
            *reinterpret_cast<float4*>(&sVh[row * VSP + seg]) =
                *reinterpret_cast<const float4*>(&vth[(size_t)row * SEQ + j0 + seg]);
            *reinterpret_cast<float4*>(&sVl[row * VSP + seg]) =
                *reinterpret_cast<const float4*>(&vtl[(size_t)row * SEQ + j0 + seg]);
        }
        __syncthreads();

        // warp-uniform skip: tile entirely in this warp's future
        if (j0 > wrow0 + 15) continue;

        // ---- S = QK^T (bf16x3) ----
        float S[8][4];
        #pragma unroll
        for (int nt = 0; nt < 8; nt++)
            #pragma unroll
            for (int e = 0; e < 4; e++) S[nt][e] = 0.f;

        #pragma unroll
        for (int kc = 0; kc < 2; kc++) {
            #pragma unroll
            for (int g = 0; g < 4; g++) {
                uint32_t kb[4], kl[4];
                const uint32_t off = (uint32_t)((g * 16 + b_r) * KSP + kc * 16 + b_c) * 2;
                ldsm_x4(sKh_u + off, kb[0], kb[1], kb[2], kb[3]);
                ldsm_x4(sKl_u + off, kl[0], kl[1], kl[2], kl[3]);
                #pragma unroll
                for (int t = 0; t < 2; t++) {
                    const int nt = g * 2 + t, hp = t * 2;
                    mma16816(S[nt], qh[kc][0], qh[kc][1], qh[kc][2], qh[kc][3],
                             kb[hp], kb[hp + 1]);
                    mma16816(S[nt], qh[kc][0], qh[kc][1], qh[kc][2], qh[kc][3],
                             kl[hp], kl[hp + 1]);
                    mma16816(S[nt], ql[kc][0], ql[kc][1], ql[kc][2], ql[kc][3],
                             kb[hp], kb[hp + 1]);
                }
            }
        }

        // ---- causal mask when tile overlaps this warp's diagonal ----
        if (j0 + FK - 1 > wrow0) {
            #pragma unroll
            for (int nt = 0; nt < 8; nt++) {
                const int col = j0 + nt * 8 + (lane & 3) * 2;
                if (col     > myrow)     S[nt][0] = -1e30f;
                if (col + 1 > myrow)     S[nt][1] = -1e30f;
                if (col     > myrow + 8) S[nt][2] = -1e30f;
                if (col + 1 > myrow + 8) S[nt][3] = -1e30f;
            }
        }

        // ---- online softmax ----
        float r0 = -1e30f, r1 = -1e30f;
        #pragma unroll
        for (int nt = 0; nt < 8; nt++) {
            r0 = fmaxf(r0, fmaxf(S[nt][0], S[nt][1]));
            r1 = fmaxf(r1, fmaxf(S[nt][2], S[nt][3]));
        }
        r0 = fmaxf(r0, __shfl_xor_sync(0xffffffff, r0, 1));
        r0 = fmaxf(r0, __shfl_xor_sync(0xffffffff, r0, 2));
        r1 = fmaxf(r1, __shfl_xor_sync(0xffffffff, r1, 1));
        r1 = fmaxf(r1, __shfl_xor_sync(0xffffffff, r1, 2));

        const float mn0 = fmaxf(m0, r0), mn1 = fmaxf(m1, r1);
        const float c0 = exp2f(m0 - mn0), c1 = exp2f(m1 - mn1);
        m0 = mn0; m1 = mn1;

        float s0 = 0.f, s1 = 0.f;
        #pragma unroll
        for (int nt = 0; nt < 8; nt++) {
            S[nt][0] = exp2f(S[nt][0] - mn0);
            S[nt][1] = exp2f(S[nt][1] - mn0);
            S[nt][2] = exp2f(S[nt][2] - mn1);
            S[nt][3] = exp2f(S[nt][3] - mn1);
            s0 += S[nt][0] + S[nt][1];
            s1 += S[nt][2] + S[nt][3];
        }
        l0 = l0 * c0 + s0;
        l1 = l1 * c1 + s1;

        #pragma unroll
        for (int nt = 0; nt < 8; nt++) {
            Od[nt][0] *= c0; Od[nt][1] *= c0;
            Od[nt][2] *= c1; Od[nt][3] *= c1;
        }

        // ---- O += P * V (bf16x3) ----
        #pragma unroll
        for (int kc = 0; kc < 4; kc++) {
            uint32_t pa[4], pl[4];
            {
                const float x0 = S[2 * kc][0],     y0 = S[2 * kc][1];
                const float x1 = S[2 * kc][2],     y1 = S[2 * kc][3];
                const float x2 = S[2 * kc + 1][0], y2 = S[2 * kc + 1][1];
                const float x3 = S[2 * kc + 1][2], y3 = S[2 * kc + 1][3];
                pa[0] = pack_bf16(x0, y0); pa[1] = pack_bf16(x1, y1);
                pa[2] = pack_bf16(x2, y2); pa[3] = pack_bf16(x3, y3);
                __nv_bfloat162 h0 = *reinterpret_cast<__nv_bfloat162*>(&pa[0]);
                __nv_bfloat162 h1 = *reinterpret_cast<__nv_bfloat162*>(&pa[1]);
                __nv_bfloat162 h2 = *reinterpret_cast<__nv_bfloat162*>(&pa[2]);
                __nv_bfloat162 h3 = *reinterpret_cast<__nv_bfloat162*>(&pa[3]);
                pl[0] = pack_bf16(x0 - __bfloat162float(h0.x), y0 - __bfloat162float(h0.y));
                pl[1] = pack_bf16(x1 - __bfloat162float(h1.x), y1 - __bfloat162float(h1.y));
                pl[2] = pack_bf16(x2 - __bfloat162float(h2.x), y2 - __bfloat162float(h2.y));
                pl[3] = pack_bf16(x3 - __bfloat162float(h3.x), y3 - __bfloat162float(h3.y));
            }
            #pragma unroll
            for (int g = 0; g < 4; g++) {
                uint32_t vb[4], vl[4];
                const uint32_t off = (uint32_t)((g * 16 + b_r) * VSP + kc * 16 + b_c) * 2;
                ldsm_x4(sVh_u + off, vb[0], vb[1], vb[2], vb[3]);
                ldsm_x4(sVl_u + off, vl[0], vl[1], vl[2], vl[3]);
                #pragma unroll
                for (int t = 0; t < 2; t++) {
                    const int nt = g * 2 + t, hp = t * 2;
                    mma16816(Od[nt], pa[0], pa[1], pa[2], pa[3], vb[hp], vb[hp + 1]);
                    mma16816(Od[nt], pl[0], pl[1], pl[2], pl[3], vb[hp], vb[hp + 1]);
                    mma16816(Od[nt], pa[0], pa[1], pa[2], pa[3], vl[hp], vl[hp + 1]);
                }
            }
        }
    }

    // ---- finalize: scale + fused bf16 hi/lo split ----
    l0 += __shfl_xor_sync(0xffffffff, l0, 1);
    l0 += __shfl_xor_sync(0xffffffff, l0, 2);
    l1 += __shfl_xor_sync(0xffffffff, l1, 1);
    l1 += __shfl_xor_sync(0xffffffff, l1, 2);
    const float i0 = 1.f / l0, i1 = 1.f / l1;

    const size_t base0 = ((size_t)(b * SEQ + myrow)) * CH + h * HD;
    const size_t base1 = base0 + (size_t)8 * CH;
    #pragma unroll
    for (int nt = 0; nt < 8; nt++) {
        const int d = nt * 8 + (lane & 3) * 2;
        float v;
        __nv_bfloat16 hh;
        v = Od[nt][0] * i0; hh = __float2bfloat16(v);
        g_aoh[base0 + d]     = hh; g_aol[base0 + d]     = __float2bfloat16(v - __bfloat162float(hh));
        v = Od[nt][1] * i0; hh = __float2bfloat16(v);
        g_aoh[base0 + d + 1] = hh; g_aol[base0 + d + 1] = __float2bfloat16(v - __bfloat162float(hh));
        v = Od[nt][2] * i1; hh = __float2bfloat16(v);
        g_aoh[base1 + d]     = hh; g_aol[base1 + d]     = __float2bfloat16(v - __bfloat162float(hh));
        v = Od[nt][3] * i1; hh = __float2bfloat16(v);
        g_aoh[base1 + d + 1] = hh; g_aol[base1 + d + 1] = __float2bfloat16(v - __bfloat162float(hh));
    }
}

// ---------------------------------------------------------------------------
// Launch
// ---------------------------------------------------------------------------
extern "C" void kernel_launch(void* const* d_in, const int* in_sizes, int n_in,
                              void* d_out, int out_size)
{
    const float* x   = (const float*)d_in[0];
    const float* Wq1 = (const float*)d_in[1];
    const float* Wk1 = (const float*)d_in[2];
    const float* Wq2 = (const float*)d_in[3];
    const float* Wk2 = (const float*)d_in[4];
    const float* Wv  = (const float*)d_in[5];
    const float* Wo  = (const float*)d_in[6];
    const float* bo  = (const float*)d_in[7];
    float* out = (float*)d_out;

    cudaFuncSetAttribute(gemm_bf16x3, cudaFuncAttributeMaxDynamicSharedMemorySize,
                         GEMM_SMEM_BYTES);
    cudaFuncSetAttribute(attn_mma_kernel, cudaFuncAttributeMaxDynamicSharedMemorySize,
                         ATTN_SMEM_BYTES);

    __nv_bfloat16 *xh, *xl, *wch, *wcl, *wvh, *wvl, *woh, *wol, *aoh, *aol;
    float *proj, *v;
    cudaGetSymbolAddress((void**)&xh,  g_xh);
    cudaGetSymbolAddress((void**)&xl,  g_xl);
    cudaGetSymbolAddress((void**)&wch, g_wch);
    cudaGetSymbolAddress((void**)&wcl, g_wcl);
    cudaGetSymbolAddress((void**)&wvh, g_wvh);
    cudaGetSymbolAddress((void**)&wvl, g_wvl);
    cudaGetSymbolAddress((void**)&woh, g_woh);
    cudaGetSymbolAddress((void**)&wol, g_wol);
    cudaGetSymbolAddress((void**)&aoh, g_aoh);
    cudaGetSymbolAddress((void**)&aol, g_aol);
    cudaGetSymbolAddress((void**)&proj, g_proj);
    cudaGetSymbolAddress((void**)&v,   g_v);

    const int SB = 256;
    split_kernel<<<(MROWS*CH + SB-1)/SB, SB>>>(x, xh, xl, MROWS*CH);
    split_kernel<<<(64*CH + SB-1)/SB, SB>>>(Wq1, wch,          wcl,          64*CH);
    split_kernel<<<(64*CH + SB-1)/SB, SB>>>(Wk1, wch +  64*CH, wcl +  64*CH, 64*CH);
    split_kernel<<<(128*CH + SB-1)/SB, SB>>>(Wq2, wch + 128*CH, wcl + 128*CH, 128*CH);
    split_kernel<<<(128*CH + SB-1)/SB, SB>>>(Wk2, wch + 256*CH, wcl + 256*CH, 128*CH);
    split_kernel<<<(CH*CH + SB-1)/SB, SB>>>(Wv, wvh, wvl, CH*CH);
    split_kernel<<<(CH*CH + SB-1)/SB, SB>>>(Wo, woh, wol, CH*CH);

    gemm_bf16x3<<<dim3(MROWS/TM, PROJC/TN), GT, GEMM_SMEM_BYTES>>>(
        xh, xl, wch, wcl, nullptr, proj, PROJC, CH);
    gemm_bf16x3<<<dim3(MROWS/TM, CH/TN), GT, GEMM_SMEM_BYTES>>>(
        xh, xl, wvh, wvl, nullptr, v, CH, CH);

    form_qkkk_kernel<<<(MROWS*NH + SB-1)/SB, SB>>>();
    vt_convert_kernel<<<dim3(SEQ/64, BH), 256>>>();

    attn_mma_kernel<<<dim3(SEQ/FQ, BH), 256, ATTN_SMEM_BYTES>>>();

    gemm_bf16x3<<<dim3(MROWS/TM, CH/TN), GT, GEMM_SMEM_BYTES>>>(
        aoh, aol, woh, wol, bo, out, CH, CH);
}

// round 9
// speedup vs baseline: 1.0273x; 1.0273x over previous
#include <cuda_runtime.h>
#include <cuda_bf16.h>
#include <math.h>
#include <stdint.h>

// ---------------------------------------------------------------------------
// Problem constants (B=2, N=2048, C=1024, H=16, R1=4, R2=8, HEAD_DIM=64)
// ---------------------------------------------------------------------------
#define BATCH 2
#define SEQ   2048
#define CH    1024
#define NH    16
#define RR1   4
#define RR2   8
#define HD    64
#define RKD   32
#define MROWS (BATCH*SEQ)     // 4096
#define PROJC 384
#define BH    (BATCH*NH)      // 32

#define L2E  1.44269504088896341f
__device__ __constant__ float kQSCALE = 0.17677669529663687f * 1.44269504088896341f;

// ---------------------------------------------------------------------------
// Scratch
// ---------------------------------------------------------------------------
__device__ __nv_bfloat16 g_xh [MROWS * CH];
__device__ __nv_bfloat16 g_xl [MROWS * CH];
__device__ __nv_bfloat16 g_wch[PROJC * CH];
__device__ __nv_bfloat16 g_wcl[PROJC * CH];
__device__ __nv_bfloat16 g_wvh[CH * CH];
__device__ __nv_bfloat16 g_wvl[CH * CH];
__device__ __nv_bfloat16 g_woh[CH * CH];
__device__ __nv_bfloat16 g_wol[CH * CH];
__device__ __nv_bfloat16 g_aoh[MROWS * CH];
__device__ __nv_bfloat16 g_aol[MROWS * CH];

__device__ float g_proj[MROWS * PROJC];
__device__ float g_v  [MROWS * CH];

__device__ __nv_bfloat16 g_qkh[(size_t)BH * SEQ * RKD];
__device__ __nv_bfloat16 g_qkl[(size_t)BH * SEQ * RKD];
__device__ __nv_bfloat16 g_kkh[(size_t)BH * SEQ * RKD];
__device__ __nv_bfloat16 g_kkl[(size_t)BH * SEQ * RKD];
__device__ __nv_bfloat16 g_vth[(size_t)BH * HD * SEQ];
__device__ __nv_bfloat16 g_vtl[(size_t)BH * HD * SEQ];

// ---------------------------------------------------------------------------
// Helpers
// ---------------------------------------------------------------------------
__device__ __forceinline__ uint32_t smem_u32(const void* p) {
    uint32_t a;
    asm("{ .reg .u64 t; cvta.to.shared.u64 t, %1; cvt.u32.u64 %0, t; }"
        : "=r"(a) : "l"(p));
    return a;
}

__device__ __forceinline__ void ldsm_x4(uint32_t addr, uint32_t& r0, uint32_t& r1,
                                        uint32_t& r2, uint32_t& r3) {
    asm volatile("ldmatrix.sync.aligned.m8n8.x4.shared.b16 {%0,%1,%2,%3}, [%4];"
                 : "=r"(r0), "=r"(r1), "=r"(r2), "=r"(r3) : "r"(addr));
}

__device__ __forceinline__ void mma16816(float* c, uint32_t a0, uint32_t a1,
                                         uint32_t a2, uint32_t a3,
                                         uint32_t b0, uint32_t b1) {
    asm volatile(
        "mma.sync.aligned.m16n8k16.row.col.f32.bf16.bf16.f32 "
        "{%0,%1,%2,%3}, {%4,%5,%6,%7}, {%8,%9}, {%0,%1,%2,%3};"
        : "+f"(c[0]), "+f"(c[1]), "+f"(c[2]), "+f"(c[3])
        : "r"(a0), "r"(a1), "r"(a2), "r"(a3), "r"(b0), "r"(b1));
}

__device__ __forceinline__ uint32_t pack_bf16(float x, float y) {
    __nv_bfloat162 t = __floats2bfloat162_rn(x, y);
    return *reinterpret_cast<uint32_t*>(&t);
}

// ---------------------------------------------------------------------------
// Splits
// ---------------------------------------------------------------------------
__global__ void split_kernel(const float* __restrict__ src,
                             __nv_bfloat16* __restrict__ hi,
                             __nv_bfloat16* __restrict__ lo, int n)
{
    int i = blockIdx.x * blockDim.x + threadIdx.x;
    if (i < n) {
        float v = src[i];
        __nv_bfloat16 h = __float2bfloat16(v);
        hi[i] = h;
        lo[i] = __float2bfloat16(v - __bfloat162float(h));
    }
}

// fused Wq1|Wk1|Wq2|Wk2 split into g_wch/g_wcl (one launch instead of four)
__global__ void split_weights_kernel(const float* __restrict__ Wq1,
                                     const float* __restrict__ Wk1,
                                     const float* __restrict__ Wq2,
                                     const float* __restrict__ Wk2)
{
    int i = blockIdx.x * blockDim.x + threadIdx.x;
    if (i >= PROJC * CH) return;
    const float* src;
    int off;
    if      (i <  64 * CH) { src = Wq1; off = i; }
    else if (i < 128 * CH) { src = Wk1; off = i - 64 * CH; }
    else if (i < 256 * CH) { src = Wq2; off = i - 128 * CH; }
    else                   { src = Wk2; off = i - 256 * CH; }
    float v = src[off];
    __nv_bfloat16 h = __float2bfloat16(v);
    g_wch[i] = h;
    g_wcl[i] = __float2bfloat16(v - __bfloat162float(h));
}

// ---------------------------------------------------------------------------
// bf16x3 NT GEMM (R7-proven static-smem version)
// ---------------------------------------------------------------------------
#define TM 128
#define TN 128
#define TKC 32
#define GT 256
#define SPAD 40

__global__ __launch_bounds__(GT)
void gemm_bf16x3(const __nv_bfloat16* __restrict__ Ahi,
                 const __nv_bfloat16* __restrict__ Alo,
                 const __nv_bfloat16* __restrict__ Bhi,
                 const __nv_bfloat16* __restrict__ Blo,
                 const float* __restrict__ bias,
                 float* __restrict__ C, int Nc, int K)
{
    __shared__ __nv_bfloat16 sAh[TM * SPAD];
    __shared__ __nv_bfloat16 sAl[TM * SPAD];
    __shared__ __nv_bfloat16 sBh[TN * SPAD];
    __shared__ __nv_bfloat16 sBl[TN * SPAD];

    const int tid  = threadIdx.x;
    const int wid  = tid >> 5;
    const int lane = tid & 31;
    const int wm   = wid >> 2;
    const int wn   = wid & 3;

    const int m0 = blockIdx.x * TM;
    const int n0 = blockIdx.y * TN;

    float acc[4][4][4] = {};

    const int a_r = lane & 15, a_c = (lane >> 4) * 8;
    const int b_r = (lane & 7) + ((lane >> 4) << 3), b_c = ((lane >> 3) & 1) * 8;

    const uint32_t sAh_u = smem_u32(sAh), sAl_u = smem_u32(sAl);
    const uint32_t sBh_u = smem_u32(sBh), sBl_u = smem_u32(sBl);

    for (int k0 = 0; k0 < K; k0 += TKC) {
        __syncthreads();
        #pragma unroll
        for (int i = tid; i < TM * 4; i += GT) {
            const int row = i >> 2, seg = (i & 3) * 8;
            const int so = row * SPAD + seg;
            const size_t ga = (size_t)(m0 + row) * K + k0 + seg;
            const size_t gb = (size_t)(n0 + row) * K + k0 + seg;
            *reinterpret_cast<float4*>(&sAh[so]) = *reinterpret_cast<const float4*>(&Ahi[ga]);
            *reinterpret_cast<float4*>(&sAl[so]) = *reinterpret_cast<const float4*>(&Alo[ga]);
            *reinterpret_cast<float4*>(&sBh[so]) = *reinterpret_cast<const float4*>(&Bhi[gb]);
            *reinterpret_cast<float4*>(&sBl[so]) = *reinterpret_cast<const float4*>(&Blo[gb]);
        }
        __syncthreads();

        #pragma unroll
        for (int kp = 0; kp < 2; kp++) {
            const int kb = kp * 16;
            uint32_t ah[4][4], al[4][4], bh[2][4], bl[2][4];

            #pragma unroll
            for (int mt = 0; mt < 4; mt++) {
                const uint32_t off =
                    (uint32_t)((wm * 64 + mt * 16 + a_r) * SPAD + kb + a_c) * 2;
                ldsm_x4(sAh_u + off, ah[mt][0], ah[mt][1], ah[mt][2], ah[mt][3]);
                ldsm_x4(sAl_u + off, al[mt][0], al[mt][1], al[mt][2], al[mt][3]);
            }
            #pragma unroll
            for (int ng = 0; ng < 2; ng++) {
                const uint32_t off =
                    (uint32_t)((wn * 32 + ng * 16 + b_r) * SPAD + kb + b_c) * 2;
                ldsm_x4(sBh_u + off, bh[ng][0], bh[ng][1], bh[ng][2], bh[ng][3]);
                ldsm_x4(sBl_u + off, bl[ng][0], bl[ng][1], bl[ng][2], bl[ng][3]);
            }

            #pragma unroll
            for (int mt = 0; mt < 4; mt++) {
                #pragma unroll
                for (int nt = 0; nt < 4; nt++) {
                    const int ng = nt >> 1, hp = (nt & 1) * 2;
                    mma16816(acc[mt][nt], ah[mt][0], ah[mt][1], ah[mt][2], ah[mt][3],
                             bh[ng][hp], bh[ng][hp + 1]);
                    mma16816(acc[mt][nt], ah[mt][0], ah[mt][1], ah[mt][2], ah[mt][3],
                             bl[ng][hp], bl[ng][hp + 1]);
                    mma16816(acc[mt][nt], al[mt][0], al[mt][1], al[mt][2], al[mt][3],
                             bh[ng][hp], bh[ng][hp + 1]);
                }
            }
        }
    }

    const int er = lane >> 2, ec = (lane & 3) * 2;
    #pragma unroll
    for (int mt = 0; mt < 4; mt++) {
        #pragma unroll
        for (int nt = 0; nt < 4; nt++) {
            const int row = m0 + wm * 64 + mt * 16 + er;
            const int col = n0 + wn * 32 + nt * 8 + ec;
            float b0 = bias ? bias[col] : 0.f;
            float b1 = bias ? bias[col + 1] : 0.f;
            C[(size_t)row * Nc + col]           = acc[mt][nt][0] + b0;
            C[(size_t)row * Nc + col + 1]       = acc[mt][nt][1] + b1;
            C[(size_t)(row + 8) * Nc + col]     = acc[mt][nt][2] + b0;
            C[(size_t)(row + 8) * Nc + col + 1] = acc[mt][nt][3] + b1;
        }
    }
}

// ---------------------------------------------------------------------------
// Form qk/kk outer products -> bf16 hi/lo
// ---------------------------------------------------------------------------
__global__ void form_qkkk_kernel()
{
    const int idx = blockIdx.x * blockDim.x + threadIdx.x;
    if (idx >= MROWS * NH) return;
    const int h  = idx % NH;
    const int bn = idx / NH;
    const int b  = bn / SEQ;
    const int n  = bn % SEQ;

    const float* pr = &g_proj[(size_t)bn * PROJC];
    float a1[RR1], a2[RR2];
    #pragma unroll
    for (int r = 0; r < RR1; r++) a1[r] = pr[h * RR1 + r];
    #pragma unroll
    for (int r = 0; r < RR2; r++) a2[r] = pr[128 + h * RR2 + r];

    const size_t base = (((size_t)b * NH + h) * SEQ + n) * RKD;
    #pragma unroll
    for (int r1 = 0; r1 < RR1; r1++)
        #pragma unroll
        for (int r2 = 0; r2 < RR2; r2++) {
            float v = a1[r1] * a2[r2] * kQSCALE;
            __nv_bfloat16 hh = __float2bfloat16(v);
            g_qkh[base + r1 * RR2 + r2] = hh;
            g_qkl[base + r1 * RR2 + r2] = __float2bfloat16(v - __bfloat162float(hh));
        }

    #pragma unroll
    for (int r = 0; r < RR1; r++) a1[r] = pr[64 + h * RR1 + r];
    #pragma unroll
    for (int r = 0; r < RR2; r++) a2[r] = pr[256 + h * RR2 + r];

    #pragma unroll
    for (int r1 = 0; r1 < RR1; r1++)
        #pragma unroll
        for (int r2 = 0; r2 < RR2; r2++) {
            float v = a1[r1] * a2[r2];
            __nv_bfloat16 hh = __float2bfloat16(v);
            g_kkh[base + r1 * RR2 + r2] = hh;
            g_kkl[base + r1 * RR2 + r2] = __float2bfloat16(v - __bfloat162float(hh));
        }
}

// ---------------------------------------------------------------------------
// V transpose+split (scalar smem stores — 65-stride rows aren't 16B-aligned)
// ---------------------------------------------------------------------------
__global__ __launch_bounds__(256)
void vt_convert_kernel()
{
    __shared__ float sm[64][65];
    const int bh = blockIdx.y;
    const int b = bh / NH, h = bh % NH;
    const int n0 = blockIdx.x * 64;
    const int tid = threadIdx.x;

    for (int i = tid; i < 64 * 16; i += 256) {
        const int n = i >> 4, seg = (i & 15) * 4;
        const float4 v4 = *reinterpret_cast<const float4*>(
            &g_v[((size_t)(b * SEQ + n0 + n)) * CH + h * HD + seg]);
        sm[n][seg + 0] = v4.x;
        sm[n][seg + 1] = v4.y;
        sm[n][seg + 2] = v4.z;
        sm[n][seg + 3] = v4.w;
    }
    __syncthreads();

    for (int i = tid; i < 64 * 64; i += 256) {
        const int d = i >> 6, n = i & 63;
        const float v = sm[n][d];
        const __nv_bfloat16 hh = __float2bfloat16(v);
        const size_t o = ((size_t)bh * HD + d) * SEQ + n0 + n;
        g_vth[o] = hh;
        g_vtl[o] = __float2bfloat16(v - __bfloat162float(hh));
    }
}

// ---------------------------------------------------------------------------
// MMA flash attention (R7-proven shape: 64 q-rows, 4 warps, 128 threads).
// Epilogue writes bf16 hi/lo directly (fused ao split, from R8).
// ---------------------------------------------------------------------------
#define FQ 64
#define FK 64
#define KSP 40
#define VSP 72

__global__ __launch_bounds__(128)
void attn_mma_kernel()
{
    __shared__ __nv_bfloat16 sQh[FQ * KSP], sQl[FQ * KSP];
    __shared__ __nv_bfloat16 sKh[FK * KSP], sKl[FK * KSP];
    __shared__ __nv_bfloat16 sVh[HD * VSP], sVl[HD * VSP];

    const int bh  = blockIdx.y;
    const int b   = bh / NH, h = bh % NH;
    const int qt  = blockIdx.x;
    const int q0  = qt * FQ;
    const int tid = threadIdx.x;
    const int wid = tid >> 5;
    const int lane = tid & 31;

    const __nv_bfloat16* qkh = &g_qkh[(size_t)bh * SEQ * RKD];
    const __nv_bfloat16* qkl = &g_qkl[(size_t)bh * SEQ * RKD];
    const __nv_bfloat16* kkh = &g_kkh[(size_t)bh * SEQ * RKD];
    const __nv_bfloat16* kkl = &g_kkl[(size_t)bh * SEQ * RKD];
    const __nv_bfloat16* vth = &g_vth[(size_t)bh * HD * SEQ];
    const __nv_bfloat16* vtl = &g_vtl[(size_t)bh * HD * SEQ];

    for (int i = tid; i < FQ * 4; i += 128) {
        const int row = i >> 2, seg = (i & 3) * 8;
        *reinterpret_cast<float4*>(&sQh[row * KSP + seg]) =
            *reinterpret_cast<const float4*>(&qkh[(size_t)(q0 + row) * RKD + seg]);
        *reinterpret_cast<float4*>(&sQl[row * KSP + seg]) =
            *reinterpret_cast<const float4*>(&qkl[(size_t)(q0 + row) * RKD + seg]);
    }
    __syncthreads();

    const int a_r = lane & 15, a_c = (lane >> 4) * 8;
    const int b_r = (lane & 7) + ((lane >> 4) << 3), b_c = ((lane >> 3) & 1) * 8;

    const uint32_t sQh_u = smem_u32(sQh), sQl_u = smem_u32(sQl);
    const uint32_t sKh_u = smem_u32(sKh), sKl_u = smem_u32(sKl);
    const uint32_t sVh_u = smem_u32(sVh), sVl_u = smem_u32(sVl);

    uint32_t qh[2][4], ql[2][4];
    #pragma unroll
    for (int kc = 0; kc < 2; kc++) {
        const uint32_t off = (uint32_t)((wid * 16 + a_r) * KSP + kc * 16 + a_c) * 2;
        ldsm_x4(sQh_u + off, qh[kc][0], qh[kc][1], qh[kc][2], qh[kc][3]);
        ldsm_x4(sQl_u + off, ql[kc][0], ql[kc][1], ql[kc][2], ql[kc][3]);
    }

    float Od[8][4] = {};
    float m0 = -1e30f, m1 = -1e30f, l0 = 0.f, l1 = 0.f;
    const int myrow = q0 + wid * 16 + (lane >> 2);

    for (int kt = 0; kt <= qt; kt++) {
        const int j0 = kt * FK;

        __syncthreads();
        for (int i = tid; i < FK * 4; i += 128) {
            const int row = i >> 2, seg = (i & 3) * 8;
            *reinterpret_cast<float4*>(&sKh[row * KSP + seg]) =
                *reinterpret_cast<const float4*>(&kkh[(size_t)(j0 + row) * RKD + seg]);
            *reinterpret_cast<float4*>(&sKl[row * KSP + seg]) =
                *reinterpret_cast<const float4*>(&kkl[(size_t)(j0 + row) * RKD + seg]);
        }
        for (int i = tid; i < HD * 8; i += 128) {
            const int row = i >> 3, seg = (i & 7) * 8;
            *reinterpret_cast<float4*>(&sVh[row * VSP + seg]) =
                *reinterpret_cast<const float4*>(&vth[(size_t)row * SEQ + j0 + seg]);
            *reinterpret_cast<float4*>(&sVl[row * VSP + seg]) =
                *reinterpret_cast<const float4*>(&vtl[(size_t)row * SEQ + j0 + seg]);
        }
        __syncthreads();

        // ---- S = QK^T (bf16x3) ----
        float S[8][4];
        #pragma unroll
        for (int nt = 0; nt < 8; nt++)
            #pragma unroll
            for (int e = 0; e < 4; e++) S[nt][e] = 0.f;

        #pragma unroll
        for (int kc = 0; kc < 2; kc++) {
            #pragma unroll
            for (int g = 0; g < 4; g++) {
                uint32_t kb[4], kl[4];
                const uint32_t off = (uint32_t)((g * 16 + b_r) * KSP + kc * 16 + b_c) * 2;
                ldsm_x4(sKh_u + off, kb[0], kb[1], kb[2], kb[3]);
                ldsm_x4(sKl_u + off, kl[0], kl[1], kl[2], kl[3]);
                #pragma unroll
                for (int t = 0; t < 2; t++) {
                    const int nt = g * 2 + t, hp = t * 2;
                    mma16816(S[nt], qh[kc][0], qh[kc][1], qh[kc][2], qh[kc][3],
                             kb[hp], kb[hp + 1]);
                    mma16816(S[nt], qh[kc][0], qh[kc][1], qh[kc][2], qh[kc][3],
                             kl[hp], kl[hp + 1]);
                    mma16816(S[nt], ql[kc][0], ql[kc][1], ql[kc][2], ql[kc][3],
                             kb[hp], kb[hp + 1]);
                }
            }
        }

        // ---- causal mask on diagonal tile ----
        if (kt == qt) {
            #pragma unroll
            for (int nt = 0; nt < 8; nt++) {
                const int col = j0 + nt * 8 + (lane & 3) * 2;
                if (col     > myrow)     S[nt][0] = -1e30f;
                if (col + 1 > myrow)     S[nt][1] = -1e30f;
                if (col     > myrow + 8) S[nt][2] = -1e30f;
                if (col + 1 > myrow + 8) S[nt][3] = -1e30f;
            }
        }

        // ---- online softmax ----
        float r0 = -1e30f, r1 = -1e30f;
        #pragma unroll
        for (int nt = 0; nt < 8; nt++) {
            r0 = fmaxf(r0, fmaxf(S[nt][0], S[nt][1]));
            r1 = fmaxf(r1, fmaxf(S[nt][2], S[nt][3]));
        }
        r0 = fmaxf(r0, __shfl_xor_sync(0xffffffff, r0, 1));
        r0 = fmaxf(r0, __shfl_xor_sync(0xffffffff, r0, 2));
        r1 = fmaxf(r1, __shfl_xor_sync(0xffffffff, r1, 1));
        r1 = fmaxf(r1, __shfl_xor_sync(0xffffffff, r1, 2));

        const float mn0 = fmaxf(m0, r0), mn1 = fmaxf(m1, r1);
        const float c0 = exp2f(m0 - mn0), c1 = exp2f(m1 - mn1);
        m0 = mn0; m1 = mn1;

        float s0 = 0.f, s1 = 0.f;
        #pragma unroll
        for (int nt = 0; nt < 8; nt++) {
            S[nt][0] = exp2f(S[nt][0] - mn0);
            S[nt][1] = exp2f(S[nt][1] - mn0);
            S[nt][2] = exp2f(S[nt][2] - mn1);
            S[nt][3] = exp2f(S[nt][3] - mn1);
            s0 += S[nt][0] + S[nt][1];
            s1 += S[nt][2] + S[nt][3];
        }
        l0 = l0 * c0 + s0;
        l1 = l1 * c1 + s1;

        #pragma unroll
        for (int nt = 0; nt < 8; nt++) {
            Od[nt][0] *= c0; Od[nt][1] *= c0;
            Od[nt][2] *= c1; Od[nt][3] *= c1;
        }

        // ---- O += P * V (bf16x3) ----
        #pragma unroll
        for (int kc = 0; kc < 4; kc++) {
            uint32_t pa[4], pl[4];
            {
                const float x0 = S[2 * kc][0],     y0 = S[2 * kc][1];
                const float x1 = S[2 * kc][2],     y1 = S[2 * kc][3];
                const float x2 = S[2 * kc + 1][0], y2 = S[2 * kc + 1][1];
                const float x3 = S[2 * kc + 1][2], y3 = S[2 * kc + 1][3];
                pa[0] = pack_bf16(x0, y0); pa[1] = pack_bf16(x1, y1);
                pa[2] = pack_bf16(x2, y2); pa[3] = pack_bf16(x3, y3);
                __nv_bfloat162 h0 = *reinterpret_cast<__nv_bfloat162*>(&pa[0]);
                __nv_bfloat162 h1 = *reinterpret_cast<__nv_bfloat162*>(&pa[1]);
                __nv_bfloat162 h2 = *reinterpret_cast<__nv_bfloat162*>(&pa[2]);
                __nv_bfloat162 h3 = *reinterpret_cast<__nv_bfloat162*>(&pa[3]);
                pl[0] = pack_bf16(x0 - __bfloat162float(h0.x), y0 - __bfloat162float(h0.y));
                pl[1] = pack_bf16(x1 - __bfloat162float(h1.x), y1 - __bfloat162float(h1.y));
                pl[2] = pack_bf16(x2 - __bfloat162float(h2.x), y2 - __bfloat162float(h2.y));
                pl[3] = pack_bf16(x3 - __bfloat162float(h3.x), y3 - __bfloat162float(h3.y));
            }
            #pragma unroll
            for (int g = 0; g < 4; g++) {
                uint32_t vb[4], vl[4];
                const uint32_t off = (uint32_t)((g * 16 + b_r) * VSP + kc * 16 + b_c) * 2;
                ldsm_x4(sVh_u + off, vb[0], vb[1], vb[2], vb[3]);
                ldsm_x4(sVl_u + off, vl[0], vl[1], vl[2], vl[3]);
                #pragma unroll
                for (int t = 0; t < 2; t++) {
                    const int nt = g * 2 + t, hp = t * 2;
                    mma16816(Od[nt], pa[0], pa[1], pa[2], pa[3], vb[hp], vb[hp + 1]);
                    mma16816(Od[nt], pl[0], pl[1], pl[2], pl[3], vb[hp], vb[hp + 1]);
                    mma16816(Od[nt], pa[0], pa[1], pa[2], pa[3], vl[hp], vl[hp + 1]);
                }
            }
        }
    }

    // ---- finalize: scale + fused bf16 hi/lo split ----
    l0 += __shfl_xor_sync(0xffffffff, l0, 1);
    l0 += __shfl_xor_sync(0xffffffff, l0, 2);
    l1 += __shfl_xor_sync(0xffffffff, l1, 1);
    l1 += __shfl_xor_sync(0xffffffff, l1, 2);
    const float i0 = 1.f / l0, i1 = 1.f / l1;

    const size_t base0 = ((size_t)(b * SEQ + myrow)) * CH + h * HD;
    const size_t base1 = base0 + (size_t)8 * CH;
    #pragma unroll
    for (int nt = 0; nt < 8; nt++) {
        const int d = nt * 8 + (lane & 3) * 2;
        float v;
        __nv_bfloat16 hh;
        v = Od[nt][0] * i0; hh = __float2bfloat16(v);
        g_aoh[base0 + d]     = hh; g_aol[base0 + d]     = __float2bfloat16(v - __bfloat162float(hh));
        v = Od[nt][1] * i0; hh = __float2bfloat16(v);
        g_aoh[base0 + d + 1] = hh; g_aol[base0 + d + 1] = __float2bfloat16(v - __bfloat162float(hh));
        v = Od[nt][2] * i1; hh = __float2bfloat16(v);
        g_aoh[base1 + d]     = hh; g_aol[base1 + d]     = __float2bfloat16(v - __bfloat162float(hh));
        v = Od[nt][3] * i1; hh = __float2bfloat16(v);
        g_aoh[base1 + d + 1] = hh; g_aol[base1 + d + 1] = __float2bfloat16(v - __bfloat162float(hh));
    }
}

// ---------------------------------------------------------------------------
// Launch
// ---------------------------------------------------------------------------
extern "C" void kernel_launch(void* const* d_in, const int* in_sizes, int n_in,
                              void* d_out, int out_size)
{
    const float* x   = (const float*)d_in[0];
    const float* Wq1 = (const float*)d_in[1];
    const float* Wk1 = (const float*)d_in[2];
    const float* Wq2 = (const float*)d_in[3];
    const float* Wk2 = (const float*)d_in[4];
    const float* Wv  = (const float*)d_in[5];
    const float* Wo  = (const float*)d_in[6];
    const float* bo  = (const float*)d_in[7];
    float* out = (float*)d_out;

    __nv_bfloat16 *xh, *xl, *wvh, *wvl, *woh, *wol, *aoh, *aol;
    float *proj, *v;
    __nv_bfloat16 *wch, *wcl;
    cudaGetSymbolAddress((void**)&xh,  g_xh);
    cudaGetSymbolAddress((void**)&xl,  g_xl);
    cudaGetSymbolAddress((void**)&wch, g_wch);
    cudaGetSymbolAddress((void**)&wcl, g_wcl);
    cudaGetSymbolAddress((void**)&wvh, g_wvh);
    cudaGetSymbolAddress((void**)&wvl, g_wvl);
    cudaGetSymbolAddress((void**)&woh, g_woh);
    cudaGetSymbolAddress((void**)&wol, g_wol);
    cudaGetSymbolAddress((void**)&aoh, g_aoh);
    cudaGetSymbolAddress((void**)&aol, g_aol);
    cudaGetSymbolAddress((void**)&proj, g_proj);
    cudaGetSymbolAddress((void**)&v,   g_v);

    const int SB = 256;
    // launches 0..3: splits (x, fused weights, Wv, Wo)
    split_kernel<<<(MROWS*CH + SB-1)/SB, SB>>>(x, xh, xl, MROWS*CH);
    split_weights_kernel<<<(PROJC*CH + SB-1)/SB, SB>>>(Wq1, Wk1, Wq2, Wk2);
    split_kernel<<<(CH*CH + SB-1)/SB, SB>>>(Wv, wvh, wvl, CH*CH);
    split_kernel<<<(CH*CH + SB-1)/SB, SB>>>(Wo, woh, wol, CH*CH);

    // launch 4: proj GEMM; launch 5: V GEMM (ncu -s 5 -c 1 captures this one)
    gemm_bf16x3<<<dim3(MROWS/TM, PROJC/TN), GT>>>(xh, xl, wch, wcl, nullptr,
                                                  proj, PROJC, CH);
    gemm_bf16x3<<<dim3(MROWS/TM, CH/TN), GT>>>(xh, xl, wvh, wvl, nullptr,
                                               v, CH, CH);

    form_qkkk_kernel<<<(MROWS*NH + SB-1)/SB, SB>>>();
    vt_convert_kernel<<<dim3(SEQ/64, BH), 256>>>();

    attn_mma_kernel<<<dim3(SEQ/FQ, BH), 128>>>();

    gemm_bf16x3<<<dim3(MROWS/TM, CH/TN), GT>>>(aoh, aol, woh, wol, bo,
                                               out, CH, CH);
}

// round 11
// speedup vs baseline: 1.1053x; 1.0759x over previous
#include <cuda_runtime.h>
#include <cuda_bf16.h>
#include <math.h>
#include <stdint.h>

// ---------------------------------------------------------------------------
// Problem constants (B=2, N=2048, C=1024, H=16, R1=4, R2=8, HEAD_DIM=64)
// ---------------------------------------------------------------------------
#define BATCH 2
#define SEQ   2048
#define CH    1024
#define NH    16
#define RR1   4
#define RR2   8
#define HD    64
#define RKD   32
#define MROWS (BATCH*SEQ)     // 4096
#define PROJC 384
#define BH    (BATCH*NH)      // 32

#define L2E  1.44269504088896341f
__device__ __constant__ float kQSCALE = 0.17677669529663687f * 1.44269504088896341f;

// ---------------------------------------------------------------------------
// Scratch
// ---------------------------------------------------------------------------
__device__ __nv_bfloat16 g_xh [MROWS * CH];
__device__ __nv_bfloat16 g_xl [MROWS * CH];
__device__ __nv_bfloat16 g_wch[PROJC * CH];
__device__ __nv_bfloat16 g_wcl[PROJC * CH];
__device__ __nv_bfloat16 g_wvh[CH * CH];
__device__ __nv_bfloat16 g_wvl[CH * CH];
__device__ __nv_bfloat16 g_woh[CH * CH];
__device__ __nv_bfloat16 g_wol[CH * CH];
__device__ __nv_bfloat16 g_aoh[MROWS * CH];
__device__ __nv_bfloat16 g_aol[MROWS * CH];

__device__ float g_proj[MROWS * PROJC];
__device__ float g_v  [MROWS * CH];

__device__ __nv_bfloat16 g_qkh[(size_t)BH * SEQ * RKD];
__device__ __nv_bfloat16 g_qkl[(size_t)BH * SEQ * RKD];
__device__ __nv_bfloat16 g_kkh[(size_t)BH * SEQ * RKD];
__device__ __nv_bfloat16 g_kkl[(size_t)BH * SEQ * RKD];
__device__ __nv_bfloat16 g_vth[(size_t)BH * HD * SEQ];
__device__ __nv_bfloat16 g_vtl[(size_t)BH * HD * SEQ];

// ---------------------------------------------------------------------------
// Helpers
// ---------------------------------------------------------------------------
__device__ __forceinline__ uint32_t smem_u32(const void* p) {
    uint32_t a;
    asm("{ .reg .u64 t; cvta.to.shared.u64 t, %1; cvt.u32.u64 %0, t; }"
        : "=r"(a) : "l"(p));
    return a;
}

__device__ __forceinline__ void ldsm_x4(uint32_t addr, uint32_t& r0, uint32_t& r1,
                                        uint32_t& r2, uint32_t& r3) {
    asm volatile("ldmatrix.sync.aligned.m8n8.x4.shared.b16 {%0,%1,%2,%3}, [%4];"
                 : "=r"(r0), "=r"(r1), "=r"(r2), "=r"(r3) : "r"(addr));
}

__device__ __forceinline__ void mma16816(float* c, uint32_t a0, uint32_t a1,
                                         uint32_t a2, uint32_t a3,
                                         uint32_t b0, uint32_t b1) {
    asm volatile(
        "mma.sync.aligned.m16n8k16.row.col.f32.bf16.bf16.f32 "
        "{%0,%1,%2,%3}, {%4,%5,%6,%7}, {%8,%9}, {%0,%1,%2,%3};"
        : "+f"(c[0]), "+f"(c[1]), "+f"(c[2]), "+f"(c[3])
        : "r"(a0), "r"(a1), "r"(a2), "r"(a3), "r"(b0), "r"(b1));
}

__device__ __forceinline__ uint32_t pack_bf16(float x, float y) {
    __nv_bfloat162 t = __floats2bfloat162_rn(x, y);
    return *reinterpret_cast<uint32_t*>(&t);
}

#define CP16(sm, gp) \
    asm volatile("cp.async.cg.shared.global [%0], [%1], 16;" \
                 :: "r"(sm), "l"(gp) : "memory")
#define CP_COMMIT() asm volatile("cp.async.commit_group;" ::: "memory")
#define CP_WAIT0()  asm volatile("cp.async.wait_group 0;" ::: "memory")
#define CP_WAIT1()  asm volatile("cp.async.wait_group 1;" ::: "memory")

// ---------------------------------------------------------------------------
// Splits
// ---------------------------------------------------------------------------
__global__ void split_kernel(const float* __restrict__ src,
                             __nv_bfloat16* __restrict__ hi,
                             __nv_bfloat16* __restrict__ lo, int n)
{
    int i = blockIdx.x * blockDim.x + threadIdx.x;
    if (i < n) {
        float v = src[i];
        __nv_bfloat16 h = __float2bfloat16(v);
        hi[i] = h;
        lo[i] = __float2bfloat16(v - __bfloat162float(h));
    }
}

__global__ void split_weights_kernel(const float* __restrict__ Wq1,
                                     const float* __restrict__ Wk1,
                                     const float* __restrict__ Wq2,
                                     const float* __restrict__ Wk2)
{
    int i = blockIdx.x * blockDim.x + threadIdx.x;
    if (i >= PROJC * CH) return;
    const float* src;
    int off;
    if      (i <  64 * CH) { src = Wq1; off = i; }
    else if (i < 128 * CH) { src = Wk1; off = i - 64 * CH; }
    else if (i < 256 * CH) { src = Wq2; off = i - 128 * CH; }
    else                   { src = Wk2; off = i - 256 * CH; }
    float v = src[off];
    __nv_bfloat16 h = __float2bfloat16(v);
    g_wch[i] = h;
    g_wcl[i] = __float2bfloat16(v - __bfloat162float(h));
}

// ---------------------------------------------------------------------------
// bf16x3 NT GEMM, cp.async double-buffered WITH occupancy preserved:
// __launch_bounds__(256, 2) caps regs at 128/thread so 2 CTAs/SM fit
// (2 x 80KB smem = 160KB <= 227KB; 2 x 32K regs = 64K).
// ---------------------------------------------------------------------------
#define TM 128
#define TN 128
#define TKC 32
#define GT 256
#define SPAD 40
#define OPB   10240u
#define BUFB  (4u*OPB)
#define GEMM_SMEM_BYTES (2*BUFB)

__global__ __launch_bounds__(GT, 2)
void gemm_bf16x3(const __nv_bfloat16* __restrict__ Ahi,
                 const __nv_bfloat16* __restrict__ Alo,
                 const __nv_bfloat16* __restrict__ Bhi,
                 const __nv_bfloat16* __restrict__ Blo,
                 const float* __restrict__ bias,
                 float* __restrict__ C, int Nc, int K)
{
    extern __shared__ __align__(16) char gsm[];
    const uint32_t sbase = smem_u32(gsm);

    const int tid  = threadIdx.x;
    const int wid  = tid >> 5;
    const int lane = tid & 31;
    const int wm   = wid >> 2;
    const int wn   = wid & 3;

    const int m0 = blockIdx.x * TM;
    const int n0 = blockIdx.y * TN;

    float acc[4][4][4] = {};

    const int a_r = lane & 15, a_c = (lane >> 4) * 8;
    const int b_r = (lane & 7) + ((lane >> 4) << 3), b_c = ((lane >> 3) & 1) * 8;

    auto issue = [&](int k0, int buf) {
        const uint32_t bb = sbase + (uint32_t)buf * BUFB;
        #pragma unroll
        for (int i = tid; i < TM * 4; i += GT) {
            const int row = i >> 2, seg = (i & 3) * 8;
            const uint32_t so = (uint32_t)(row * SPAD + seg) * 2;
            const size_t ga = (size_t)(m0 + row) * K + k0 + seg;
            const size_t gb = (size_t)(n0 + row) * K + k0 + seg;
            CP16(bb + 0*OPB + so, Ahi + ga);
            CP16(bb + 1*OPB + so, Alo + ga);
            CP16(bb + 2*OPB + so, Bhi + gb);
            CP16(bb + 3*OPB + so, Blo + gb);
        }
        CP_COMMIT();
    };

    const int nk = K / TKC;
    issue(0, 0);

    for (int k = 0; k < nk; k++) {
        if (k + 1 < nk) { issue((k + 1) * TKC, (k + 1) & 1); CP_WAIT1(); }
        else            { CP_WAIT0(); }
        __syncthreads();

        const uint32_t bb = sbase + (uint32_t)(k & 1) * BUFB;
        const uint32_t uAh = bb, uAl = bb + OPB, uBh = bb + 2*OPB, uBl = bb + 3*OPB;

        #pragma unroll
        for (int kp = 0; kp < 2; kp++) {
            const int kb = kp * 16;
            uint32_t ah[4][4], al[4][4], bh[2][4], bl[2][4];

            #pragma unroll
            for (int mt = 0; mt < 4; mt++) {
                const uint32_t off =
                    (uint32_t)((wm * 64 + mt * 16 + a_r) * SPAD + kb + a_c) * 2;
                ldsm_x4(uAh + off, ah[mt][0], ah[mt][1], ah[mt][2], ah[mt][3]);
                ldsm_x4(uAl + off, al[mt][0], al[mt][1], al[mt][2], al[mt][3]);
            }
            #pragma unroll
            for (int ng = 0; ng < 2; ng++) {
                const uint32_t off =
                    (uint32_t)((wn * 32 + ng * 16 + b_r) * SPAD + kb + b_c) * 2;
                ldsm_x4(uBh + off, bh[ng][0], bh[ng][1], bh[ng][2], bh[ng][3]);
                ldsm_x4(uBl + off, bl[ng][0], bl[ng][1], bl[ng][2], bl[ng][3]);
            }

            #pragma unroll
            for (int mt = 0; mt < 4; mt++) {
                #pragma unroll
                for (int nt = 0; nt < 4; nt++) {
                    const int ng = nt >> 1, hp = (nt & 1) * 2;
                    mma16816(acc[mt][nt], ah[mt][0], ah[mt][1], ah[mt][2], ah[mt][3],
                             bh[ng][hp], bh[ng][hp + 1]);
                    mma16816(acc[mt][nt], ah[mt][0], ah[mt][1], ah[mt][2], ah[mt][3],
                             bl[ng][hp], bl[ng][hp + 1]);
                    mma16816(acc[mt][nt], al[mt][0], al[mt][1], al[mt][2], al[mt][3],
                             bh[ng][hp], bh[ng][hp + 1]);
                }
            }
        }
        __syncthreads();
    }

    const int er = lane >> 2, ec = (lane & 3) * 2;
    #pragma unroll
    for (int mt = 0; mt < 4; mt++) {
        #pragma unroll
        for (int nt = 0; nt < 4; nt++) {
            const int row = m0 + wm * 64 + mt * 16 + er;
            const int col = n0 + wn * 32 + nt * 8 + ec;
            float b0 = bias ? bias[col] : 0.f;
            float b1 = bias ? bias[col + 1] : 0.f;
            C[(size_t)row * Nc + col]           = acc[mt][nt][0] + b0;
            C[(size_t)row * Nc + col + 1]       = acc[mt][nt][1] + b1;
            C[(size_t)(row + 8) * Nc + col]     = acc[mt][nt][2] + b0;
            C[(size_t)(row + 8) * Nc + col + 1] = acc[mt][nt][3] + b1;
        }
    }
}

// ---------------------------------------------------------------------------
// Form qk/kk outer products -> bf16 hi/lo
// ---------------------------------------------------------------------------
__global__ void form_qkkk_kernel()
{
    const int idx = blockIdx.x * blockDim.x + threadIdx.x;
    if (idx >= MROWS * NH) return;
    const int h  = idx % NH;
    const int bn = idx / NH;
    const int b  = bn / SEQ;
    const int n  = bn % SEQ;

    const float* pr = &g_proj[(size_t)bn * PROJC];
    float a1[RR1], a2[RR2];
    #pragma unroll
    for (int r = 0; r < RR1; r++) a1[r] = pr[h * RR1 + r];
    #pragma unroll
    for (int r = 0; r < RR2; r++) a2[r] = pr[128 + h * RR2 + r];

    const size_t base = (((size_t)b * NH + h) * SEQ + n) * RKD;
    #pragma unroll
    for (int r1 = 0; r1 < RR1; r1++)
        #pragma unroll
        for (int r2 = 0; r2 < RR2; r2++) {
            float v = a1[r1] * a2[r2] * kQSCALE;
            __nv_bfloat16 hh = __float2bfloat16(v);
            g_qkh[base + r1 * RR2 + r2] = hh;
            g_qkl[base + r1 * RR2 + r2] = __float2bfloat16(v - __bfloat162float(hh));
        }

    #pragma unroll
    for (int r = 0; r < RR1; r++) a1[r] = pr[64 + h * RR1 + r];
    #pragma unroll
    for (int r = 0; r < RR2; r++) a2[r] = pr[256 + h * RR2 + r];

    #pragma unroll
    for (int r1 = 0; r1 < RR1; r1++)
        #pragma unroll
        for (int r2 = 0; r2 < RR2; r2++) {
            float v = a1[r1] * a2[r2];
            __nv_bfloat16 hh = __float2bfloat16(v);
            g_kkh[base + r1 * RR2 + r2] = hh;
            g_kkl[base + r1 * RR2 + r2] = __float2bfloat16(v - __bfloat162float(hh));
        }
}

// ---------------------------------------------------------------------------
// V transpose+split
// ---------------------------------------------------------------------------
__global__ __launch_bounds__(256)
void vt_convert_kernel()
{
    __shared__ float sm[64][65];
    const int bh = blockIdx.y;
    const int b = bh / NH, h = bh % NH;
    const int n0 = blockIdx.x * 64;
    const int tid = threadIdx.x;

    for (int i = tid; i < 64 * 16; i += 256) {
        const int n = i >> 4, seg = (i & 15) * 4;
        const float4 v4 = *reinterpret_cast<const float4*>(
            &g_v[((size_t)(b * SEQ + n0 + n)) * CH + h * HD + seg]);
        sm[n][seg + 0] = v4.x;
        sm[n][seg + 1] = v4.y;
        sm[n][seg + 2] = v4.z;
        sm[n][seg + 3] = v4.w;
    }
    __syncthreads();

    for (int i = tid; i < 64 * 64; i += 256) {
        const int d = i >> 6, n = i & 63;
        const float v = sm[n][d];
        const __nv_bfloat16 hh = __float2bfloat16(v);
        const size_t o = ((size_t)bh * HD + d) * SEQ + n0 + n;
        g_vth[o] = hh;
        g_vtl[o] = __float2bfloat16(v - __bfloat162float(hh));
    }
}

// ---------------------------------------------------------------------------
// MMA flash attention (64 q-rows, 4 warps, 128 threads).
// LPT: heaviest q-tiles (largest qt) are launched FIRST via index reversal.
// ---------------------------------------------------------------------------
#define FQ 64
#define FK 64
#define KSP 40
#define VSP 72

__global__ __launch_bounds__(128)
void attn_mma_kernel()
{
    __shared__ __nv_bfloat16 sQh[FQ * KSP], sQl[FQ * KSP];
    __shared__ __nv_bfloat16 sKh[FK * KSP], sKl[FK * KSP];
    __shared__ __nv_bfloat16 sVh[HD * VSP], sVl[HD * VSP];

    const int bh  = blockIdx.y;
    const int b   = bh / NH, h = bh % NH;
    const int qt  = (gridDim.x - 1) - blockIdx.x;   // LPT: big tiles first
    const int q0  = qt * FQ;
    const int tid = threadIdx.x;
    const int wid = tid >> 5;
    const int lane = tid & 31;

    const __nv_bfloat16* qkh = &g_qkh[(size_t)bh * SEQ * RKD];
    const __nv_bfloat16* qkl = &g_qkl[(size_t)bh * SEQ * RKD];
    const __nv_bfloat16* kkh = &g_kkh[(size_t)bh * SEQ * RKD];
    const __nv_bfloat16* kkl = &g_kkl[(size_t)bh * SEQ * RKD];
    const __nv_bfloat16* vth = &g_vth[(size_t)bh * HD * SEQ];
    const __nv_bfloat16* vtl = &g_vtl[(size_t)bh * HD * SEQ];

    for (int i = tid; i < FQ * 4; i += 128) {
        const int row = i >> 2, seg = (i & 3) * 8;
        *reinterpret_cast<float4*>(&sQh[row * KSP + seg]) =
            *reinterpret_cast<const float4*>(&qkh[(size_t)(q0 + row) * RKD + seg]);
        *reinterpret_cast<float4*>(&sQl[row * KSP + seg]) =
            *reinterpret_cast<const float4*>(&qkl[(size_t)(q0 + row) * RKD + seg]);
    }
    __syncthreads();

    const int a_r = lane & 15, a_c = (lane >> 4) * 8;
    const int b_r = (lane & 7) + ((lane >> 4) << 3), b_c = ((lane >> 3) & 1) * 8;

    const uint32_t sQh_u = smem_u32(sQh), sQl_u = smem_u32(sQl);
    const uint32_t sKh_u = smem_u32(sKh), sKl_u = smem_u32(sKl);
    const uint32_t sVh_u = smem_u32(sVh), sVl_u = smem_u32(sVl);

    uint32_t qh[2][4], ql[2][4];
    #pragma unroll
    for (int kc = 0; kc < 2; kc++) {
        const uint32_t off = (uint32_t)((wid * 16 + a_r) * KSP + kc * 16 + a_c) * 2;
        ldsm_x4(sQh_u + off, qh[kc][0], qh[kc][1], qh[kc][2], qh[kc][3]);
        ldsm_x4(sQl_u + off, ql[kc][0], ql[kc][1], ql[kc][2], ql[kc][3]);
    }

    float Od[8][4] = {};
    float m0 = -1e30f, m1 = -1e30f, l0 = 0.f, l1 = 0.f;
    const int myrow = q0 + wid * 16 + (lane >> 2);

    for (int kt = 0; kt <= qt; kt++) {
        const int j0 = kt * FK;

        __syncthreads();
        for (int i = tid; i < FK * 4; i += 128) {
            const int row = i >> 2, seg = (i & 3) * 8;
            *reinterpret_cast<float4*>(&sKh[row * KSP + seg]) =
                *reinterpret_cast<const float4*>(&kkh[(size_t)(j0 + row) * RKD + seg]);
            *reinterpret_cast<float4*>(&sKl[row * KSP + seg]) =
                *reinterpret_cast<const float4*>(&kkl[(size_t)(j0 + row) * RKD + seg]);
        }
        for (int i = tid; i < HD * 8; i += 128) {
            const int row = i >> 3, seg = (i & 7) * 8;
            *reinterpret_cast<float4*>(&sVh[row * VSP + seg]) =
                *reinterpret_cast<const float4*>(&vth[(size_t)row * SEQ + j0 + seg]);
            *reinterpret_cast<float4*>(&sVl[row * VSP + seg]) =
                *reinterpret_cast<const float4*>(&vtl[(size_t)row * SEQ + j0 + seg]);
        }
        __syncthreads();

        // ---- S = QK^T (bf16x3) ----
        float S[8][4];
        #pragma unroll
        for (int nt = 0; nt < 8; nt++)
            #pragma unroll
            for (int e = 0; e < 4; e++) S[nt][e] = 0.f;

        #pragma unroll
        for (int kc = 0; kc < 2; kc++) {
            #pragma unroll
            for (int g = 0; g < 4; g++) {
                uint32_t kb[4], kl[4];
                const uint32_t off = (uint32_t)((g * 16 + b_r) * KSP + kc * 16 + b_c) * 2;
                ldsm_x4(sKh_u + off, kb[0], kb[1], kb[2], kb[3]);
                ldsm_x4(sKl_u + off, kl[0], kl[1], kl[2], kl[3]);
                #pragma unroll
                for (int t = 0; t < 2; t++) {
                    const int nt = g * 2 + t, hp = t * 2;
                    mma16816(S[nt], qh[kc][0], qh[kc][1], qh[kc][2], qh[kc][3],
                             kb[hp], kb[hp + 1]);
                    mma16816(S[nt], qh[kc][0], qh[kc][1], qh[kc][2], qh[kc][3],
                             kl[hp], kl[hp + 1]);
                    mma16816(S[nt], ql[kc][0], ql[kc][1], ql[kc][2], ql[kc][3],
                             kb[hp], kb[hp + 1]);
                }
            }
        }

        // ---- causal mask on diagonal tile ----
        if (kt == qt) {
            #pragma unroll
            for (int nt = 0; nt < 8; nt++) {
                const int col = j0 + nt * 8 + (lane & 3) * 2;
                if (col     > myrow)     S[nt][0] = -1e30f;
                if (col + 1 > myrow)     S[nt][1] = -1e30f;
                if (col     > myrow + 8) S[nt][2] = -1e30f;
                if (col + 1 > myrow + 8) S[nt][3] = -1e30f;
            }
        }

        // ---- online softmax ----
        float r0 = -1e30f, r1 = -1e30f;
        #pragma unroll
        for (int nt = 0; nt < 8; nt++) {
            r0 = fmaxf(r0, fmaxf(S[nt][0], S[nt][1]));
            r1 = fmaxf(r1, fmaxf(S[nt][2], S[nt][3]));
        }
        r0 = fmaxf(r0, __shfl_xor_sync(0xffffffff, r0, 1));
        r0 = fmaxf(r0, __shfl_xor_sync(0xffffffff, r0, 2));
        r1 = fmaxf(r1, __shfl_xor_sync(0xffffffff, r1, 1));
        r1 = fmaxf(r1, __shfl_xor_sync(0xffffffff, r1, 2));

        const float mn0 = fmaxf(m0, r0), mn1 = fmaxf(m1, r1);
        const float c0 = exp2f(m0 - mn0), c1 = exp2f(m1 - mn1);
        m0 = mn0; m1 = mn1;

        float s0 = 0.f, s1 = 0.f;
        #pragma unroll
        for (int nt = 0; nt < 8; nt++) {
            S[nt][0] = exp2f(S[nt][0] - mn0);
            S[nt][1] = exp2f(S[nt][1] - mn0);
            S[nt][2] = exp2f(S[nt][2] - mn1);
            S[nt][3] = exp2f(S[nt][3] - mn1);
            s0 += S[nt][0] + S[nt][1];
            s1 += S[nt][2] + S[nt][3];
        }
        l0 = l0 * c0 + s0;
        l1 = l1 * c1 + s1;

        #pragma unroll
        for (int nt = 0; nt < 8; nt++) {
            Od[nt][0] *= c0; Od[nt][1] *= c0;
            Od[nt][2] *= c1; Od[nt][3] *= c1;
        }

        // ---- O += P * V (bf16x3) ----
        #pragma unroll
        for (int kc = 0; kc < 4; kc++) {
            uint32_t pa[4], pl[4];
            {
                const float x0 = S[2 * kc][0],     y0 = S[2 * kc][1];
                const float x1 = S[2 * kc][2],     y1 = S[2 * kc][3];
                const float x2 = S[2 * kc + 1][0], y2 = S[2 * kc + 1][1];
                const float x3 = S[2 * kc + 1][2], y3 = S[2 * kc + 1][3];
                pa[0] = pack_bf16(x0, y0); pa[1] = pack_bf16(x1, y1);
                pa[2] = pack_bf16(x2, y2); pa[3] = pack_bf16(x3, y3);
                __nv_bfloat162 h0 = *reinterpret_cast<__nv_bfloat162*>(&pa[0]);
                __nv_bfloat162 h1 = *reinterpret_cast<__nv_bfloat162*>(&pa[1]);
                __nv_bfloat162 h2 = *reinterpret_cast<__nv_bfloat162*>(&pa[2]);
                __nv_bfloat162 h3 = *reinterpret_cast<__nv_bfloat162*>(&pa[3]);
                pl[0] = pack_bf16(x0 - __bfloat162float(h0.x), y0 - __bfloat162float(h0.y));
                pl[1] = pack_bf16(x1 - __bfloat162float(h1.x), y1 - __bfloat162float(h1.y));
                pl[2] = pack_bf16(x2 - __bfloat162float(h2.x), y2 - __bfloat162float(h2.y));
                pl[3] = pack_bf16(x3 - __bfloat162float(h3.x), y3 - __bfloat162float(h3.y));
            }
            #pragma unroll
            for (int g = 0; g < 4; g++) {
                uint32_t vb[4], vl[4];
                const uint32_t off = (uint32_t)((g * 16 + b_r) * VSP + kc * 16 + b_c) * 2;
                ldsm_x4(sVh_u + off, vb[0], vb[1], vb[2], vb[3]);
                ldsm_x4(sVl_u + off, vl[0], vl[1], vl[2], vl[3]);
                #pragma unroll
                for (int t = 0; t < 2; t++) {
                    const int nt = g * 2 + t, hp = t * 2;
                    mma16816(Od[nt], pa[0], pa[1], pa[2], pa[3], vb[hp], vb[hp + 1]);
                    mma16816(Od[nt], pl[0], pl[1], pl[2], pl[3], vb[hp], vb[hp + 1]);
                    mma16816(Od[nt], pa[0], pa[1], pa[2], pa[3], vl[hp], vl[hp + 1]);
                }
            }
        }
    }

    // ---- finalize: scale + fused bf16 hi/lo split ----
    l0 += __shfl_xor_sync(0xffffffff, l0, 1);
    l0 += __shfl_xor_sync(0xffffffff, l0, 2);
    l1 += __shfl_xor_sync(0xffffffff, l1, 1);
    l1 += __shfl_xor_sync(0xffffffff, l1, 2);
    const float i0 = 1.f / l0, i1 = 1.f / l1;

    const size_t base0 = ((size_t)(b * SEQ + myrow)) * CH + h * HD;
    const size_t base1 = base0 + (size_t)8 * CH;
    #pragma unroll
    for (int nt = 0; nt < 8; nt++) {
        const int d = nt * 8 + (lane & 3) * 2;
        float v;
        __nv_bfloat16 hh;
        v = Od[nt][0] * i0; hh = __float2bfloat16(v);
        g_aoh[base0 + d]     = hh; g_aol[base0 + d]     = __float2bfloat16(v - __bfloat162float(hh));
        v = Od[nt][1] * i0; hh = __float2bfloat16(v);
        g_aoh[base0 + d + 1] = hh; g_aol[base0 + d + 1] = __float2bfloat16(v - __bfloat162float(hh));
        v = Od[nt][2] * i1; hh = __float2bfloat16(v);
        g_aoh[base1 + d]     = hh; g_aol[base1 + d]     = __float2bfloat16(v - __bfloat162float(hh));
        v = Od[nt][3] * i1; hh = __float2bfloat16(v);
        g_aoh[base1 + d + 1] = hh; g_aol[base1 + d + 1] = __float2bfloat16(v - __bfloat162float(hh));
    }
}

// ---------------------------------------------------------------------------
// Launch
// ---------------------------------------------------------------------------
extern "C" void kernel_launch(void* const* d_in, const int* in_sizes, int n_in,
                              void* d_out, int out_size)
{
    const float* x   = (const float*)d_in[0];
    const float* Wq1 = (const float*)d_in[1];
    const float* Wk1 = (const float*)d_in[2];
    const float* Wq2 = (const float*)d_in[3];
    const float* Wk2 = (const float*)d_in[4];
    const float* Wv  = (const float*)d_in[5];
    const float* Wo  = (const float*)d_in[6];
    const float* bo  = (const float*)d_in[7];
    float* out = (float*)d_out;

    cudaFuncSetAttribute(gemm_bf16x3, cudaFuncAttributeMaxDynamicSharedMemorySize,
                         GEMM_SMEM_BYTES);

    __nv_bfloat16 *xh, *xl, *wch, *wcl, *wvh, *wvl, *woh, *wol, *aoh, *aol;
    float *proj, *v;
    cudaGetSymbolAddress((void**)&xh,  g_xh);
    cudaGetSymbolAddress((void**)&xl,  g_xl);
    cudaGetSymbolAddress((void**)&wch, g_wch);
    cudaGetSymbolAddress((void**)&wcl, g_wcl);
    cudaGetSymbolAddress((void**)&wvh, g_wvh);
    cudaGetSymbolAddress((void**)&wvl, g_wvl);
    cudaGetSymbolAddress((void**)&woh, g_woh);
    cudaGetSymbolAddress((void**)&wol, g_wol);
    cudaGetSymbolAddress((void**)&aoh, g_aoh);
    cudaGetSymbolAddress((void**)&aol, g_aol);
    cudaGetSymbolAddress((void**)&proj, g_proj);
    cudaGetSymbolAddress((void**)&v,   g_v);

    const int SB = 256;
    split_kernel<<<(MROWS*CH + SB-1)/SB, SB>>>(x, xh, xl, MROWS*CH);
    split_weights_kernel<<<(PROJC*CH + SB-1)/SB, SB>>>(Wq1, Wk1, Wq2, Wk2);
    split_kernel<<<(CH*CH + SB-1)/SB, SB>>>(Wv, wvh, wvl, CH*CH);
    split_kernel<<<(CH*CH + SB-1)/SB, SB>>>(Wo, woh, wol, CH*CH);

    gemm_bf16x3<<<dim3(MROWS/TM, PROJC/TN), GT, GEMM_SMEM_BYTES>>>(
        xh, xl, wch, wcl, nullptr, proj, PROJC, CH);
    gemm_bf16x3<<<dim3(MROWS/TM, CH/TN), GT, GEMM_SMEM_BYTES>>>(
        xh, xl, wvh, wvl, nullptr, v, CH, CH);

    form_qkkk_kernel<<<(MROWS*NH + SB-1)/SB, SB>>>();
    vt_convert_kernel<<<dim3(SEQ/64, BH), 256>>>();

    attn_mma_kernel<<<dim3(SEQ/FQ, BH), 128>>>();

    gemm_bf16x3<<<dim3(MROWS/TM, CH/TN), GT, GEMM_SMEM_BYTES>>>(
        aoh, aol, woh, wol, bo, out, CH, CH);
}

// round 12
// speedup vs baseline: 1.1168x; 1.0104x over previous
#include <cuda_runtime.h>
#include <cuda_bf16.h>
#include <math.h>
#include <stdint.h>

// ---------------------------------------------------------------------------
// Problem constants (B=2, N=2048, C=1024, H=16, R1=4, R2=8, HEAD_DIM=64)
// ---------------------------------------------------------------------------
#define BATCH 2
#define SEQ   2048
#define CH    1024
#define NH    16
#define RR1   4
#define RR2   8
#define HD    64
#define RKD   32
#define MROWS (BATCH*SEQ)     // 4096
#define PROJC 384
#define BH    (BATCH*NH)      // 32

#define L2E  1.44269504088896341f
__device__ __constant__ float kQSCALE = 0.17677669529663687f * 1.44269504088896341f;

// ---------------------------------------------------------------------------
// Scratch
// ---------------------------------------------------------------------------
__device__ __nv_bfloat16 g_xh [MROWS * CH];
__device__ __nv_bfloat16 g_xl [MROWS * CH];
__device__ __nv_bfloat16 g_wch[PROJC * CH];
__device__ __nv_bfloat16 g_wcl[PROJC * CH];
__device__ __nv_bfloat16 g_wvh[CH * CH];
__device__ __nv_bfloat16 g_wvl[CH * CH];
__device__ __nv_bfloat16 g_woh[CH * CH];
__device__ __nv_bfloat16 g_wol[CH * CH];
__device__ __nv_bfloat16 g_aoh[MROWS * CH];
__device__ __nv_bfloat16 g_aol[MROWS * CH];

__device__ float g_proj[MROWS * PROJC];
__device__ float g_v  [MROWS * CH];

__device__ __nv_bfloat16 g_qkh[(size_t)BH * SEQ * RKD];
__device__ __nv_bfloat16 g_qkl[(size_t)BH * SEQ * RKD];
__device__ __nv_bfloat16 g_kkh[(size_t)BH * SEQ * RKD];
__device__ __nv_bfloat16 g_kkl[(size_t)BH * SEQ * RKD];
__device__ __nv_bfloat16 g_vth[(size_t)BH * HD * SEQ];
__device__ __nv_bfloat16 g_vtl[(size_t)BH * HD * SEQ];

// ---------------------------------------------------------------------------
// Helpers
// ---------------------------------------------------------------------------
__device__ __forceinline__ uint32_t smem_u32(const void* p) {
    uint32_t a;
    asm("{ .reg .u64 t; cvta.to.shared.u64 t, %1; cvt.u32.u64 %0, t; }"
        : "=r"(a) : "l"(p));
    return a;
}

__device__ __forceinline__ void ldsm_x4(uint32_t addr, uint32_t& r0, uint32_t& r1,
                                        uint32_t& r2, uint32_t& r3) {
    asm volatile("ldmatrix.sync.aligned.m8n8.x4.shared.b16 {%0,%1,%2,%3}, [%4];"
                 : "=r"(r0), "=r"(r1), "=r"(r2), "=r"(r3) : "r"(addr));
}

__device__ __forceinline__ void mma16816(float* c, uint32_t a0, uint32_t a1,
                                         uint32_t a2, uint32_t a3,
                                         uint32_t b0, uint32_t b1) {
    asm volatile(
        "mma.sync.aligned.m16n8k16.row.col.f32.bf16.bf16.f32 "
        "{%0,%1,%2,%3}, {%4,%5,%6,%7}, {%8,%9}, {%0,%1,%2,%3};"
        : "+f"(c[0]), "+f"(c[1]), "+f"(c[2]), "+f"(c[3])
        : "r"(a0), "r"(a1), "r"(a2), "r"(a3), "r"(b0), "r"(b1));
}

__device__ __forceinline__ uint32_t pack_bf16(float x, float y) {
    __nv_bfloat162 t = __floats2bfloat162_rn(x, y);
    return *reinterpret_cast<uint32_t*>(&t);
}

#define CP16(sm, gp) \
    asm volatile("cp.async.cg.shared.global [%0], [%1], 16;" \
                 :: "r"(sm), "l"(gp) : "memory")
#define CP_COMMIT() asm volatile("cp.async.commit_group;" ::: "memory")
#define CP_WAIT0()  asm volatile("cp.async.wait_group 0;" ::: "memory")
#define CP_WAIT1()  asm volatile("cp.async.wait_group 1;" ::: "memory")

// ---------------------------------------------------------------------------
// Splits
// ---------------------------------------------------------------------------
__global__ void split_kernel(const float* __restrict__ src,
                             __nv_bfloat16* __restrict__ hi,
                             __nv_bfloat16* __restrict__ lo, int n)
{
    int i = blockIdx.x * blockDim.x + threadIdx.x;
    if (i < n) {
        float v = src[i];
        __nv_bfloat16 h = __float2bfloat16(v);
        hi[i] = h;
        lo[i] = __float2bfloat16(v - __bfloat162float(h));
    }
}

__global__ void split_weights_kernel(const float* __restrict__ Wq1,
                                     const float* __restrict__ Wk1,
                                     const float* __restrict__ Wq2,
                                     const float* __restrict__ Wk2)
{
    int i = blockIdx.x * blockDim.x + threadIdx.x;
    if (i >= PROJC * CH) return;
    const float* src;
    int off;
    if      (i <  64 * CH) { src = Wq1; off = i; }
    else if (i < 128 * CH) { src = Wk1; off = i - 64 * CH; }
    else if (i < 256 * CH) { src = Wq2; off = i - 128 * CH; }
    else                   { src = Wk2; off = i - 256 * CH; }
    float v = src[off];
    __nv_bfloat16 h = __float2bfloat16(v);
    g_wch[i] = h;
    g_wcl[i] = __float2bfloat16(v - __bfloat162float(h));
}

// ---------------------------------------------------------------------------
// bf16x3 NT GEMM, cp.async double-buffered, 2 CTAs/SM (unchanged from R11)
// ---------------------------------------------------------------------------
#define TM 128
#define TN 128
#define TKC 32
#define GT 256
#define SPAD 40
#define OPB   10240u
#define BUFB  (4u*OPB)
#define GEMM_SMEM_BYTES (2*BUFB)

__global__ __launch_bounds__(GT, 2)
void gemm_bf16x3(const __nv_bfloat16* __restrict__ Ahi,
                 const __nv_bfloat16* __restrict__ Alo,
                 const __nv_bfloat16* __restrict__ Bhi,
                 const __nv_bfloat16* __restrict__ Blo,
                 const float* __restrict__ bias,
                 float* __restrict__ C, int Nc, int K)
{
    extern __shared__ __align__(16) char gsm[];
    const uint32_t sbase = smem_u32(gsm);

    const int tid  = threadIdx.x;
    const int wid  = tid >> 5;
    const int lane = tid & 31;
    const int wm   = wid >> 2;
    const int wn   = wid & 3;

    const int m0 = blockIdx.x * TM;
    const int n0 = blockIdx.y * TN;

    float acc[4][4][4] = {};

    const int a_r = lane & 15, a_c = (lane >> 4) * 8;
    const int b_r = (lane & 7) + ((lane >> 4) << 3), b_c = ((lane >> 3) & 1) * 8;

    auto issue = [&](int k0, int buf) {
        const uint32_t bb = sbase + (uint32_t)buf * BUFB;
        #pragma unroll
        for (int i = tid; i < TM * 4; i += GT) {
            const int row = i >> 2, seg = (i & 3) * 8;
            const uint32_t so = (uint32_t)(row * SPAD + seg) * 2;
            const size_t ga = (size_t)(m0 + row) * K + k0 + seg;
            const size_t gb = (size_t)(n0 + row) * K + k0 + seg;
            CP16(bb + 0*OPB + so, Ahi + ga);
            CP16(bb + 1*OPB + so, Alo + ga);
            CP16(bb + 2*OPB + so, Bhi + gb);
            CP16(bb + 3*OPB + so, Blo + gb);
        }
        CP_COMMIT();
    };

    const int nk = K / TKC;
    issue(0, 0);

    for (int k = 0; k < nk; k++) {
        if (k + 1 < nk) { issue((k + 1) * TKC, (k + 1) & 1); CP_WAIT1(); }
        else            { CP_WAIT0(); }
        __syncthreads();

        const uint32_t bb = sbase + (uint32_t)(k & 1) * BUFB;
        const uint32_t uAh = bb, uAl = bb + OPB, uBh = bb + 2*OPB, uBl = bb + 3*OPB;

        #pragma unroll
        for (int kp = 0; kp < 2; kp++) {
            const int kb = kp * 16;
            uint32_t ah[4][4], al[4][4], bh[2][4], bl[2][4];

            #pragma unroll
            for (int mt = 0; mt < 4; mt++) {
                const uint32_t off =
                    (uint32_t)((wm * 64 + mt * 16 + a_r) * SPAD + kb + a_c) * 2;
                ldsm_x4(uAh + off, ah[mt][0], ah[mt][1], ah[mt][2], ah[mt][3]);
                ldsm_x4(uAl + off, al[mt][0], al[mt][1], al[mt][2], al[mt][3]);
            }
            #pragma unroll
            for (int ng = 0; ng < 2; ng++) {
                const uint32_t off =
                    (uint32_t)((wn * 32 + ng * 16 + b_r) * SPAD + kb + b_c) * 2;
                ldsm_x4(uBh + off, bh[ng][0], bh[ng][1], bh[ng][2], bh[ng][3]);
                ldsm_x4(uBl + off, bl[ng][0], bl[ng][1], bl[ng][2], bl[ng][3]);
            }

            #pragma unroll
            for (int mt = 0; mt < 4; mt++) {
                #pragma unroll
                for (int nt = 0; nt < 4; nt++) {
                    const int ng = nt >> 1, hp = (nt & 1) * 2;
                    mma16816(acc[mt][nt], ah[mt][0], ah[mt][1], ah[mt][2], ah[mt][3],
                             bh[ng][hp], bh[ng][hp + 1]);
                    mma16816(acc[mt][nt], ah[mt][0], ah[mt][1], ah[mt][2], ah[mt][3],
                             bl[ng][hp], bl[ng][hp + 1]);
                    mma16816(acc[mt][nt], al[mt][0], al[mt][1], al[mt][2], al[mt][3],
                             bh[ng][hp], bh[ng][hp + 1]);
                }
            }
        }
        __syncthreads();
    }

    const int er = lane >> 2, ec = (lane & 3) * 2;
    #pragma unroll
    for (int mt = 0; mt < 4; mt++) {
        #pragma unroll
        for (int nt = 0; nt < 4; nt++) {
            const int row = m0 + wm * 64 + mt * 16 + er;
            const int col = n0 + wn * 32 + nt * 8 + ec;
            float b0 = bias ? bias[col] : 0.f;
            float b1 = bias ? bias[col + 1] : 0.f;
            C[(size_t)row * Nc + col]           = acc[mt][nt][0] + b0;
            C[(size_t)row * Nc + col + 1]       = acc[mt][nt][1] + b1;
            C[(size_t)(row + 8) * Nc + col]     = acc[mt][nt][2] + b0;
            C[(size_t)(row + 8) * Nc + col + 1] = acc[mt][nt][3] + b1;
        }
    }
}

// ---------------------------------------------------------------------------
// Form qk/kk outer products -> bf16 hi/lo
// ---------------------------------------------------------------------------
__global__ void form_qkkk_kernel()
{
    const int idx = blockIdx.x * blockDim.x + threadIdx.x;
    if (idx >= MROWS * NH) return;
    const int h  = idx % NH;
    const int bn = idx / NH;
    const int b  = bn / SEQ;
    const int n  = bn % SEQ;

    const float* pr = &g_proj[(size_t)bn * PROJC];
    float a1[RR1], a2[RR2];
    #pragma unroll
    for (int r = 0; r < RR1; r++) a1[r] = pr[h * RR1 + r];
    #pragma unroll
    for (int r = 0; r < RR2; r++) a2[r] = pr[128 + h * RR2 + r];

    const size_t base = (((size_t)b * NH + h) * SEQ + n) * RKD;
    #pragma unroll
    for (int r1 = 0; r1 < RR1; r1++)
        #pragma unroll
        for (int r2 = 0; r2 < RR2; r2++) {
            float v = a1[r1] * a2[r2] * kQSCALE;
            __nv_bfloat16 hh = __float2bfloat16(v);
            g_qkh[base + r1 * RR2 + r2] = hh;
            g_qkl[base + r1 * RR2 + r2] = __float2bfloat16(v - __bfloat162float(hh));
        }

    #pragma unroll
    for (int r = 0; r < RR1; r++) a1[r] = pr[64 + h * RR1 + r];
    #pragma unroll
    for (int r = 0; r < RR2; r++) a2[r] = pr[256 + h * RR2 + r];

    #pragma unroll
    for (int r1 = 0; r1 < RR1; r1++)
        #pragma unroll
        for (int r2 = 0; r2 < RR2; r2++) {
            float v = a1[r1] * a2[r2];
            __nv_bfloat16 hh = __float2bfloat16(v);
            g_kkh[base + r1 * RR2 + r2] = hh;
            g_kkl[base + r1 * RR2 + r2] = __float2bfloat16(v - __bfloat162float(hh));
        }
}

// ---------------------------------------------------------------------------
// V transpose+split
// ---------------------------------------------------------------------------
__global__ __launch_bounds__(256)
void vt_convert_kernel()
{
    __shared__ float sm[64][65];
    const int bh = blockIdx.y;
    const int b = bh / NH, h = bh % NH;
    const int n0 = blockIdx.x * 64;
    const int tid = threadIdx.x;

    for (int i = tid; i < 64 * 16; i += 256) {
        const int n = i >> 4, seg = (i & 15) * 4;
        const float4 v4 = *reinterpret_cast<const float4*>(
            &g_v[((size_t)(b * SEQ + n0 + n)) * CH + h * HD + seg]);
        sm[n][seg + 0] = v4.x;
        sm[n][seg + 1] = v4.y;
        sm[n][seg + 2] = v4.z;
        sm[n][seg + 3] = v4.w;
    }
    __syncthreads();

    for (int i = tid; i < 64 * 64; i += 256) {
        const int d = i >> 6, n = i & 63;
        const float v = sm[n][d];
        const __nv_bfloat16 hh = __float2bfloat16(v);
        const size_t o = ((size_t)bh * HD + d) * SEQ + n0 + n;
        g_vth[o] = hh;
        g_vtl[o] = __float2bfloat16(v - __bfloat162float(hh));
    }
}

// ---------------------------------------------------------------------------
// MMA flash attention, cp.async DOUBLE-BUFFERED K/V staging.
// Dynamic smem: Q (10240 B) + 2 x KV buffer (28672 B) = 67584 B.
// LPT tile order + fused bf16 epilogue retained.
// ---------------------------------------------------------------------------
#define FQ 64
#define FK 64
#define KSP 40
#define VSP 72
#define AQH_OFF 0u
#define AQL_OFF 5120u
#define AKV0    10240u
#define KB_KH   0u
#define KB_KL   5120u
#define KB_VH   10240u
#define KB_VL   19456u
#define KVBUF   28672u
#define ATTN_SMEM_BYTES (10240 + 2*28672)   // 67584

__global__ __launch_bounds__(128)
void attn_mma_kernel()
{
    extern __shared__ __align__(16) char asmem[];
    const uint32_t sbase = smem_u32(asmem);
    __nv_bfloat16* sQh = reinterpret_cast<__nv_bfloat16*>(asmem + AQH_OFF);
    __nv_bfloat16* sQl = reinterpret_cast<__nv_bfloat16*>(asmem + AQL_OFF);

    const int bh  = blockIdx.y;
    const int b   = bh / NH, h = bh % NH;
    const int qt  = (gridDim.x - 1) - blockIdx.x;   // LPT: big tiles first
    const int q0  = qt * FQ;
    const int tid = threadIdx.x;
    const int wid = tid >> 5;
    const int lane = tid & 31;

    const __nv_bfloat16* qkh = &g_qkh[(size_t)bh * SEQ * RKD];
    const __nv_bfloat16* qkl = &g_qkl[(size_t)bh * SEQ * RKD];
    const __nv_bfloat16* kkh = &g_kkh[(size_t)bh * SEQ * RKD];
    const __nv_bfloat16* kkl = &g_kkl[(size_t)bh * SEQ * RKD];
    const __nv_bfloat16* vth = &g_vth[(size_t)bh * HD * SEQ];
    const __nv_bfloat16* vtl = &g_vtl[(size_t)bh * HD * SEQ];

    auto issue_kv = [&](int j0, int buf) {
        const uint32_t bb = sbase + AKV0 + (uint32_t)buf * KVBUF;
        #pragma unroll
        for (int i = tid; i < FK * 4; i += 128) {
            const int row = i >> 2, seg = (i & 3) * 8;
            const uint32_t so = (uint32_t)(row * KSP + seg) * 2;
            CP16(bb + KB_KH + so, kkh + (size_t)(j0 + row) * RKD + seg);
            CP16(bb + KB_KL + so, kkl + (size_t)(j0 + row) * RKD + seg);
        }
        #pragma unroll
        for (int i = tid; i < HD * 8; i += 128) {
            const int row = i >> 3, seg = (i & 7) * 8;
            const uint32_t so = (uint32_t)(row * VSP + seg) * 2;
            CP16(bb + KB_VH + so, vth + (size_t)row * SEQ + j0 + seg);
            CP16(bb + KB_VL + so, vtl + (size_t)row * SEQ + j0 + seg);
        }
        CP_COMMIT();
    };

    // issue tile 0 immediately, then stage Q while it flies
    issue_kv(0, 0);
    for (int i = tid; i < FQ * 4; i += 128) {
        const int row = i >> 2, seg = (i & 3) * 8;
        *reinterpret_cast<float4*>(&sQh[row * KSP + seg]) =
            *reinterpret_cast<const float4*>(&qkh[(size_t)(q0 + row) * RKD + seg]);
        *reinterpret_cast<float4*>(&sQl[row * KSP + seg]) =
            *reinterpret_cast<const float4*>(&qkl[(size_t)(q0 + row) * RKD + seg]);
    }
    __syncthreads();

    const int a_r = lane & 15, a_c = (lane >> 4) * 8;
    const int b_r = (lane & 7) + ((lane >> 4) << 3), b_c = ((lane >> 3) & 1) * 8;

    const uint32_t sQh_u = sbase + AQH_OFF, sQl_u = sbase + AQL_OFF;

    uint32_t qh[2][4], ql[2][4];
    #pragma unroll
    for (int kc = 0; kc < 2; kc++) {
        const uint32_t off = (uint32_t)((wid * 16 + a_r) * KSP + kc * 16 + a_c) * 2;
        ldsm_x4(sQh_u + off, qh[kc][0], qh[kc][1], qh[kc][2], qh[kc][3]);
        ldsm_x4(sQl_u + off, ql[kc][0], ql[kc][1], ql[kc][2], ql[kc][3]);
    }

    float Od[8][4] = {};
    float m0 = -1e30f, m1 = -1e30f, l0 = 0.f, l1 = 0.f;
    const int myrow = q0 + wid * 16 + (lane >> 2);

    for (int kt = 0; kt <= qt; kt++) {
        const int j0 = kt * FK;

        if (kt < qt) { issue_kv((kt + 1) * FK, (kt + 1) & 1); CP_WAIT1(); }
        else         { CP_WAIT0(); }
        __syncthreads();

        const uint32_t kb_ = sbase + AKV0 + (uint32_t)(kt & 1) * KVBUF;
        const uint32_t sKh_u = kb_ + KB_KH, sKl_u = kb_ + KB_KL;
        const uint32_t sVh_u = kb_ + KB_VH, sVl_u = kb_ + KB_VL;

        // ---- S = QK^T (bf16x3) ----
        float S[8][4];
        #pragma unroll
        for (int nt = 0; nt < 8; nt++)
            #pragma unroll
            for (int e = 0; e < 4; e++) S[nt][e] = 0.f;

        #pragma unroll
        for (int kc = 0; kc < 2; kc++) {
            #pragma unroll
            for (int g = 0; g < 4; g++) {
                uint32_t kb[4], kl[4];
                const uint32_t off = (uint32_t)((g * 16 + b_r) * KSP + kc * 16 + b_c) * 2;
                ldsm_x4(sKh_u + off, kb[0], kb[1], kb[2], kb[3]);
                ldsm_x4(sKl_u + off, kl[0], kl[1], kl[2], kl[3]);
                #pragma unroll
                for (int t = 0; t < 2; t++) {
                    const int nt = g * 2 + t, hp = t * 2;
                    mma16816(S[nt], qh[kc][0], qh[kc][1], qh[kc][2], qh[kc][3],
                             kb[hp], kb[hp + 1]);
                    mma16816(S[nt], qh[kc][0], qh[kc][1], qh[kc][2], qh[kc][3],
                             kl[hp], kl[hp + 1]);
                    mma16816(S[nt], ql[kc][0], ql[kc][1], ql[kc][2], ql[kc][3],
                             kb[hp], kb[hp + 1]);
                }
            }
        }

        // ---- causal mask on diagonal tile ----
        if (kt == qt) {
            #pragma unroll
            for (int nt = 0; nt < 8; nt++) {
                const int col = j0 + nt * 8 + (lane & 3) * 2;
                if (col     > myrow)     S[nt][0] = -1e30f;
                if (col + 1 > myrow)     S[nt][1] = -1e30f;
                if (col     > myrow + 8) S[nt][2] = -1e30f;
                if (col + 1 > myrow + 8) S[nt][3] = -1e30f;
            }
        }

        // ---- online softmax ----
        float r0 = -1e30f, r1 = -1e30f;
        #pragma unroll
        for (int nt = 0; nt < 8; nt++) {
            r0 = fmaxf(r0, fmaxf(S[nt][0], S[nt][1]));
            r1 = fmaxf(r1, fmaxf(S[nt][2], S[nt][3]));
        }
        r0 = fmaxf(r0, __shfl_xor_sync(0xffffffff, r0, 1));
        r0 = fmaxf(r0, __shfl_xor_sync(0xffffffff, r0, 2));
        r1 = fmaxf(r1, __shfl_xor_sync(0xffffffff, r1, 1));
        r1 = fmaxf(r1, __shfl_xor_sync(0xffffffff, r1, 2));

        const float mn0 = fmaxf(m0, r0), mn1 = fmaxf(m1, r1);
        const float c0 = exp2f(m0 - mn0), c1 = exp2f(m1 - mn1);
        m0 = mn0; m1 = mn1;

        float s0 = 0.f, s1 = 0.f;
        #pragma unroll
        for (int nt = 0; nt < 8; nt++) {
            S[nt][0] = exp2f(S[nt][0] - mn0);
            S[nt][1] = exp2f(S[nt][1] - mn0);
            S[nt][2] = exp2f(S[nt][2] - mn1);
            S[nt][3] = exp2f(S[nt][3] - mn1);
            s0 += S[nt][0] + S[nt][1];
            s1 += S[nt][2] + S[nt][3];
        }
        l0 = l0 * c0 + s0;
        l1 = l1 * c1 + s1;

        #pragma unroll
        for (int nt = 0; nt < 8; nt++) {
            Od[nt][0] *= c0; Od[nt][1] *= c0;
            Od[nt][2] *= c1; Od[nt][3] *= c1;
        }

        // ---- O += P * V (bf16x3) ----
        #pragma unroll
        for (int kc = 0; kc < 4; kc++) {
            uint32_t pa[4], pl[4];
            {
                const float x0 = S[2 * kc][0],     y0 = S[2 * kc][1];
                const float x1 = S[2 * kc][2],     y1 = S[2 * kc][3];
                const float x2 = S[2 * kc + 1][0], y2 = S[2 * kc + 1][1];
                const float x3 = S[2 * kc + 1][2], y3 = S[2 * kc + 1][3];
                pa[0] = pack_bf16(x0, y0); pa[1] = pack_bf16(x1, y1);
                pa[2] = pack_bf16(x2, y2); pa[3] = pack_bf16(x3, y3);
                __nv_bfloat162 h0 = *reinterpret_cast<__nv_bfloat162*>(&pa[0]);
                __nv_bfloat162 h1 = *reinterpret_cast<__nv_bfloat162*>(&pa[1]);
                __nv_bfloat162 h2 = *reinterpret_cast<__nv_bfloat162*>(&pa[2]);
                __nv_bfloat162 h3 = *reinterpret_cast<__nv_bfloat162*>(&pa[3]);
                pl[0] = pack_bf16(x0 - __bfloat162float(h0.x), y0 - __bfloat162float(h0.y));
                pl[1] = pack_bf16(x1 - __bfloat162float(h1.x), y1 - __bfloat162float(h1.y));
                pl[2] = pack_bf16(x2 - __bfloat162float(h2.x), y2 - __bfloat162float(h2.y));
                pl[3] = pack_bf16(x3 - __bfloat162float(h3.x), y3 - __bfloat162float(h3.y));
            }
            #pragma unroll
            for (int g = 0; g < 4; g++) {
                uint32_t vb[4], vl[4];
                const uint32_t off = (uint32_t)((g * 16 + b_r) * VSP + kc * 16 + b_c) * 2;
                ldsm_x4(sVh_u + off, vb[0], vb[1], vb[2], vb[3]);
                ldsm_x4(sVl_u + off, vl[0], vl[1], vl[2], vl[3]);
                #pragma unroll
                for (int t = 0; t < 2; t++) {
                    const int nt = g * 2 + t, hp = t * 2;
                    mma16816(Od[nt], pa[0], pa[1], pa[2], pa[3], vb[hp], vb[hp + 1]);
                    mma16816(Od[nt], pl[0], pl[1], pl[2], pl[3], vb[hp], vb[hp + 1]);
                    mma16816(Od[nt], pa[0], pa[1], pa[2], pa[3], vl[hp], vl[hp + 1]);
                }
            }
        }
        __syncthreads();   // all warps done with this buffer before re-issue
    }

    // ---- finalize: scale + fused bf16 hi/lo split ----
    l0 += __shfl_xor_sync(0xffffffff, l0, 1);
    l0 += __shfl_xor_sync(0xffffffff, l0, 2);
    l1 += __shfl_xor_sync(0xffffffff, l1, 1);
    l1 += __shfl_xor_sync(0xffffffff, l1, 2);
    const float i0 = 1.f / l0, i1 = 1.f / l1;

    const size_t base0 = ((size_t)(b * SEQ + myrow)) * CH + h * HD;
    const size_t base1 = base0 + (size_t)8 * CH;
    #pragma unroll
    for (int nt = 0; nt < 8; nt++) {
        const int d = nt * 8 + (lane & 3) * 2;
        float v;
        __nv_bfloat16 hh;
        v = Od[nt][0] * i0; hh = __float2bfloat16(v);
        g_aoh[base0 + d]     = hh; g_aol[base0 + d]     = __float2bfloat16(v - __bfloat162float(hh));
        v = Od[nt][1] * i0; hh = __float2bfloat16(v);
        g_aoh[base0 + d + 1] = hh; g_aol[base0 + d + 1] = __float2bfloat16(v - __bfloat162float(hh));
        v = Od[nt][2] * i1; hh = __float2bfloat16(v);
        g_aoh[base1 + d]     = hh; g_aol[base1 + d]     = __float2bfloat16(v - __bfloat162float(hh));
        v = Od[nt][3] * i1; hh = __float2bfloat16(v);
        g_aoh[base1 + d + 1] = hh; g_aol[base1 + d + 1] = __float2bfloat16(v - __bfloat162float(hh));
    }
}

// ---------------------------------------------------------------------------
// Launch
// ---------------------------------------------------------------------------
extern "C" void kernel_launch(void* const* d_in, const int* in_sizes, int n_in,
                              void* d_out, int out_size)
{
    const float* x   = (const float*)d_in[0];
    const float* Wq1 = (const float*)d_in[1];
    const float* Wk1 = (const float*)d_in[2];
    const float* Wq2 = (const float*)d_in[3];
    const float* Wk2 = (const float*)d_in[4];
    const float* Wv  = (const float*)d_in[5];
    const float* Wo  = (const float*)d_in[6];
    const float* bo  = (const float*)d_in[7];
    float* out = (float*)d_out;

    cudaFuncSetAttribute(gemm_bf16x3, cudaFuncAttributeMaxDynamicSharedMemorySize,
                         GEMM_SMEM_BYTES);
    cudaFuncSetAttribute(attn_mma_kernel, cudaFuncAttributeMaxDynamicSharedMemorySize,
                         ATTN_SMEM_BYTES);

    __nv_bfloat16 *xh, *xl, *wch, *wcl, *wvh, *wvl, *woh, *wol, *aoh, *aol;
    float *proj, *v;
    cudaGetSymbolAddress((void**)&xh,  g_xh);
    cudaGetSymbolAddress((void**)&xl,  g_xl);
    cudaGetSymbolAddress((void**)&wch, g_wch);
    cudaGetSymbolAddress((void**)&wcl, g_wcl);
    cudaGetSymbolAddress((void**)&wvh, g_wvh);
    cudaGetSymbolAddress((void**)&wvl, g_wvl);
    cudaGetSymbolAddress((void**)&woh, g_woh);
    cudaGetSymbolAddress((void**)&wol, g_wol);
    cudaGetSymbolAddress((void**)&aoh, g_aoh);
    cudaGetSymbolAddress((void**)&aol, g_aol);
    cudaGetSymbolAddress((void**)&proj, g_proj);
    cudaGetSymbolAddress((void**)&v,   g_v);

    const int SB = 256;
    split_kernel<<<(MROWS*CH + SB-1)/SB, SB>>>(x, xh, xl, MROWS*CH);
    split_weights_kernel<<<(PROJC*CH + SB-1)/SB, SB>>>(Wq1, Wk1, Wq2, Wk2);
    split_kernel<<<(CH*CH + SB-1)/SB, SB>>>(Wv, wvh, wvl, CH*CH);
    split_kernel<<<(CH*CH + SB-1)/SB, SB>>>(Wo, woh, wol, CH*CH);

    gemm_bf16x3<<<dim3(MROWS/TM, PROJC/TN), GT, GEMM_SMEM_BYTES>>>(
        xh, xl, wch, wcl, nullptr, proj, PROJC, CH);
    gemm_bf16x3<<<dim3(MROWS/TM, CH/TN), GT, GEMM_SMEM_BYTES>>>(
        xh, xl, wvh, wvl, nullptr, v, CH, CH);

    form_qkkk_kernel<<<(MROWS*NH + SB-1)/SB, SB>>>();
    vt_convert_kernel<<<dim3(SEQ/64, BH), 256>>>();

    attn_mma_kernel<<<dim3(SEQ/FQ, BH), 128, ATTN_SMEM_BYTES>>>();

    gemm_bf16x3<<<dim3(MROWS/TM, CH/TN), GT, GEMM_SMEM_BYTES>>>(
        aoh, aol, woh, wol, bo, out, CH, CH);
}

// round 13
// speedup vs baseline: 1.3081x; 1.1712x over previous
#include <cuda_runtime.h>
#include <cuda_bf16.h>
#include <math.h>
#include <stdint.h>

// ---------------------------------------------------------------------------
// Problem constants (B=2, N=2048, C=1024, H=16, R1=4, R2=8, HEAD_DIM=64)
// ---------------------------------------------------------------------------
#define BATCH 2
#define SEQ   2048
#define CH    1024
#define NH    16
#define RR1   4
#define RR2   8
#define HD    64
#define RKD   32
#define MROWS (BATCH*SEQ)     // 4096
#define PROJC 384
#define PVC   (PROJC+CH)      // 1408: fused proj|V output width
#define BH    (BATCH*NH)      // 32

#define L2E  1.44269504088896341f
__device__ __constant__ float kQSCALE = 0.17677669529663687f * 1.44269504088896341f;

// ---------------------------------------------------------------------------
// Scratch
// ---------------------------------------------------------------------------
__device__ __nv_bfloat16 g_xh  [MROWS * CH];
__device__ __nv_bfloat16 g_xl  [MROWS * CH];
__device__ __nv_bfloat16 g_wcvh[PVC * CH];     // concat(Wq1,Wk1,Wq2,Wk2,Wv) hi
__device__ __nv_bfloat16 g_wcvl[PVC * CH];
__device__ __nv_bfloat16 g_woh [CH * CH];
__device__ __nv_bfloat16 g_wol [CH * CH];
__device__ __nv_bfloat16 g_aoh [MROWS * CH];
__device__ __nv_bfloat16 g_aol [MROWS * CH];

__device__ float g_projv[(size_t)MROWS * PVC];  // [proj(384) | v(1024)] per row

__device__ __nv_bfloat16 g_qkh[(size_t)BH * SEQ * RKD];
__device__ __nv_bfloat16 g_qkl[(size_t)BH * SEQ * RKD];
__device__ __nv_bfloat16 g_kkh[(size_t)BH * SEQ * RKD];
__device__ __nv_bfloat16 g_kkl[(size_t)BH * SEQ * RKD];
__device__ __nv_bfloat16 g_vth[(size_t)BH * HD * SEQ];
__device__ __nv_bfloat16 g_vtl[(size_t)BH * HD * SEQ];

// ---------------------------------------------------------------------------
// Helpers
// ---------------------------------------------------------------------------
__device__ __forceinline__ uint32_t smem_u32(const void* p) {
    uint32_t a;
    asm("{ .reg .u64 t; cvta.to.shared.u64 t, %1; cvt.u32.u64 %0, t; }"
        : "=r"(a) : "l"(p));
    return a;
}

__device__ __forceinline__ void ldsm_x4(uint32_t addr, uint32_t& r0, uint32_t& r1,
                                        uint32_t& r2, uint32_t& r3) {
    asm volatile("ldmatrix.sync.aligned.m8n8.x4.shared.b16 {%0,%1,%2,%3}, [%4];"
                 : "=r"(r0), "=r"(r1), "=r"(r2), "=r"(r3) : "r"(addr));
}

__device__ __forceinline__ void mma16816(float* c, uint32_t a0, uint32_t a1,
                                         uint32_t a2, uint32_t a3,
                                         uint32_t b0, uint32_t b1) {
    asm volatile(
        "mma.sync.aligned.m16n8k16.row.col.f32.bf16.bf16.f32 "
        "{%0,%1,%2,%3}, {%4,%5,%6,%7}, {%8,%9}, {%0,%1,%2,%3};"
        : "+f"(c[0]), "+f"(c[1]), "+f"(c[2]), "+f"(c[3])
        : "r"(a0), "r"(a1), "r"(a2), "r"(a3), "r"(b0), "r"(b1));
}

__device__ __forceinline__ uint32_t pack_bf16(float x, float y) {
    __nv_bfloat162 t = __floats2bfloat162_rn(x, y);
    return *reinterpret_cast<uint32_t*>(&t);
}

#define CP16(sm, gp) \
    asm volatile("cp.async.cg.shared.global [%0], [%1], 16;" \
                 :: "r"(sm), "l"(gp) : "memory")
#define CP_COMMIT() asm volatile("cp.async.commit_group;" ::: "memory")
#define CP_WAIT0()  asm volatile("cp.async.wait_group 0;" ::: "memory")
#define CP_WAIT1()  asm volatile("cp.async.wait_group 1;" ::: "memory")

// ---------------------------------------------------------------------------
// Mega split: x, (Wq1|Wk1|Wq2|Wk2|Wv) -> g_wcv*, Wo -> g_wo* in ONE launch.
// 4 elems per thread, float4 loads, vectorized bf16 stores.
// Region sizes (elems): x 4194304 | Wq1 65536 | Wk1 65536 | Wq2 131072 |
//                       Wk2 131072 | Wv 1048576 | Wo 1048576
// ---------------------------------------------------------------------------
#define XSZ   (MROWS*CH)          // 4194304
#define WQ1SZ (64*CH)
#define WK1SZ (64*CH)
#define WQ2SZ (128*CH)
#define WK2SZ (128*CH)
#define WVSZ  (CH*CH)
#define WOSZ  (CH*CH)
#define WCATSZ (WQ1SZ+WK1SZ+WQ2SZ+WK2SZ)   // 393216
#define TOTSPLIT (XSZ + WCATSZ + WVSZ + WOSZ)  // 6684672

__global__ __launch_bounds__(256)
void mega_split_kernel(const float* __restrict__ x,
                       const float* __restrict__ Wq1,
                       const float* __restrict__ Wk1,
                       const float* __restrict__ Wq2,
                       const float* __restrict__ Wk2,
                       const float* __restrict__ Wv,
                       const float* __restrict__ Wo)
{
    const int i4 = (blockIdx.x * blockDim.x + threadIdx.x) * 4;
    if (i4 >= TOTSPLIT) return;

    const float* src;
    __nv_bfloat16 *dh, *dl;
    int off;

    if (i4 < XSZ) {
        src = x; off = i4; dh = g_xh; dl = g_xl;
    } else if (i4 < XSZ + WCATSZ + WVSZ) {
        const int wo = i4 - XSZ;       // offset within wcv dest
        dh = g_wcvh; dl = g_wcvl; off = wo;
        // src region
        if      (wo < WQ1SZ)                        { src = Wq1 - 0; off = wo; src = Wq1; }
        else if (wo < WQ1SZ+WK1SZ)                  { src = Wk1; off = wo - WQ1SZ; }
        else if (wo < WQ1SZ+WK1SZ+WQ2SZ)            { src = Wq2; off = wo - (WQ1SZ+WK1SZ); }
        else if (wo < WCATSZ)                       { src = Wk2; off = wo - (WQ1SZ+WK1SZ+WQ2SZ); }
        else                                        { src = Wv;  off = wo - WCATSZ; }
        // dest index is wo (contiguous concat layout)
        const float4 v4 = *reinterpret_cast<const float4*>(&src[off]);
        float vv[4] = {v4.x, v4.y, v4.z, v4.w};
        uint32_t hs[2], ls[2];
        #pragma unroll
        for (int p = 0; p < 2; p++) {
            __nv_bfloat162 hp = __floats2bfloat162_rn(vv[2*p], vv[2*p+1]);
            hs[p] = *reinterpret_cast<uint32_t*>(&hp);
            float r0 = vv[2*p]   - __bfloat162float(hp.x);
            float r1 = vv[2*p+1] - __bfloat162float(hp.y);
            ls[p] = pack_bf16(r0, r1);
        }
        *reinterpret_cast<uint2*>(&dh[wo]) = make_uint2(hs[0], hs[1]);
        *reinterpret_cast<uint2*>(&dl[wo]) = make_uint2(ls[0], ls[1]);
        return;
    } else {
        const int wo = i4 - (XSZ + WCATSZ + WVSZ);
        src = Wo; off = wo; dh = g_woh; dl = g_wol;
    }

    const float4 v4 = *reinterpret_cast<const float4*>(&src[off]);
    float vv[4] = {v4.x, v4.y, v4.z, v4.w};
    uint32_t hs[2], ls[2];
    #pragma unroll
    for (int p = 0; p < 2; p++) {
        __nv_bfloat162 hp = __floats2bfloat162_rn(vv[2*p], vv[2*p+1]);
        hs[p] = *reinterpret_cast<uint32_t*>(&hp);
        float r0 = vv[2*p]   - __bfloat162float(hp.x);
        float r1 = vv[2*p+1] - __bfloat162float(hp.y);
        ls[p] = pack_bf16(r0, r1);
    }
    *reinterpret_cast<uint2*>(&dh[off]) = make_uint2(hs[0], hs[1]);
    *reinterpret_cast<uint2*>(&dl[off]) = make_uint2(ls[0], ls[1]);
}

// split for attention output (ao lives in fused attn epilogue; this kernel gone)

// ---------------------------------------------------------------------------
// bf16x3 NT GEMM, cp.async double-buffered, 2 CTAs/SM (unchanged from R11)
// ---------------------------------------------------------------------------
#define TM 128
#define TN 128
#define TKC 32
#define GT 256
#define SPAD 40
#define OPB   10240u
#define BUFB  (4u*OPB)
#define GEMM_SMEM_BYTES (2*BUFB)

__global__ __launch_bounds__(GT, 2)
void gemm_bf16x3(const __nv_bfloat16* __restrict__ Ahi,
                 const __nv_bfloat16* __restrict__ Alo,
                 const __nv_bfloat16* __restrict__ Bhi,
                 const __nv_bfloat16* __restrict__ Blo,
                 const float* __restrict__ bias,
                 float* __restrict__ C, int Nc, int K)
{
    extern __shared__ __align__(16) char gsm[];
    const uint32_t sbase = smem_u32(gsm);

    const int tid  = threadIdx.x;
    const int wid  = tid >> 5;
    const int lane = tid & 31;
    const int wm   = wid >> 2;
    const int wn   = wid & 3;

    const int m0 = blockIdx.x * TM;
    const int n0 = blockIdx.y * TN;

    float acc[4][4][4] = {};

    const int a_r = lane & 15, a_c = (lane >> 4) * 8;
    const int b_r = (lane & 7) + ((lane >> 4) << 3), b_c = ((lane >> 3) & 1) * 8;

    auto issue = [&](int k0, int buf) {
        const uint32_t bb = sbase + (uint32_t)buf * BUFB;
        #pragma unroll
        for (int i = tid; i < TM * 4; i += GT) {
            const int row = i >> 2, seg = (i & 3) * 8;
            const uint32_t so = (uint32_t)(row * SPAD + seg) * 2;
            const size_t ga = (size_t)(m0 + row) * K + k0 + seg;
            const size_t gb = (size_t)(n0 + row) * K + k0 + seg;
            CP16(bb + 0*OPB + so, Ahi + ga);
            CP16(bb + 1*OPB + so, Alo + ga);
            CP16(bb + 2*OPB + so, Bhi + gb);
            CP16(bb + 3*OPB + so, Blo + gb);
        }
        CP_COMMIT();
    };

    const int nk = K / TKC;
    issue(0, 0);

    for (int k = 0; k < nk; k++) {
        if (k + 1 < nk) { issue((k + 1) * TKC, (k + 1) & 1); CP_WAIT1(); }
        else            { CP_WAIT0(); }
        __syncthreads();

        const uint32_t bb = sbase + (uint32_t)(k & 1) * BUFB;
        const uint32_t uAh = bb, uAl = bb + OPB, uBh = bb + 2*OPB, uBl = bb + 3*OPB;

        #pragma unroll
        for (int kp = 0; kp < 2; kp++) {
            const int kb = kp * 16;
            uint32_t ah[4][4], al[4][4], bh[2][4], bl[2][4];

            #pragma unroll
            for (int mt = 0; mt < 4; mt++) {
                const uint32_t off =
                    (uint32_t)((wm * 64 + mt * 16 + a_r) * SPAD + kb + a_c) * 2;
                ldsm_x4(uAh + off, ah[mt][0], ah[mt][1], ah[mt][2], ah[mt][3]);
                ldsm_x4(uAl + off, al[mt][0], al[mt][1], al[mt][2], al[mt][3]);
            }
            #pragma unroll
            for (int ng = 0; ng < 2; ng++) {
                const uint32_t off =
                    (uint32_t)((wn * 32 + ng * 16 + b_r) * SPAD + kb + b_c) * 2;
                ldsm_x4(uBh + off, bh[ng][0], bh[ng][1], bh[ng][2], bh[ng][3]);
                ldsm_x4(uBl + off, bl[ng][0], bl[ng][1], bl[ng][2], bl[ng][3]);
            }

            #pragma unroll
            for (int mt = 0; mt < 4; mt++) {
                #pragma unroll
                for (int nt = 0; nt < 4; nt++) {
                    const int ng = nt >> 1, hp = (nt & 1) * 2;
                    mma16816(acc[mt][nt], ah[mt][0], ah[mt][1], ah[mt][2], ah[mt][3],
                             bh[ng][hp], bh[ng][hp + 1]);
                    mma16816(acc[mt][nt], ah[mt][0], ah[mt][1], ah[mt][2], ah[mt][3],
                             bl[ng][hp], bl[ng][hp + 1]);
                    mma16816(acc[mt][nt], al[mt][0], al[mt][1], al[mt][2], al[mt][3],
                             bh[ng][hp], bh[ng][hp + 1]);
                }
            }
        }
        __syncthreads();
    }

    const int er = lane >> 2, ec = (lane & 3) * 2;
    #pragma unroll
    for (int mt = 0; mt < 4; mt++) {
        #pragma unroll
        for (int nt = 0; nt < 4; nt++) {
            const int row = m0 + wm * 64 + mt * 16 + er;
            const int col = n0 + wn * 32 + nt * 8 + ec;
            float b0 = bias ? bias[col] : 0.f;
            float b1 = bias ? bias[col + 1] : 0.f;
            C[(size_t)row * Nc + col]           = acc[mt][nt][0] + b0;
            C[(size_t)row * Nc + col + 1]       = acc[mt][nt][1] + b1;
            C[(size_t)(row + 8) * Nc + col]     = acc[mt][nt][2] + b0;
            C[(size_t)(row + 8) * Nc + col + 1] = acc[mt][nt][3] + b1;
        }
    }
}

// ---------------------------------------------------------------------------
// Form qk/kk outer products -> bf16 hi/lo (reads fused projv; vectorized stores)
// ---------------------------------------------------------------------------
__global__ void form_qkkk_kernel()
{
    const int idx = blockIdx.x * blockDim.x + threadIdx.x;
    if (idx >= MROWS * NH) return;
    const int h  = idx % NH;
    const int bn = idx / NH;
    const int b  = bn / SEQ;
    const int n  = bn % SEQ;

    const float* pr = &g_projv[(size_t)bn * PVC];
    float a1[RR1], a2[RR2];
    #pragma unroll
    for (int r = 0; r < RR1; r++) a1[r] = pr[h * RR1 + r];
    #pragma unroll
    for (int r = 0; r < RR2; r++) a2[r] = pr[128 + h * RR2 + r];

    const size_t base = (((size_t)b * NH + h) * SEQ + n) * RKD;

    uint32_t hs[16], ls[16];
    #pragma unroll
    for (int r1 = 0; r1 < RR1; r1++)
        #pragma unroll
        for (int r2 = 0; r2 < RR2; r2 += 2) {
            const int p = (r1 * RR2 + r2) >> 1;
            float v0 = a1[r1] * a2[r2]     * kQSCALE;
            float v1 = a1[r1] * a2[r2 + 1] * kQSCALE;
            __nv_bfloat162 hp = __floats2bfloat162_rn(v0, v1);
            hs[p] = *reinterpret_cast<uint32_t*>(&hp);
            ls[p] = pack_bf16(v0 - __bfloat162float(hp.x), v1 - __bfloat162float(hp.y));
        }
    #pragma unroll
    for (int q = 0; q < 4; q++) {
        *reinterpret_cast<uint4*>(&g_qkh[base + q * 8]) =
            make_uint4(hs[4*q], hs[4*q+1], hs[4*q+2], hs[4*q+3]);
        *reinterpret_cast<uint4*>(&g_qkl[base + q * 8]) =
            make_uint4(ls[4*q], ls[4*q+1], ls[4*q+2], ls[4*q+3]);
    }

    #pragma unroll
    for (int r = 0; r < RR1; r++) a1[r] = pr[64 + h * RR1 + r];
    #pragma unroll
    for (int r = 0; r < RR2; r++) a2[r] = pr[256 + h * RR2 + r];

    #pragma unroll
    for (int r1 = 0; r1 < RR1; r1++)
        #pragma unroll
        for (int r2 = 0; r2 < RR2; r2 += 2) {
            const int p = (r1 * RR2 + r2) >> 1;
            float v0 = a1[r1] * a2[r2];
            float v1 = a1[r1] * a2[r2 + 1];
            __nv_bfloat162 hp = __floats2bfloat162_rn(v0, v1);
            hs[p] = *reinterpret_cast<uint32_t*>(&hp);
            ls[p] = pack_bf16(v0 - __bfloat162float(hp.x), v1 - __bfloat162float(hp.y));
        }
    #pragma unroll
    for (int q = 0; q < 4; q++) {
        *reinterpret_cast<uint4*>(&g_kkh[base + q * 8]) =
            make_uint4(hs[4*q], hs[4*q+1], hs[4*q+2], hs[4*q+3]);
        *reinterpret_cast<uint4*>(&g_kkl[base + q * 8]) =
            make_uint4(ls[4*q], ls[4*q+1], ls[4*q+2], ls[4*q+3]);
    }
}

// ---------------------------------------------------------------------------
// V transpose+split (reads V columns of fused projv)
// ---------------------------------------------------------------------------
__global__ __launch_bounds__(256)
void vt_convert_kernel()
{
    __shared__ float sm[64][65];
    const int bh = blockIdx.y;
    const int b = bh / NH, h = bh % NH;
    const int n0 = blockIdx.x * 64;
    const int tid = threadIdx.x;

    for (int i = tid; i < 64 * 16; i += 256) {
        const int n = i >> 4, seg = (i & 15) * 4;
        const float4 v4 = *reinterpret_cast<const float4*>(
            &g_projv[((size_t)(b * SEQ + n0 + n)) * PVC + PROJC + h * HD + seg]);
        sm[n][seg + 0] = v4.x;
        sm[n][seg + 1] = v4.y;
        sm[n][seg + 2] = v4.z;
        sm[n][seg + 3] = v4.w;
    }
    __syncthreads();

    for (int i = tid; i < 64 * 64; i += 256) {
        const int d = i >> 6, n = i & 63;
        const float v = sm[n][d];
        const __nv_bfloat16 hh = __float2bfloat16(v);
        const size_t o = ((size_t)bh * HD + d) * SEQ + n0 + n;
        g_vth[o] = hh;
        g_vtl[o] = __float2bfloat16(v - __bfloat162float(hh));
    }
}

// ---------------------------------------------------------------------------
// MMA flash attention (unchanged from R12: cp.async double-buffered K/V,
// LPT tile order, fused bf16 epilogue)
// ---------------------------------------------------------------------------
#define FQ 64
#define FK 64
#define KSP 40
#define VSP 72
#define AQH_OFF 0u
#define AQL_OFF 5120u
#define AKV0    10240u
#define KB_KH   0u
#define KB_KL   5120u
#define KB_VH   10240u
#define KB_VL   19456u
#define KVBUF   28672u
#define ATTN_SMEM_BYTES (10240 + 2*28672)   // 67584

__global__ __launch_bounds__(128)
void attn_mma_kernel()
{
    extern __shared__ __align__(16) char asmem[];
    const uint32_t sbase = smem_u32(asmem);
    __nv_bfloat16* sQh = reinterpret_cast<__nv_bfloat16*>(asmem + AQH_OFF);
    __nv_bfloat16* sQl = reinterpret_cast<__nv_bfloat16*>(asmem + AQL_OFF);

    const int bh  = blockIdx.y;
    const int b   = bh / NH, h = bh % NH;
    const int qt  = (gridDim.x - 1) - blockIdx.x;   // LPT
    const int q0  = qt * FQ;
    const int tid = threadIdx.x;
    const int wid = tid >> 5;
    const int lane = tid & 31;

    const __nv_bfloat16* qkh = &g_qkh[(size_t)bh * SEQ * RKD];
    const __nv_bfloat16* qkl = &g_qkl[(size_t)bh * SEQ * RKD];
    const __nv_bfloat16* kkh = &g_kkh[(size_t)bh * SEQ * RKD];
    const __nv_bfloat16* kkl = &g_kkl[(size_t)bh * SEQ * RKD];
    const __nv_bfloat16* vth = &g_vth[(size_t)bh * HD * SEQ];
    const __nv_bfloat16* vtl = &g_vtl[(size_t)bh * HD * SEQ];

    auto issue_kv = [&](int j0, int buf) {
        const uint32_t bb = sbase + AKV0 + (uint32_t)buf * KVBUF;
        #pragma unroll
        for (int i = tid; i < FK * 4; i += 128) {
            const int row = i >> 2, seg = (i & 3) * 8;
            const uint32_t so = (uint32_t)(row * KSP + seg) * 2;
            CP16(bb + KB_KH + so, kkh + (size_t)(j0 + row) * RKD + seg);
            CP16(bb + KB_KL + so, kkl + (size_t)(j0 + row) * RKD + seg);
        }
        #pragma unroll
        for (int i = tid; i < HD * 8; i += 128) {
            const int row = i >> 3, seg = (i & 7) * 8;
            const uint32_t so = (uint32_t)(row * VSP + seg) * 2;
            CP16(bb + KB_VH + so, vth + (size_t)row * SEQ + j0 + seg);
            CP16(bb + KB_VL + so, vtl + (size_t)row * SEQ + j0 + seg);
        }
        CP_COMMIT();
    };

    issue_kv(0, 0);
    for (int i = tid; i < FQ * 4; i += 128) {
        const int row = i >> 2, seg = (i & 3) * 8;
        *reinterpret_cast<float4*>(&sQh[row * KSP + seg]) =
            *reinterpret_cast<const float4*>(&qkh[(size_t)(q0 + row) * RKD + seg]);
        *reinterpret_cast<float4*>(&sQl[row * KSP + seg]) =
            *reinterpret_cast<const float4*>(&qkl[(size_t)(q0 + row) * RKD + seg]);
    }
    __syncthreads();

    const int a_r = lane & 15, a_c = (lane >> 4) * 8;
    const int b_r = (lane & 7) + ((lane >> 4) << 3), b_c = ((lane >> 3) & 1) * 8;

    const uint32_t sQh_u = sbase + AQH_OFF, sQl_u = sbase + AQL_OFF;

    uint32_t qh[2][4], ql[2][4];
    #pragma unroll
    for (int kc = 0; kc < 2; kc++) {
        const uint32_t off = (uint32_t)((wid * 16 + a_r) * KSP + kc * 16 + a_c) * 2;
        ldsm_x4(sQh_u + off, qh[kc][0], qh[kc][1], qh[kc][2], qh[kc][3]);
        ldsm_x4(sQl_u + off, ql[kc][0], ql[kc][1], ql[kc][2], ql[kc][3]);
    }

    float Od[8][4] = {};
    float m0 = -1e30f, m1 = -1e30f, l0 = 0.f, l1 = 0.f;
    const int myrow = q0 + wid * 16 + (lane >> 2);

    for (int kt = 0; kt <= qt; kt++) {
        const int j0 = kt * FK;

        if (kt < qt) { issue_kv((kt + 1) * FK, (kt + 1) & 1); CP_WAIT1(); }
        else         { CP_WAIT0(); }
        __syncthreads();

        const uint32_t kb_ = sbase + AKV0 + (uint32_t)(kt & 1) * KVBUF;
        const uint32_t sKh_u = kb_ + KB_KH, sKl_u = kb_ + KB_KL;
        const uint32_t sVh_u = kb_ + KB_VH, sVl_u = kb_ + KB_VL;

        float S[8][4];
        #pragma unroll
        for (int nt = 0; nt < 8; nt++)
            #pragma unroll
            for (int e = 0; e < 4; e++) S[nt][e] = 0.f;

        #pragma unroll
        for (int kc = 0; kc < 2; kc++) {
            #pragma unroll
            for (int g = 0; g < 4; g++) {
                uint32_t kb[4], kl[4];
                const uint32_t off = (uint32_t)((g * 16 + b_r) * KSP + kc * 16 + b_c) * 2;
                ldsm_x4(sKh_u + off, kb[0], kb[1], kb[2], kb[3]);
                ldsm_x4(sKl_u + off, kl[0], kl[1], kl[2], kl[3]);
                #pragma unroll
                for (int t = 0; t < 2; t++) {
                    const int nt = g * 2 + t, hp = t * 2;
                    mma16816(S[nt], qh[kc][0], qh[kc][1], qh[kc][2], qh[kc][3],
                             kb[hp], kb[hp + 1]);
                    mma16816(S[nt], qh[kc][0], qh[kc][1], qh[kc][2], qh[kc][3],
                             kl[hp], kl[hp + 1]);
                    mma16816(S[nt], ql[kc][0], ql[kc][1], ql[kc][2], ql[kc][3],
                             kb[hp], kb[hp + 1]);
                }
            }
        }

        if (kt == qt) {
            #pragma unroll
            for (int nt = 0; nt < 8; nt++) {
                const int col = j0 + nt * 8 + (lane & 3) * 2;
                if (col     > myrow)     S[nt][0] = -1e30f;
                if (col + 1 > myrow)     S[nt][1] = -1e30f;
                if (col     > myrow + 8) S[nt][2] = -1e30f;
                if (col + 1 > myrow + 8) S[nt][3] = -1e30f;
            }
        }

        float r0 = -1e30f, r1 = -1e30f;
        #pragma unroll
        for (int nt = 0; nt < 8; nt++) {
            r0 = fmaxf(r0, fmaxf(S[nt][0], S[nt][1]));
            r1 = fmaxf(r1, fmaxf(S[nt][2], S[nt][3]));
        }
        r0 = fmaxf(r0, __shfl_xor_sync(0xffffffff, r0, 1));
        r0 = fmaxf(r0, __shfl_xor_sync(0xffffffff, r0, 2));
        r1 = fmaxf(r1, __shfl_xor_sync(0xffffffff, r1, 1));
        r1 = fmaxf(r1, __shfl_xor_sync(0xffffffff, r1, 2));

        const float mn0 = fmaxf(m0, r0), mn1 = fmaxf(m1, r1);
        const float c0 = exp2f(m0 - mn0), c1 = exp2f(m1 - mn1);
        m0 = mn0; m1 = mn1;

        float s0 = 0.f, s1 = 0.f;
        #pragma unroll
        for (int nt = 0; nt < 8; nt++) {
            S[nt][0] = exp2f(S[nt][0] - mn0);
            S[nt][1] = exp2f(S[nt][1] - mn0);
            S[nt][2] = exp2f(S[nt][2] - mn1);
            S[nt][3] = exp2f(S[nt][3] - mn1);
            s0 += S[nt][0] + S[nt][1];
            s1 += S[nt][2] + S[nt][3];
        }
        l0 = l0 * c0 + s0;
        l1 = l1 * c1 + s1;

        #pragma unroll
        for (int nt = 0; nt < 8; nt++) {
            Od[nt][0] *= c0; Od[nt][1] *= c0;
            Od[nt][2] *= c1; Od[nt][3] *= c1;
        }

        #pragma unroll
        for (int kc = 0; kc < 4; kc++) {
            uint32_t pa[4], pl[4];
            {
                const float x0 = S[2 * kc][0],     y0 = S[2 * kc][1];
                const float x1 = S[2 * kc][2],     y1 = S[2 * kc][3];
                const float x2 = S[2 * kc + 1][0], y2 = S[2 * kc + 1][1];
                const float x3 = S[2 * kc + 1][2], y3 = S[2 * kc + 1][3];
                pa[0] = pack_bf16(x0, y0); pa[1] = pack_bf16(x1, y1);
                pa[2] = pack_bf16(x2, y2); pa[3] = pack_bf16(x3, y3);
                __nv_bfloat162 h0 = *reinterpret_cast<__nv_bfloat162*>(&pa[0]);
                __nv_bfloat162 h1 = *reinterpret_cast<__nv_bfloat162*>(&pa[1]);
                __nv_bfloat162 h2 = *reinterpret_cast<__nv_bfloat162*>(&pa[2]);
                __nv_bfloat162 h3 = *reinterpret_cast<__nv_bfloat162*>(&pa[3]);
                pl[0] = pack_bf16(x0 - __bfloat162float(h0.x), y0 - __bfloat162float(h0.y));
                pl[1] = pack_bf16(x1 - __bfloat162float(h1.x), y1 - __bfloat162float(h1.y));
                pl[2] = pack_bf16(x2 - __bfloat162float(h2.x), y2 - __bfloat162float(h2.y));
                pl[3] = pack_bf16(x3 - __bfloat162float(h3.x), y3 - __bfloat162float(h3.y));
            }
            #pragma unroll
            for (int g = 0; g < 4; g++) {
                uint32_t vb[4], vl[4];
                const uint32_t off = (uint32_t)((g * 16 + b_r) * VSP + kc * 16 + b_c) * 2;
                ldsm_x4(sVh_u + off, vb[0], vb[1], vb[2], vb[3]);
                ldsm_x4(sVl_u + off, vl[0], vl[1], vl[2], vl[3]);
                #pragma unroll
                for (int t = 0; t < 2; t++) {
                    const int nt = g * 2 + t, hp = t * 2;
                    mma16816(Od[nt], pa[0], pa[1], pa[2], pa[3], vb[hp], vb[hp + 1]);
                    mma16816(Od[nt], pl[0], pl[1], pl[2], pl[3], vb[hp], vb[hp + 1]);
                    mma16816(Od[nt], pa[0], pa[1], pa[2], pa[3], vl[hp], vl[hp + 1]);
                }
            }
        }
        __syncthreads();
    }

    l0 += __shfl_xor_sync(0xffffffff, l0, 1);
    l0 += __shfl_xor_sync(0xffffffff, l0, 2);
    l1 += __shfl_xor_sync(0xffffffff, l1, 1);
    l1 += __shfl_xor_sync(0xffffffff, l1, 2);
    const float i0 = 1.f / l0, i1 = 1.f / l1;

    const size_t base0 = ((size_t)(b * SEQ + myrow)) * CH + h * HD;
    const size_t base1 = base0 + (size_t)8 * CH;
    #pragma unroll
    for (int nt = 0; nt < 8; nt++) {
        const int d = nt * 8 + (lane & 3) * 2;
        float v;
        __nv_bfloat16 hh;
        v = Od[nt][0] * i0; hh = __float2bfloat16(v);
        g_aoh[base0 + d]     = hh; g_aol[base0 + d]     = __float2bfloat16(v - __bfloat162float(hh));
        v = Od[nt][1] * i0; hh = __float2bfloat16(v);
        g_aoh[base0 + d + 1] = hh; g_aol[base0 + d + 1] = __float2bfloat16(v - __bfloat162float(hh));
        v = Od[nt][2] * i1; hh = __float2bfloat16(v);
        g_aoh[base1 + d]     = hh; g_aol[base1 + d]     = __float2bfloat16(v - __bfloat162float(hh));
        v = Od[nt][3] * i1; hh = __float2bfloat16(v);
        g_aoh[base1 + d + 1] = hh; g_aol[base1 + d + 1] = __float2bfloat16(v - __bfloat162float(hh));
    }
}

// ---------------------------------------------------------------------------
// Launch
// ---------------------------------------------------------------------------
extern "C" void kernel_launch(void* const* d_in, const int* in_sizes, int n_in,
                              void* d_out, int out_size)
{
    const float* x   = (const float*)d_in[0];
    const float* Wq1 = (const float*)d_in[1];
    const float* Wk1 = (const float*)d_in[2];
    const float* Wq2 = (const float*)d_in[3];
    const float* Wk2 = (const float*)d_in[4];
    const float* Wv  = (const float*)d_in[5];
    const float* Wo  = (const float*)d_in[6];
    const float* bo  = (const float*)d_in[7];
    float* out = (float*)d_out;

    cudaFuncSetAttribute(gemm_bf16x3, cudaFuncAttributeMaxDynamicSharedMemorySize,
                         GEMM_SMEM_BYTES);
    cudaFuncSetAttribute(attn_mma_kernel, cudaFuncAttributeMaxDynamicSharedMemorySize,
                         ATTN_SMEM_BYTES);

    __nv_bfloat16 *xh, *xl, *wcvh, *wcvl, *woh, *wol, *aoh, *aol;
    float *projv;
    cudaGetSymbolAddress((void**)&xh,   g_xh);
    cudaGetSymbolAddress((void**)&xl,   g_xl);
    cudaGetSymbolAddress((void**)&wcvh, g_wcvh);
    cudaGetSymbolAddress((void**)&wcvl, g_wcvl);
    cudaGetSymbolAddress((void**)&woh,  g_woh);
    cudaGetSymbolAddress((void**)&wol,  g_wol);
    cudaGetSymbolAddress((void**)&aoh,  g_aoh);
    cudaGetSymbolAddress((void**)&aol,  g_aol);
    cudaGetSymbolAddress((void**)&projv, g_projv);

    const int SB = 256;
    // one fused split launch for everything
    mega_split_kernel<<<(TOTSPLIT/4 + SB-1)/SB, SB>>>(x, Wq1, Wk1, Wq2, Wk2, Wv, Wo);

    // fused proj|V GEMM: [4096 x 1408]
    gemm_bf16x3<<<dim3(MROWS/TM, PVC/TN), GT, GEMM_SMEM_BYTES>>>(
        xh, xl, wcvh, wcvl, nullptr, projv, PVC, CH);

    form_qkkk_kernel<<<(MROWS*NH + SB-1)/SB, SB>>>();
    vt_convert_kernel<<<dim3(SEQ/64, BH), 256>>>();

    attn_mma_kernel<<<dim3(SEQ/FQ, BH), 128, ATTN_SMEM_BYTES>>>();

    gemm_bf16x3<<<dim3(MROWS/TM, CH/TN), GT, GEMM_SMEM_BYTES>>>(
        aoh, aol, woh, wol, bo, out, CH, CH);
}

// round 14
// speedup vs baseline: 1.3685x; 1.0462x over previous
#include <cuda_runtime.h>
#include <cuda_bf16.h>
#include <math.h>
#include <stdint.h>

// ---------------------------------------------------------------------------
// Problem constants (B=2, N=2048, C=1024, H=16, R1=4, R2=8, HEAD_DIM=64)
// ---------------------------------------------------------------------------
#define BATCH 2
#define SEQ   2048
#define CH    1024
#define NH    16
#define RR1   4
#define RR2   8
#define HD    64
#define RKD   32
#define MROWS (BATCH*SEQ)     // 4096
#define PROJC 384
#define PVC   (PROJC+CH)      // 1408
#define BH    (BATCH*NH)      // 32

#define L2E  1.44269504088896341f
__device__ __constant__ float kQSCALE = 0.17677669529663687f * 1.44269504088896341f;

// ---------------------------------------------------------------------------
// Scratch
// ---------------------------------------------------------------------------
__device__ __nv_bfloat16 g_xh  [MROWS * CH];
__device__ __nv_bfloat16 g_xl  [MROWS * CH];
__device__ __nv_bfloat16 g_wcvh[PVC * CH];
__device__ __nv_bfloat16 g_wcvl[PVC * CH];
__device__ __nv_bfloat16 g_woh [CH * CH];
__device__ __nv_bfloat16 g_wol [CH * CH];
__device__ __nv_bfloat16 g_aoh [MROWS * CH];
__device__ __nv_bfloat16 g_aol [MROWS * CH];

__device__ float g_projv[(size_t)MROWS * PVC];

__device__ __nv_bfloat16 g_qkh[(size_t)BH * SEQ * RKD];
__device__ __nv_bfloat16 g_qkl[(size_t)BH * SEQ * RKD];
__device__ __nv_bfloat16 g_kkh[(size_t)BH * SEQ * RKD];
__device__ __nv_bfloat16 g_kkl[(size_t)BH * SEQ * RKD];
__device__ __nv_bfloat16 g_vth[(size_t)BH * HD * SEQ];
__device__ __nv_bfloat16 g_vtl[(size_t)BH * HD * SEQ];

// ---------------------------------------------------------------------------
// Helpers
// ---------------------------------------------------------------------------
__device__ __forceinline__ uint32_t smem_u32(const void* p) {
    uint32_t a;
    asm("{ .reg .u64 t; cvta.to.shared.u64 t, %1; cvt.u32.u64 %0, t; }"
        : "=r"(a) : "l"(p));
    return a;
}

__device__ __forceinline__ void ldsm_x4(uint32_t addr, uint32_t& r0, uint32_t& r1,
                                        uint32_t& r2, uint32_t& r3) {
    asm volatile("ldmatrix.sync.aligned.m8n8.x4.shared.b16 {%0,%1,%2,%3}, [%4];"
                 : "=r"(r0), "=r"(r1), "=r"(r2), "=r"(r3) : "r"(addr));
}

__device__ __forceinline__ void mma16816(float* c, uint32_t a0, uint32_t a1,
                                         uint32_t a2, uint32_t a3,
                                         uint32_t b0, uint32_t b1) {
    asm volatile(
        "mma.sync.aligned.m16n8k16.row.col.f32.bf16.bf16.f32 "
        "{%0,%1,%2,%3}, {%4,%5,%6,%7}, {%8,%9}, {%0,%1,%2,%3};"
        : "+f"(c[0]), "+f"(c[1]), "+f"(c[2]), "+f"(c[3])
        : "r"(a0), "r"(a1), "r"(a2), "r"(a3), "r"(b0), "r"(b1));
}

__device__ __forceinline__ uint32_t pack_bf16(float x, float y) {
    __nv_bfloat162 t = __floats2bfloat162_rn(x, y);
    return *reinterpret_cast<uint32_t*>(&t);
}

#define SW64(o)  ((o) ^ ((((uint32_t)(o)) >> 3) & 0x30))
#define SW128(o) ((o) ^ ((((uint32_t)(o)) >> 3) & 0x70))

#define CP16(sm, gp) \
    asm volatile("cp.async.cg.shared.global [%0], [%1], 16;" \
                 :: "r"(sm), "l"(gp) : "memory")
#define CP_COMMIT() asm volatile("cp.async.commit_group;" ::: "memory")
#define CP_WAIT0()  asm volatile("cp.async.wait_group 0;" ::: "memory")
#define CP_WAIT1()  asm volatile("cp.async.wait_group 1;" ::: "memory")

// ---------------------------------------------------------------------------
// Mega split (unchanged from R13)
// ---------------------------------------------------------------------------
#define XSZ   (MROWS*CH)
#define WQ1SZ (64*CH)
#define WK1SZ (64*CH)
#define WQ2SZ (128*CH)
#define WK2SZ (128*CH)
#define WVSZ  (CH*CH)
#define WOSZ  (CH*CH)
#define WCATSZ (WQ1SZ+WK1SZ+WQ2SZ+WK2SZ)
#define TOTSPLIT (XSZ + WCATSZ + WVSZ + WOSZ)

__global__ __launch_bounds__(256)
void mega_split_kernel(const float* __restrict__ x,
                       const float* __restrict__ Wq1,
                       const float* __restrict__ Wk1,
                       const float* __restrict__ Wq2,
                       const float* __restrict__ Wk2,
                       const float* __restrict__ Wv,
                       const float* __restrict__ Wo)
{
    const int i4 = (blockIdx.x * blockDim.x + threadIdx.x) * 4;
    if (i4 >= TOTSPLIT) return;

    const float* src;
    __nv_bfloat16 *dh, *dl;
    int off, dsto;

    if (i4 < XSZ) {
        src = x; off = i4; dh = g_xh; dl = g_xl; dsto = off;
    } else if (i4 < XSZ + WCATSZ + WVSZ) {
        const int wo = i4 - XSZ;
        dh = g_wcvh; dl = g_wcvl; dsto = wo;
        if      (wo < WQ1SZ)             { src = Wq1; off = wo; }
        else if (wo < WQ1SZ+WK1SZ)       { src = Wk1; off = wo - WQ1SZ; }
        else if (wo < WQ1SZ+WK1SZ+WQ2SZ) { src = Wq2; off = wo - (WQ1SZ+WK1SZ); }
        else if (wo < WCATSZ)            { src = Wk2; off = wo - (WQ1SZ+WK1SZ+WQ2SZ); }
        else                             { src = Wv;  off = wo - WCATSZ; }
    } else {
        const int wo = i4 - (XSZ + WCATSZ + WVSZ);
        src = Wo; off = wo; dh = g_woh; dl = g_wol; dsto = wo;
    }

    const float4 v4 = *reinterpret_cast<const float4*>(&src[off]);
    float vv[4] = {v4.x, v4.y, v4.z, v4.w};
    uint32_t hs[2], ls[2];
    #pragma unroll
    for (int p = 0; p < 2; p++) {
        __nv_bfloat162 hp = __floats2bfloat162_rn(vv[2*p], vv[2*p+1]);
        hs[p] = *reinterpret_cast<uint32_t*>(&hp);
        float r0 = vv[2*p]   - __bfloat162float(hp.x);
        float r1 = vv[2*p+1] - __bfloat162float(hp.y);
        ls[p] = pack_bf16(r0, r1);
    }
    *reinterpret_cast<uint2*>(&dh[dsto]) = make_uint2(hs[0], hs[1]);
    *reinterpret_cast<uint2*>(&dl[dsto]) = make_uint2(ls[0], ls[1]);
}

// ---------------------------------------------------------------------------
// bf16x3 NT GEMM (unchanged from R13)
// ---------------------------------------------------------------------------
#define TM 128
#define TN 128
#define TKC 32
#define GT 256
#define SPAD 40
#define OPB   10240u
#define BUFB  (4u*OPB)
#define GEMM_SMEM_BYTES (2*BUFB)

__global__ __launch_bounds__(GT, 2)
void gemm_bf16x3(const __nv_bfloat16* __restrict__ Ahi,
                 const __nv_bfloat16* __restrict__ Alo,
                 const __nv_bfloat16* __restrict__ Bhi,
                 const __nv_bfloat16* __restrict__ Blo,
                 const float* __restrict__ bias,
                 float* __restrict__ C, int Nc, int K)
{
    extern __shared__ __align__(16) char gsm[];
    const uint32_t sbase = smem_u32(gsm);

    const int tid  = threadIdx.x;
    const int wid  = tid >> 5;
    const int lane = tid & 31;
    const int wm   = wid >> 2;
    const int wn   = wid & 3;

    const int m0 = blockIdx.x * TM;
    const int n0 = blockIdx.y * TN;

    float acc[4][4][4] = {};

    const int a_r = lane & 15, a_c = (lane >> 4) * 8;
    const int b_r = (lane & 7) + ((lane >> 4) << 3), b_c = ((lane >> 3) & 1) * 8;

    auto issue = [&](int k0, int buf) {
        const uint32_t bb = sbase + (uint32_t)buf * BUFB;
        #pragma unroll
        for (int i = tid; i < TM * 4; i += GT) {
            const int row = i >> 2, seg = (i & 3) * 8;
            const uint32_t so = (uint32_t)(row * SPAD + seg) * 2;
            const size_t ga = (size_t)(m0 + row) * K + k0 + seg;
            const size_t gb = (size_t)(n0 + row) * K + k0 + seg;
            CP16(bb + 0*OPB + so, Ahi + ga);
            CP16(bb + 1*OPB + so, Alo + ga);
            CP16(bb + 2*OPB + so, Bhi + gb);
            CP16(bb + 3*OPB + so, Blo + gb);
        }
        CP_COMMIT();
    };

    const int nk = K / TKC;
    issue(0, 0);

    for (int k = 0; k < nk; k++) {
        if (k + 1 < nk) { issue((k + 1) * TKC, (k + 1) & 1); CP_WAIT1(); }
        else            { CP_WAIT0(); }
        __syncthreads();

        const uint32_t bb = sbase + (uint32_t)(k & 1) * BUFB;
        const uint32_t uAh = bb, uAl = bb + OPB, uBh = bb + 2*OPB, uBl = bb + 3*OPB;

        #pragma unroll
        for (int kp = 0; kp < 2; kp++) {
            const int kb = kp * 16;
            uint32_t ah[4][4], al[4][4], bh[2][4], bl[2][4];

            #pragma unroll
            for (int mt = 0; mt < 4; mt++) {
                const uint32_t off =
                    (uint32_t)((wm * 64 + mt * 16 + a_r) * SPAD + kb + a_c) * 2;
                ldsm_x4(uAh + off, ah[mt][0], ah[mt][1], ah[mt][2], ah[mt][3]);
                ldsm_x4(uAl + off, al[mt][0], al[mt][1], al[mt][2], al[mt][3]);
            }
            #pragma unroll
            for (int ng = 0; ng < 2; ng++) {
                const uint32_t off =
                    (uint32_t)((wn * 32 + ng * 16 + b_r) * SPAD + kb + b_c) * 2;
                ldsm_x4(uBh + off, bh[ng][0], bh[ng][1], bh[ng][2], bh[ng][3]);
                ldsm_x4(uBl + off, bl[ng][0], bl[ng][1], bl[ng][2], bl[ng][3]);
            }

            #pragma unroll
            for (int mt = 0; mt < 4; mt++) {
                #pragma unroll
                for (int nt = 0; nt < 4; nt++) {
                    const int ng = nt >> 1, hp = (nt & 1) * 2;
                    mma16816(acc[mt][nt], ah[mt][0], ah[mt][1], ah[mt][2], ah[mt][3],
                             bh[ng][hp], bh[ng][hp + 1]);
                    mma16816(acc[mt][nt], ah[mt][0], ah[mt][1], ah[mt][2], ah[mt][3],
                             bl[ng][hp], bl[ng][hp + 1]);
                    mma16816(acc[mt][nt], al[mt][0], al[mt][1], al[mt][2], al[mt][3],
                             bh[ng][hp], bh[ng][hp + 1]);
                }
            }
        }
        __syncthreads();
    }

    const int er = lane >> 2, ec = (lane & 3) * 2;
    #pragma unroll
    for (int mt = 0; mt < 4; mt++) {
        #pragma unroll
        for (int nt = 0; nt < 4; nt++) {
            const int row = m0 + wm * 64 + mt * 16 + er;
            const int col = n0 + wn * 32 + nt * 8 + ec;
            float b0 = bias ? bias[col] : 0.f;
            float b1 = bias ? bias[col + 1] : 0.f;
            C[(size_t)row * Nc + col]           = acc[mt][nt][0] + b0;
            C[(size_t)row * Nc + col + 1]       = acc[mt][nt][1] + b1;
            C[(size_t)(row + 8) * Nc + col]     = acc[mt][nt][2] + b0;
            C[(size_t)(row + 8) * Nc + col + 1] = acc[mt][nt][3] + b1;
        }
    }
}

// ---------------------------------------------------------------------------
// Form qk/kk (unchanged from R13)
// ---------------------------------------------------------------------------
__global__ void form_qkkk_kernel()
{
    const int idx = blockIdx.x * blockDim.x + threadIdx.x;
    if (idx >= MROWS * NH) return;
    const int h  = idx % NH;
    const int bn = idx / NH;
    const int b  = bn / SEQ;
    const int n  = bn % SEQ;

    const float* pr = &g_projv[(size_t)bn * PVC];
    float a1[RR1], a2[RR2];
    #pragma unroll
    for (int r = 0; r < RR1; r++) a1[r] = pr[h * RR1 + r];
    #pragma unroll
    for (int r = 0; r < RR2; r++) a2[r] = pr[128 + h * RR2 + r];

    const size_t base = (((size_t)b * NH + h) * SEQ + n) * RKD;

    uint32_t hs[16], ls[16];
    #pragma unroll
    for (int r1 = 0; r1 < RR1; r1++)
        #pragma unroll
        for (int r2 = 0; r2 < RR2; r2 += 2) {
            const int p = (r1 * RR2 + r2) >> 1;
            float v0 = a1[r1] * a2[r2]     * kQSCALE;
            float v1 = a1[r1] * a2[r2 + 1] * kQSCALE;
            __nv_bfloat162 hp = __floats2bfloat162_rn(v0, v1);
            hs[p] = *reinterpret_cast<uint32_t*>(&hp);
            ls[p] = pack_bf16(v0 - __bfloat162float(hp.x), v1 - __bfloat162float(hp.y));
        }
    #pragma unroll
    for (int q = 0; q < 4; q++) {
        *reinterpret_cast<uint4*>(&g_qkh[base + q * 8]) =
            make_uint4(hs[4*q], hs[4*q+1], hs[4*q+2], hs[4*q+3]);
        *reinterpret_cast<uint4*>(&g_qkl[base + q * 8]) =
            make_uint4(ls[4*q], ls[4*q+1], ls[4*q+2], ls[4*q+3]);
    }

    #pragma unroll
    for (int r = 0; r < RR1; r++) a1[r] = pr[64 + h * RR1 + r];
    #pragma unroll
    for (int r = 0; r < RR2; r++) a2[r] = pr[256 + h * RR2 + r];

    #pragma unroll
    for (int r1 = 0; r1 < RR1; r1++)
        #pragma unroll
        for (int r2 = 0; r2 < RR2; r2 += 2) {
            const int p = (r1 * RR2 + r2) >> 1;
            float v0 = a1[r1] * a2[r2];
            float v1 = a1[r1] * a2[r2 + 1];
            __nv_bfloat162 hp = __floats2bfloat162_rn(v0, v1);
            hs[p] = *reinterpret_cast<uint32_t*>(&hp);
            ls[p] = pack_bf16(v0 - __bfloat162float(hp.x), v1 - __bfloat162float(hp.y));
        }
    #pragma unroll
    for (int q = 0; q < 4; q++) {
        *reinterpret_cast<uint4*>(&g_kkh[base + q * 8]) =
            make_uint4(hs[4*q], hs[4*q+1], hs[4*q+2], hs[4*q+3]);
        *reinterpret_cast<uint4*>(&g_kkl[base + q * 8]) =
            make_uint4(ls[4*q], ls[4*q+1], ls[4*q+2], ls[4*q+3]);
    }
}

// ---------------------------------------------------------------------------
// V transpose+split (unchanged from R13)
// ---------------------------------------------------------------------------
__global__ __launch_bounds__(256)
void vt_convert_kernel()
{
    __shared__ float sm[64][65];
    const int bh = blockIdx.y;
    const int b = bh / NH, h = bh % NH;
    const int n0 = blockIdx.x * 64;
    const int tid = threadIdx.x;

    for (int i = tid; i < 64 * 16; i += 256) {
        const int n = i >> 4, seg = (i & 15) * 4;
        const float4 v4 = *reinterpret_cast<const float4*>(
            &g_projv[((size_t)(b * SEQ + n0 + n)) * PVC + PROJC + h * HD + seg]);
        sm[n][seg + 0] = v4.x;
        sm[n][seg + 1] = v4.y;
        sm[n][seg + 2] = v4.z;
        sm[n][seg + 3] = v4.w;
    }
    __syncthreads();

    for (int i = tid; i < 64 * 64; i += 256) {
        const int d = i >> 6, n = i & 63;
        const float v = sm[n][d];
        const __nv_bfloat16 hh = __float2bfloat16(v);
        const size_t o = ((size_t)bh * HD + d) * SEQ + n0 + n;
        g_vth[o] = hh;
        g_vtl[o] = __float2bfloat16(v - __bfloat162float(hh));
    }
}

// ---------------------------------------------------------------------------
// MMA flash attention — compact swizzled smem for 4 CTAs/SM.
// K/Q tiles: dense 64B rows, SW64. V tiles: dense 128B rows, SW128.
// Q overlaid into buffer 1 (consumed to regs before buffer 1's first fill).
// Dynamic smem: 2 x 24576 = 49152 B.
// ---------------------------------------------------------------------------
#define FQ 64
#define FK 64
#define KB_KH   0u
#define KB_KL   4096u
#define KB_VH   8192u
#define KB_VL   16384u
#define KVBUF   24576u
#define ATTN_SMEM_BYTES (2*24576)   // 49152

__global__ __launch_bounds__(128)
void attn_mma_kernel()
{
    extern __shared__ __align__(16) char asmem[];
    const uint32_t sbase = smem_u32(asmem);

    const int bh  = blockIdx.y;
    const int b   = bh / NH, h = bh % NH;
    const int qt  = (gridDim.x - 1) - blockIdx.x;   // LPT
    const int q0  = qt * FQ;
    const int tid = threadIdx.x;
    const int wid = tid >> 5;
    const int lane = tid & 31;

    const __nv_bfloat16* qkh = &g_qkh[(size_t)bh * SEQ * RKD];
    const __nv_bfloat16* qkl = &g_qkl[(size_t)bh * SEQ * RKD];
    const __nv_bfloat16* kkh = &g_kkh[(size_t)bh * SEQ * RKD];
    const __nv_bfloat16* kkl = &g_kkl[(size_t)bh * SEQ * RKD];
    const __nv_bfloat16* vth = &g_vth[(size_t)bh * HD * SEQ];
    const __nv_bfloat16* vtl = &g_vtl[(size_t)bh * HD * SEQ];

    auto issue_kv = [&](int j0, int buf) {
        const uint32_t bb = sbase + (uint32_t)buf * KVBUF;
        #pragma unroll
        for (int i = tid; i < FK * 4; i += 128) {
            const int row = i >> 2, sg = i & 3;
            const uint32_t o = (uint32_t)(row * 64 + sg * 16);
            const uint32_t so = SW64(o);
            CP16(bb + KB_KH + so, kkh + (size_t)(j0 + row) * RKD + sg * 8);
            CP16(bb + KB_KL + so, kkl + (size_t)(j0 + row) * RKD + sg * 8);
        }
        #pragma unroll
        for (int i = tid; i < HD * 8; i += 128) {
            const int row = i >> 3, sg = i & 7;
            const uint32_t o = (uint32_t)(row * 128 + sg * 16);
            const uint32_t so = SW128(o);
            CP16(bb + KB_VH + so, vth + (size_t)row * SEQ + j0 + sg * 8);
            CP16(bb + KB_VL + so, vtl + (size_t)row * SEQ + j0 + sg * 8);
        }
        CP_COMMIT();
    };

    // issue KV tile 0 into buffer 0, stage Q into buffer 1 region meanwhile
    issue_kv(0, 0);
    for (int i = tid; i < FQ * 4; i += 128) {
        const int row = i >> 2, sg = i & 3;
        const uint32_t o = (uint32_t)(row * 64 + sg * 16);
        const uint32_t so = SW64(o);
        *reinterpret_cast<float4*>(asmem + KVBUF + so) =
            *reinterpret_cast<const float4*>(&qkh[(size_t)(q0 + row) * RKD + sg * 8]);
        *reinterpret_cast<float4*>(asmem + KVBUF + 4096 + so) =
            *reinterpret_cast<const float4*>(&qkl[(size_t)(q0 + row) * RKD + sg * 8]);
    }
    __syncthreads();

    const int a_r = lane & 15, a_c = (lane >> 4) * 8;
    const int b_r = (lane & 7) + ((lane >> 4) << 3), b_c = ((lane >> 3) & 1) * 8;

    // lane-constant swizzle XOR terms
    const uint32_t qxor = (uint32_t)(((a_r * 64) >> 3) & 0x30);
    const uint32_t kxor = (uint32_t)(((b_r * 64) >> 3) & 0x30);
    const uint32_t vxor = (uint32_t)(((b_r * 128) >> 3) & 0x70);

    // Q fragments from buffer-1 overlay
    uint32_t qh[2][4], ql[2][4];
    {
        const uint32_t qb = sbase + KVBUF;
        const uint32_t xl_ = (uint32_t)(wid * 1024 + a_r * 64 + a_c * 2);
        #pragma unroll
        for (int kc = 0; kc < 2; kc++) {
            const uint32_t x = xl_ + kc * 32;
            ldsm_x4(qb + (x ^ qxor),        qh[kc][0], qh[kc][1], qh[kc][2], qh[kc][3]);
            ldsm_x4(qb + 4096 + (x ^ qxor), ql[kc][0], ql[kc][1], ql[kc][2], ql[kc][3]);
        }
    }
    __syncthreads();   // all Q reads done before buffer 1 is overwritten

    float Od[8][4] = {};
    float m0 = -1e30f, m1 = -1e30f, l0 = 0.f, l1 = 0.f;
    const int myrow = q0 + wid * 16 + (lane >> 2);

    for (int kt = 0; kt <= qt; kt++) {
        const int j0 = kt * FK;

        if (kt < qt) { issue_kv((kt + 1) * FK, (kt + 1) & 1); CP_WAIT1(); }
        else         { CP_WAIT0(); }
        __syncthreads();

        const uint32_t bb = sbase + (uint32_t)(kt & 1) * KVBUF;
        const uint32_t sKh_u = bb + KB_KH, sKl_u = bb + KB_KL;
        const uint32_t sVh_u = bb + KB_VH, sVl_u = bb + KB_VL;

        // ---- S = QK^T (bf16x3) ----
        float S[8][4];
        #pragma unroll
        for (int nt = 0; nt < 8; nt++)
            #pragma unroll
            for (int e = 0; e < 4; e++) S[nt][e] = 0.f;

        const uint32_t kxl = (uint32_t)(b_r * 64 + b_c * 2);
        #pragma unroll
        for (int kc = 0; kc < 2; kc++) {
            #pragma unroll
            for (int g = 0; g < 4; g++) {
                uint32_t kb[4], kl[4];
                const uint32_t x = (uint32_t)(g * 1024) + kxl + kc * 32;
                ldsm_x4(sKh_u + (x ^ kxor), kb[0], kb[1], kb[2], kb[3]);
                ldsm_x4(sKl_u + (x ^ kxor), kl[0], kl[1], kl[2], kl[3]);
                #pragma unroll
                for (int t = 0; t < 2; t++) {
                    const int nt = g * 2 + t, hp = t * 2;
                    mma16816(S[nt], qh[kc][0], qh[kc][1], qh[kc][2], qh[kc][3],
                             kb[hp], kb[hp + 1]);
                    mma16816(S[nt], qh[kc][0], qh[kc][1], qh[kc][2], qh[kc][3],
                             kl[hp], kl[hp + 1]);
                    mma16816(S[nt], ql[kc][0], ql[kc][1], ql[kc][2], ql[kc][3],
                             kb[hp], kb[hp + 1]);
                }
            }
        }

        // ---- causal mask on diagonal tile ----
        if (kt == qt) {
            #pragma unroll
            for (int nt = 0; nt < 8; nt++) {
                const int col = j0 + nt * 8 + (lane & 3) * 2;
                if (col     > myrow)     S[nt][0] = -1e30f;
                if (col + 1 > myrow)     S[nt][1] = -1e30f;
                if (col     > myrow + 8) S[nt][2] = -1e30f;
                if (col + 1 > myrow + 8) S[nt][3] = -1e30f;
            }
        }

        // ---- online softmax ----
        float r0 = -1e30f, r1 = -1e30f;
        #pragma unroll
        for (int nt = 0; nt < 8; nt++) {
            r0 = fmaxf(r0, fmaxf(S[nt][0], S[nt][1]));
            r1 = fmaxf(r1, fmaxf(S[nt][2], S[nt][3]));
        }
        r0 = fmaxf(r0, __shfl_xor_sync(0xffffffff, r0, 1));
        r0 = fmaxf(r0, __shfl_xor_sync(0xffffffff, r0, 2));
        r1 = fmaxf(r1, __shfl_xor_sync(0xffffffff, r1, 1));
        r1 = fmaxf(r1, __shfl_xor_sync(0xffffffff, r1, 2));

        const float mn0 = fmaxf(m0, r0), mn1 = fmaxf(m1, r1);
        const float c0 = exp2f(m0 - mn0), c1 = exp2f(m1 - mn1);
        m0 = mn0; m1 = mn1;

        float s0 = 0.f, s1 = 0.f;
        #pragma unroll
        for (int nt = 0; nt < 8; nt++) {
            S[nt][0] = exp2f(S[nt][0] - mn0);
            S[nt][1] = exp2f(S[nt][1] - mn0);
            S[nt][2] = exp2f(S[nt][2] - mn1);
            S[nt][3] = exp2f(S[nt][3] - mn1);
            s0 += S[nt][0] + S[nt][1];
            s1 += S[nt][2] + S[nt][3];
        }
        l0 = l0 * c0 + s0;
        l1 = l1 * c1 + s1;

        #pragma unroll
        for (int nt = 0; nt < 8; nt++) {
            Od[nt][0] *= c0; Od[nt][1] *= c0;
            Od[nt][2] *= c1; Od[nt][3] *= c1;
        }

        // ---- O += P * V (bf16x3) ----
        const uint32_t vxl = (uint32_t)(b_r * 128 + b_c * 2);
        #pragma unroll
        for (int kc = 0; kc < 4; kc++) {
            uint32_t pa[4], pl[4];
            {
                const float x0 = S[2 * kc][0],     y0 = S[2 * kc][1];
                const float x1 = S[2 * kc][2],     y1 = S[2 * kc][3];
                const float x2 = S[2 * kc + 1][0], y2 = S[2 * kc + 1][1];
                const float x3 = S[2 * kc + 1][2], y3 = S[2 * kc + 1][3];
                pa[0] = pack_bf16(x0, y0); pa[1] = pack_bf16(x1, y1);
                pa[2] = pack_bf16(x2, y2); pa[3] = pack_bf16(x3, y3);
                __nv_bfloat162 h0 = *reinterpret_cast<__nv_bfloat162*>(&pa[0]);
                __nv_bfloat162 h1 = *reinterpret_cast<__nv_bfloat162*>(&pa[1]);
                __nv_bfloat162 h2 = *reinterpret_cast<__nv_bfloat162*>(&pa[2]);
                __nv_bfloat162 h3 = *reinterpret_cast<__nv_bfloat162*>(&pa[3]);
                pl[0] = pack_bf16(x0 - __bfloat162float(h0.x), y0 - __bfloat162float(h0.y));
                pl[1] = pack_bf16(x1 - __bfloat162float(h1.x), y1 - __bfloat162float(h1.y));
                pl[2] = pack_bf16(x2 - __bfloat162float(h2.x), y2 - __bfloat162float(h2.y));
                pl[3] = pack_bf16(x3 - __bfloat162float(h3.x), y3 - __bfloat162float(h3.y));
            }
            #pragma unroll
            for (int g = 0; g < 4; g++) {
                uint32_t vb[4], vl[4];
                const uint32_t x = (uint32_t)(g * 2048) + vxl + kc * 32;
                ldsm_x4(sVh_u + (x ^ vxor), vb[0], vb[1], vb[2], vb[3]);
                ldsm_x4(sVl_u + (x ^ vxor), vl[0], vl[1], vl[2], vl[3]);
                #pragma unroll
                for (int t = 0; t < 2; t++) {
                    const int nt = g * 2 + t, hp = t * 2;
                    mma16816(Od[nt], pa[0], pa[1], pa[2], pa[3], vb[hp], vb[hp + 1]);
                    mma16816(Od[nt], pl[0], pl[1], pl[2], pl[3], vb[hp], vb[hp + 1]);
                    mma16816(Od[nt], pa[0], pa[1], pa[2], pa[3], vl[hp], vl[hp + 1]);
                }
            }
        }
        __syncthreads();
    }

    // ---- finalize: scale + fused bf16 hi/lo split ----
    l0 += __shfl_xor_sync(0xffffffff, l0, 1);
    l0 += __shfl_xor_sync(0xffffffff, l0, 2);
    l1 += __shfl_xor_sync(0xffffffff, l1, 1);
    l1 += __shfl_xor_sync(0xffffffff, l1, 2);
    const float i0 = 1.f / l0, i1 = 1.f / l1;

    const size_t base0 = ((size_t)(b * SEQ + myrow)) * CH + h * HD;
    const size_t base1 = base0 + (size_t)8 * CH;
    #pragma unroll
    for (int nt = 0; nt < 8; nt++) {
        const int d = nt * 8 + (lane & 3) * 2;
        float v;
        __nv_bfloat16 hh;
        v = Od[nt][0] * i0; hh = __float2bfloat16(v);
        g_aoh[base0 + d]     = hh; g_aol[base0 + d]     = __float2bfloat16(v - __bfloat162float(hh));
        v = Od[nt][1] * i0; hh = __float2bfloat16(v);
        g_aoh[base0 + d + 1] = hh; g_aol[base0 + d + 1] = __float2bfloat16(v - __bfloat162float(hh));
        v = Od[nt][2] * i1; hh = __float2bfloat16(v);
        g_aoh[base1 + d]     = hh; g_aol[base1 + d]     = __float2bfloat16(v - __bfloat162float(hh));
        v = Od[nt][3] * i1; hh = __float2bfloat16(v);
        g_aoh[base1 + d + 1] = hh; g_aol[base1 + d + 1] = __float2bfloat16(v - __bfloat162float(hh));
    }
}

// ---------------------------------------------------------------------------
// Launch
// ---------------------------------------------------------------------------
extern "C" void kernel_launch(void* const* d_in, const int* in_sizes, int n_in,
                              void* d_out, int out_size)
{
    const float* x   = (const float*)d_in[0];
    const float* Wq1 = (const float*)d_in[1];
    const float* Wk1 = (const float*)d_in[2];
    const float* Wq2 = (const float*)d_in[3];
    const float* Wk2 = (const float*)d_in[4];
    const float* Wv  = (const float*)d_in[5];
    const float* Wo  = (const float*)d_in[6];
    const float* bo  = (const float*)d_in[7];
    float* out = (float*)d_out;

    cudaFuncSetAttribute(gemm_bf16x3, cudaFuncAttributeMaxDynamicSharedMemorySize,
                         GEMM_SMEM_BYTES);
    cudaFuncSetAttribute(attn_mma_kernel, cudaFuncAttributeMaxDynamicSharedMemorySize,
                         ATTN_SMEM_BYTES);

    __nv_bfloat16 *xh, *xl, *wcvh, *wcvl, *woh, *wol, *aoh, *aol;
    float *projv;
    cudaGetSymbolAddress((void**)&xh,   g_xh);
    cudaGetSymbolAddress((void**)&xl,   g_xl);
    cudaGetSymbolAddress((void**)&wcvh, g_wcvh);
    cudaGetSymbolAddress((void**)&wcvl, g_wcvl);
    cudaGetSymbolAddress((void**)&woh,  g_woh);
    cudaGetSymbolAddress((void**)&wol,  g_wol);
    cudaGetSymbolAddress((void**)&aoh,  g_aoh);
    cudaGetSymbolAddress((void**)&aol,  g_aol);
    cudaGetSymbolAddress((void**)&projv, g_projv);

    const int SB = 256;
    mega_split_kernel<<<(TOTSPLIT/4 + SB-1)/SB, SB>>>(x, Wq1, Wk1, Wq2, Wk2, Wv, Wo);

    gemm_bf16x3<<<dim3(MROWS/TM, PVC/TN), GT, GEMM_SMEM_BYTES>>>(
        xh, xl, wcvh, wcvl, nullptr, projv, PVC, CH);

    form_qkkk_kernel<<<(MROWS*NH + SB-1)/SB, SB>>>();
    vt_convert_kernel<<<dim3(SEQ/64, BH), 256>>>();

    attn_mma_kernel<<<dim3(SEQ/FQ, BH), 128, ATTN_SMEM_BYTES>>>();

    gemm_bf16x3<<<dim3(MROWS/TM, CH/TN), GT, GEMM_SMEM_BYTES>>>(
        aoh, aol, woh, wol, bo, out, CH, CH);
}

// round 17
// speedup vs baseline: 1.3715x; 1.0021x over previous
#include <cuda_runtime.h>
#include <cuda_bf16.h>
#include <math.h>
#include <stdint.h>

// ---------------------------------------------------------------------------
// Problem constants (B=2, N=2048, C=1024, H=16, R1=4, R2=8, HEAD_DIM=64)
// ---------------------------------------------------------------------------
#define BATCH 2
#define SEQ   2048
#define CH    1024
#define NH    16
#define RR1   4
#define RR2   8
#define HD    64
#define RKD   32
#define MROWS (BATCH*SEQ)     // 4096
#define PROJC 384
#define PVC   (PROJC+CH)      // 1408
#define BH    (BATCH*NH)      // 32

#define L2E  1.44269504088896341f
__device__ __constant__ float kQSCALE = 0.17677669529663687f * 1.44269504088896341f;

// ---------------------------------------------------------------------------
// Scratch
// ---------------------------------------------------------------------------
__device__ __nv_bfloat16 g_xh  [MROWS * CH];
__device__ __nv_bfloat16 g_xl  [MROWS * CH];
__device__ __nv_bfloat16 g_wcvh[PVC * CH];
__device__ __nv_bfloat16 g_wcvl[PVC * CH];
__device__ __nv_bfloat16 g_woh [CH * CH];
__device__ __nv_bfloat16 g_wol [CH * CH];
__device__ __nv_bfloat16 g_aoh [MROWS * CH];
__device__ __nv_bfloat16 g_aol [MROWS * CH];

__device__ float g_projv[(size_t)MROWS * PVC];

__device__ __nv_bfloat16 g_qkh[(size_t)BH * SEQ * RKD];
__device__ __nv_bfloat16 g_qkl[(size_t)BH * SEQ * RKD];
__device__ __nv_bfloat16 g_kkh[(size_t)BH * SEQ * RKD];
__device__ __nv_bfloat16 g_kkl[(size_t)BH * SEQ * RKD];
__device__ __nv_bfloat16 g_vth[(size_t)BH * HD * SEQ];
__device__ __nv_bfloat16 g_vtl[(size_t)BH * HD * SEQ];

// ---------------------------------------------------------------------------
// Helpers
// ---------------------------------------------------------------------------
__device__ __forceinline__ uint32_t smem_u32(const void* p) {
    uint32_t a;
    asm("{ .reg .u64 t; cvta.to.shared.u64 t, %1; cvt.u32.u64 %0, t; }"
        : "=r"(a) : "l"(p));
    return a;
}

__device__ __forceinline__ void ldsm_x4(uint32_t addr, uint32_t& r0, uint32_t& r1,
                                        uint32_t& r2, uint32_t& r3) {
    asm volatile("ldmatrix.sync.aligned.m8n8.x4.shared.b16 {%0,%1,%2,%3}, [%4];"
                 : "=r"(r0), "=r"(r1), "=r"(r2), "=r"(r3) : "r"(addr));
}

__device__ __forceinline__ void mma16816(float* c, uint32_t a0, uint32_t a1,
                                         uint32_t a2, uint32_t a3,
                                         uint32_t b0, uint32_t b1) {
    asm volatile(
        "mma.sync.aligned.m16n8k16.row.col.f32.bf16.bf16.f32 "
        "{%0,%1,%2,%3}, {%4,%5,%6,%7}, {%8,%9}, {%0,%1,%2,%3};"
        : "+f"(c[0]), "+f"(c[1]), "+f"(c[2]), "+f"(c[3])
        : "r"(a0), "r"(a1), "r"(a2), "r"(a3), "r"(b0), "r"(b1));
}

__device__ __forceinline__ uint32_t pack_bf16(float x, float y) {
    __nv_bfloat162 t = __floats2bfloat162_rn(x, y);
    return *reinterpret_cast<uint32_t*>(&t);
}

#define SW64(o)  ((o) ^ ((((uint32_t)(o)) >> 3) & 0x30))
#define SW128(o) ((o) ^ ((((uint32_t)(o)) >> 3) & 0x70))

#define CP16(sm, gp) \
    asm volatile("cp.async.cg.shared.global [%0], [%1], 16;" \
                 :: "r"(sm), "l"(gp) : "memory")
#define CP_COMMIT() asm volatile("cp.async.commit_group;" ::: "memory")
#define CP_WAIT0()  asm volatile("cp.async.wait_group 0;" ::: "memory")
#define CP_WAIT1()  asm volatile("cp.async.wait_group 1;" ::: "memory")

// ---------------------------------------------------------------------------
// Mega split
// ---------------------------------------------------------------------------
#define XSZ   (MROWS*CH)
#define WQ1SZ (64*CH)
#define WK1SZ (64*CH)
#define WQ2SZ (128*CH)
#define WK2SZ (128*CH)
#define WVSZ  (CH*CH)
#define WOSZ  (CH*CH)
#define WCATSZ (WQ1SZ+WK1SZ+WQ2SZ+WK2SZ)
#define TOTSPLIT (XSZ + WCATSZ + WVSZ + WOSZ)

__global__ __launch_bounds__(256)
void mega_split_kernel(const float* __restrict__ x,
                       const float* __restrict__ Wq1,
                       const float* __restrict__ Wk1,
                       const float* __restrict__ Wq2,
                       const float* __restrict__ Wk2,
                       const float* __restrict__ Wv,
                       const float* __restrict__ Wo)
{
    const int i4 = (blockIdx.x * blockDim.x + threadIdx.x) * 4;
    if (i4 >= TOTSPLIT) return;

    const float* src;
    __nv_bfloat16 *dh, *dl;
    int off, dsto;

    if (i4 < XSZ) {
        src = x; off = i4; dh = g_xh; dl = g_xl; dsto = off;
    } else if (i4 < XSZ + WCATSZ + WVSZ) {
        const int wo = i4 - XSZ;
        dh = g_wcvh; dl = g_wcvl; dsto = wo;
        if      (wo < WQ1SZ)             { src = Wq1; off = wo; }
        else if (wo < WQ1SZ+WK1SZ)       { src = Wk1; off = wo - WQ1SZ; }
        else if (wo < WQ1SZ+WK1SZ+WQ2SZ) { src = Wq2; off = wo - (WQ1SZ+WK1SZ); }
        else if (wo < WCATSZ)            { src = Wk2; off = wo - (WQ1SZ+WK1SZ+WQ2SZ); }
        else                             { src = Wv;  off = wo - WCATSZ; }
    } else {
        const int wo = i4 - (XSZ + WCATSZ + WVSZ);
        src = Wo; off = wo; dh = g_woh; dl = g_wol; dsto = wo;
    }

    const float4 v4 = *reinterpret_cast<const float4*>(&src[off]);
    float vv[4] = {v4.x, v4.y, v4.z, v4.w};
    uint32_t hs[2], ls[2];
    #pragma unroll
    for (int p = 0; p < 2; p++) {
        __nv_bfloat162 hp = __floats2bfloat162_rn(vv[2*p], vv[2*p+1]);
        hs[p] = *reinterpret_cast<uint32_t*>(&hp);
        float r0 = vv[2*p]   - __bfloat162float(hp.x);
        float r1 = vv[2*p+1] - __bfloat162float(hp.y);
        ls[p] = pack_bf16(r0, r1);
    }
    *reinterpret_cast<uint2*>(&dh[dsto]) = make_uint2(hs[0], hs[1]);
    *reinterpret_cast<uint2*>(&dl[dsto]) = make_uint2(ls[0], ls[1]);
}

// ---------------------------------------------------------------------------
// bf16x3 NT GEMM, cp.async double-buffered, 2 CTAs/SM
// ---------------------------------------------------------------------------
#define TM 128
#define TN 128
#define TKC 32
#define GT 256
#define SPAD 40
#define OPB   10240u
#define BUFB  (4u*OPB)
#define GEMM_SMEM_BYTES (2*BUFB)

__global__ __launch_bounds__(GT, 2)
void gemm_bf16x3(const __nv_bfloat16* __restrict__ Ahi,
                 const __nv_bfloat16* __restrict__ Alo,
                 const __nv_bfloat16* __restrict__ Bhi,
                 const __nv_bfloat16* __restrict__ Blo,
                 const float* __restrict__ bias,
                 float* __restrict__ C, int Nc, int K)
{
    extern __shared__ __align__(16) char gsm[];
    const uint32_t sbase = smem_u32(gsm);

    const int tid  = threadIdx.x;
    const int wid  = tid >> 5;
    const int lane = tid & 31;
    const int wm   = wid >> 2;
    const int wn   = wid & 3;

    const int m0 = blockIdx.x * TM;
    const int n0 = blockIdx.y * TN;

    float acc[4][4][4] = {};

    const int a_r = lane & 15, a_c = (lane >> 4) * 8;
    const int b_r = (lane & 7) + ((lane >> 4) << 3), b_c = ((lane >> 3) & 1) * 8;

    auto issue = [&](int k0, int buf) {
        const uint32_t bb = sbase + (uint32_t)buf * BUFB;
        #pragma unroll
        for (int i = tid; i < TM * 4; i += GT) {
            const int row = i >> 2, seg = (i & 3) * 8;
            const uint32_t so = (uint32_t)(row * SPAD + seg) * 2;
            const size_t ga = (size_t)(m0 + row) * K + k0 + seg;
            const size_t gb = (size_t)(n0 + row) * K + k0 + seg;
            CP16(bb + 0*OPB + so, Ahi + ga);
            CP16(bb + 1*OPB + so, Alo + ga);
            CP16(bb + 2*OPB + so, Bhi + gb);
            CP16(bb + 3*OPB + so, Blo + gb);
        }
        CP_COMMIT();
    };

    const int nk = K / TKC;
    issue(0, 0);

    for (int k = 0; k < nk; k++) {
        if (k + 1 < nk) { issue((k + 1) * TKC, (k + 1) & 1); CP_WAIT1(); }
        else            { CP_WAIT0(); }
        __syncthreads();

        const uint32_t bb = sbase + (uint32_t)(k & 1) * BUFB;
        const uint32_t uAh = bb, uAl = bb + OPB, uBh = bb + 2*OPB, uBl = bb + 3*OPB;

        #pragma unroll
        for (int kp = 0; kp < 2; kp++) {
            const int kb = kp * 16;
            uint32_t ah[4][4], al[4][4], bh[2][4], bl[2][4];

            #pragma unroll
            for (int mt = 0; mt < 4; mt++) {
                const uint32_t off =
                    (uint32_t)((wm * 64 + mt * 16 + a_r) * SPAD + kb + a_c) * 2;
                ldsm_x4(uAh + off, ah[mt][0], ah[mt][1], ah[mt][2], ah[mt][3]);
                ldsm_x4(uAl + off, al[mt][0], al[mt][1], al[mt][2], al[mt][3]);
            }
            #pragma unroll
            for (int ng = 0; ng < 2; ng++) {
                const uint32_t off =
                    (uint32_t)((wn * 32 + ng * 16 + b_r) * SPAD + kb + b_c) * 2;
                ldsm_x4(uBh + off, bh[ng][0], bh[ng][1], bh[ng][2], bh[ng][3]);
                ldsm_x4(uBl + off, bl[ng][0], bl[ng][1], bl[ng][2], bl[ng][3]);
            }

            #pragma unroll
            for (int mt = 0; mt < 4; mt++) {
                #pragma unroll
                for (int nt = 0; nt < 4; nt++) {
                    const int ng = nt >> 1, hp = (nt & 1) * 2;
                    mma16816(acc[mt][nt], ah[mt][0], ah[mt][1], ah[mt][2], ah[mt][3],
                             bh[ng][hp], bh[ng][hp + 1]);
                    mma16816(acc[mt][nt], ah[mt][0], ah[mt][1], ah[mt][2], ah[mt][3],
                             bl[ng][hp], bl[ng][hp + 1]);
                    mma16816(acc[mt][nt], al[mt][0], al[mt][1], al[mt][2], al[mt][3],
                             bh[ng][hp], bh[ng][hp + 1]);
                }
            }
        }
        __syncthreads();
    }

    const int er = lane >> 2, ec = (lane & 3) * 2;
    #pragma unroll
    for (int mt = 0; mt < 4; mt++) {
        #pragma unroll
        for (int nt = 0; nt < 4; nt++) {
            const int row = m0 + wm * 64 + mt * 16 + er;
            const int col = n0 + wn * 32 + nt * 8 + ec;
            float b0 = bias ? bias[col] : 0.f;
            float b1 = bias ? bias[col + 1] : 0.f;
            C[(size_t)row * Nc + col]           = acc[mt][nt][0] + b0;
            C[(size_t)row * Nc + col + 1]       = acc[mt][nt][1] + b1;
            C[(size_t)(row + 8) * Nc + col]     = acc[mt][nt][2] + b0;
            C[(size_t)(row + 8) * Nc + col + 1] = acc[mt][nt][3] + b1;
        }
    }
}

// ---------------------------------------------------------------------------
// Form qk/kk (reads fused projv, stride PVC)
// ---------------------------------------------------------------------------
__global__ void form_qkkk_kernel()
{
    const int idx = blockIdx.x * blockDim.x + threadIdx.x;
    if (idx >= MROWS * NH) return;
    const int h  = idx % NH;
    const int bn = idx / NH;
    const int b  = bn / SEQ;
    const int n  = bn % SEQ;

    const float* pr = &g_projv[(size_t)bn * PVC];
    float a1[RR1], a2[RR2];
    #pragma unroll
    for (int r = 0; r < RR1; r++) a1[r] = pr[h * RR1 + r];
    #pragma unroll
    for (int r = 0; r < RR2; r++) a2[r] = pr[128 + h * RR2 + r];

    const size_t base = (((size_t)b * NH + h) * SEQ + n) * RKD;

    uint32_t hs[16], ls[16];
    #pragma unroll
    for (int r1 = 0; r1 < RR1; r1++)
        #pragma unroll
        for (int r2 = 0; r2 < RR2; r2 += 2) {
            const int p = (r1 * RR2 + r2) >> 1;
            float v0 = a1[r1] * a2[r2]     * kQSCALE;
            float v1 = a1[r1] * a2[r2 + 1] * kQSCALE;
            __nv_bfloat162 hp = __floats2bfloat162_rn(v0, v1);
            hs[p] = *reinterpret_cast<uint32_t*>(&hp);
            ls[p] = pack_bf16(v0 - __bfloat162float(hp.x), v1 - __bfloat162float(hp.y));
        }
    #pragma unroll
    for (int q = 0; q < 4; q++) {
        *reinterpret_cast<uint4*>(&g_qkh[base + q * 8]) =
            make_uint4(hs[4*q], hs[4*q+1], hs[4*q+2], hs[4*q+3]);
        *reinterpret_cast<uint4*>(&g_qkl[base + q * 8]) =
            make_uint4(ls[4*q], ls[4*q+1], ls[4*q+2], ls[4*q+3]);
    }

    #pragma unroll
    for (int r = 0; r < RR1; r++) a1[r] = pr[64 + h * RR1 + r];
    #pragma unroll
    for (int r = 0; r < RR2; r++) a2[r] = pr[256 + h * RR2 + r];

    #pragma unroll
    for (int r1 = 0; r1 < RR1; r1++)
        #pragma unroll
        for (int r2 = 0; r2 < RR2; r2 += 2) {
            const int p = (r1 * RR2 + r2) >> 1;
            float v0 = a1[r1] * a2[r2];
            float v1 = a1[r1] * a2[r2 + 1];
            __nv_bfloat162 hp = __floats2bfloat162_rn(v0, v1);
            hs[p] = *reinterpret_cast<uint32_t*>(&hp);
            ls[p] = pack_bf16(v0 - __bfloat162float(hp.x), v1 - __bfloat162float(hp.y));
        }
    #pragma unroll
    for (int q = 0; q < 4; q++) {
        *reinterpret_cast<uint4*>(&g_kkh[base + q * 8]) =
            make_uint4(hs[4*q], hs[4*q+1], hs[4*q+2], hs[4*q+3]);
        *reinterpret_cast<uint4*>(&g_kkl[base + q * 8]) =
            make_uint4(ls[4*q], ls[4*q+1], ls[4*q+2], ls[4*q+3]);
    }
}

// ---------------------------------------------------------------------------
// V transpose+split (reads V columns of fused projv)
// ---------------------------------------------------------------------------
__global__ __launch_bounds__(256)
void vt_convert_kernel()
{
    __shared__ float sm[64][65];
    const int bh = blockIdx.y;
    const int b = bh / NH, h = bh % NH;
    const int n0 = blockIdx.x * 64;
    const int tid = threadIdx.x;

    for (int i = tid; i < 64 * 16; i += 256) {
        const int n = i >> 4, seg = (i & 15) * 4;
        const float4 v4 = *reinterpret_cast<const float4*>(
            &g_projv[((size_t)(b * SEQ + n0 + n)) * PVC + PROJC + h * HD + seg]);
        sm[n][seg + 0] = v4.x;
        sm[n][seg + 1] = v4.y;
        sm[n][seg + 2] = v4.z;
        sm[n][seg + 3] = v4.w;
    }
    __syncthreads();

    for (int i = tid; i < 64 * 64; i += 256) {
        const int d = i >> 6, n = i & 63;
        const float v = sm[n][d];
        const __nv_bfloat16 hh = __float2bfloat16(v);
        const size_t o = ((size_t)bh * HD + d) * SEQ + n0 + n;
        g_vth[o] = hh;
        g_vtl[o] = __float2bfloat16(v - __bfloat162float(hh));
    }
}

// ---------------------------------------------------------------------------
// MMA flash attention — compact swizzled smem for 4 CTAs/SM.
// K/Q tiles: dense 64B rows, SW64. V tiles: dense 128B rows, SW128.
// Q overlaid into buffer 1 (consumed to regs before buffer 1's first fill).
// Dynamic smem: 2 x 24576 = 49152 B.
// ---------------------------------------------------------------------------
#define FQ 64
#define FK 64
#define KB_KH   0u
#define KB_KL   4096u
#define KB_VH   8192u
#define KB_VL   16384u
#define KVBUF   24576u
#define ATTN_SMEM_BYTES (2*24576)   // 49152

__global__ __launch_bounds__(128)
void attn_mma_kernel()
{
    extern __shared__ __align__(16) char asmem[];
    const uint32_t sbase = smem_u32(asmem);

    const int bh  = blockIdx.y;
    const int b   = bh / NH, h = bh % NH;
    const int qt  = (gridDim.x - 1) - blockIdx.x;   // LPT
    const int q0  = qt * FQ;
    const int tid = threadIdx.x;
    const int wid = tid >> 5;
    const int lane = tid & 31;

    const __nv_bfloat16* qkh = &g_qkh[(size_t)bh * SEQ * RKD];
    const __nv_bfloat16* qkl = &g_qkl[(size_t)bh * SEQ * RKD];
    const __nv_bfloat16* kkh = &g_kkh[(size_t)bh * SEQ * RKD];
    const __nv_bfloat16* kkl = &g_kkl[(size_t)bh * SEQ * RKD];
    const __nv_bfloat16* vth = &g_vth[(size_t)bh * HD * SEQ];
    const __nv_bfloat16* vtl = &g_vtl[(size_t)bh * HD * SEQ];

    auto issue_kv = [&](int j0, int buf) {
        const uint32_t bb = sbase + (uint32_t)buf * KVBUF;
        #pragma unroll
        for (int i = tid; i < FK * 4; i += 128) {
            const int row = i >> 2, sg = i & 3;
            const uint32_t o = (uint32_t)(row * 64 + sg * 16);
            const uint32_t so = SW64(o);
            CP16(bb + KB_KH + so, kkh + (size_t)(j0 + row) * RKD + sg * 8);
            CP16(bb + KB_KL + so, kkl + (size_t)(j0 + row) * RKD + sg * 8);
        }
        #pragma unroll
        for (int i = tid; i < HD * 8; i += 128) {
            const int row = i >> 3, sg = i & 7;
            const uint32_t o = (uint32_t)(row * 128 + sg * 16);
            const uint32_t so = SW128(o);
            CP16(bb + KB_VH + so, vth + (size_t)row * SEQ + j0 + sg * 8);
            CP16(bb + KB_VL + so, vtl + (size_t)row * SEQ + j0 + sg * 8);
        }
        CP_COMMIT();
    };

    issue_kv(0, 0);
    for (int i = tid; i < FQ * 4; i += 128) {
        const int row = i >> 2, sg = i & 3;
        const uint32_t o = (uint32_t)(row * 64 + sg * 16);
        const uint32_t so = SW64(o);
        *reinterpret_cast<float4*>(asmem + KVBUF + so) =
            *reinterpret_cast<const float4*>(&qkh[(size_t)(q0 + row) * RKD + sg * 8]);
        *reinterpret_cast<float4*>(asmem + KVBUF + 4096 + so) =
            *reinterpret_cast<const float4*>(&qkl[(size_t)(q0 + row) * RKD + sg * 8]);
    }
    __syncthreads();

    const int a_r = lane & 15, a_c = (lane >> 4) * 8;
    const int b_r = (lane & 7) + ((lane >> 4) << 3), b_c = ((lane >> 3) & 1) * 8;

    const uint32_t qxor = (uint32_t)(((a_r * 64) >> 3) & 0x30);
    const uint32_t kxor = (uint32_t)(((b_r * 64) >> 3) & 0x30);
    const uint32_t vxor = (uint32_t)(((b_r * 128) >> 3) & 0x70);

    uint32_t qh[2][4], ql[2][4];
    {
        const uint32_t qb = sbase + KVBUF;
        const uint32_t xl_ = (uint32_t)(wid * 1024 + a_r * 64 + a_c * 2);
        #pragma unroll
        for (int kc = 0; kc < 2; kc++) {
            const uint32_t x = xl_ + kc * 32;
            ldsm_x4(qb + (x ^ qxor),        qh[kc][0], qh[kc][1], qh[kc][2], qh[kc][3]);
            ldsm_x4(qb + 4096 + (x ^ qxor), ql[kc][0], ql[kc][1], ql[kc][2], ql[kc][3]);
        }
    }
    __syncthreads();

    float Od[8][4] = {};
    float m0 = -1e30f, m1 = -1e30f, l0 = 0.f, l1 = 0.f;
    const int myrow = q0 + wid * 16 + (lane >> 2);

    for (int kt = 0; kt <= qt; kt++) {
        const int j0 = kt * FK;

        if (kt < qt) { issue_kv((kt + 1) * FK, (kt + 1) & 1); CP_WAIT1(); }
        else         { CP_WAIT0(); }
        __syncthreads();

        const uint32_t bb = sbase + (uint32_t)(kt & 1) * KVBUF;
        const uint32_t sKh_u = bb + KB_KH, sKl_u = bb + KB_KL;
        const uint32_t sVh_u = bb + KB_VH, sVl_u = bb + KB_VL;

        float S[8][4];
        #pragma unroll
        for (int nt = 0; nt < 8; nt++)
            #pragma unroll
            for (int e = 0; e < 4; e++) S[nt][e] = 0.f;

        const uint32_t kxl = (uint32_t)(b_r * 64 + b_c * 2);
        #pragma unroll
        for (int kc = 0; kc < 2; kc++) {
            #pragma unroll
            for (int g = 0; g < 4; g++) {
                uint32_t kb[4], kl[4];
                const uint32_t x = (uint32_t)(g * 1024) + kxl + kc * 32;
                ldsm_x4(sKh_u + (x ^ kxor), kb[0], kb[1], kb[2], kb[3]);
                ldsm_x4(sKl_u + (x ^ kxor), kl[0], kl[1], kl[2], kl[3]);
                #pragma unroll
                for (int t = 0; t < 2; t++) {
                    const int nt = g * 2 + t, hp = t * 2;
                    mma16816(S[nt], qh[kc][0], qh[kc][1], qh[kc][2], qh[kc][3],
                             kb[hp], kb[hp + 1]);
                    mma16816(S[nt], qh[kc][0], qh[kc][1], qh[kc][2], qh[kc][3],
                             kl[hp], kl[hp + 1]);
                    mma16816(S[nt], ql[kc][0], ql[kc][1], ql[kc][2], ql[kc][3],
                             kb[hp], kb[hp + 1]);
                }
            }
        }

        if (kt == qt) {
            #pragma unroll
            for (int nt = 0; nt < 8; nt++) {
                const int col = j0 + nt * 8 + (lane & 3) * 2;
                if (col     > myrow)     S[nt][0] = -1e30f;
                if (col + 1 > myrow)     S[nt][1] = -1e30f;
                if (col     > myrow + 8) S[nt][2] = -1e30f;
                if (col + 1 > myrow + 8) S[nt][3] = -1e30f;
            }
        }

        float r0 = -1e30f, r1 = -1e30f;
        #pragma unroll
        for (int nt = 0; nt < 8; nt++) {
            r0 = fmaxf(r0, fmaxf(S[nt][0], S[nt][1]));
            r1 = fmaxf(r1, fmaxf(S[nt][2], S[nt][3]));
        }
        r0 = fmaxf(r0, __shfl_xor_sync(0xffffffff, r0, 1));
        r0 = fmaxf(r0, __shfl_xor_sync(0xffffffff, r0, 2));
        r1 = fmaxf(r1, __shfl_xor_sync(0xffffffff, r1, 1));
        r1 = fmaxf(r1, __shfl_xor_sync(0xffffffff, r1, 2));

        const float mn0 = fmaxf(m0, r0), mn1 = fmaxf(m1, r1);
        const float c0 = exp2f(m0 - mn0), c1 = exp2f(m1 - mn1);
        m0 = mn0; m1 = mn1;

        float s0 = 0.f, s1 = 0.f;
        #pragma unroll
        for (int nt = 0; nt < 8; nt++) {
            S[nt][0] = exp2f(S[nt][0] - mn0);
            S[nt][1] = exp2f(S[nt][1] - mn0);
            S[nt][2] = exp2f(S[nt][2] - mn1);
            S[nt][3] = exp2f(S[nt][3] - mn1);
            s0 += S[nt][0] + S[nt][1];
            s1 += S[nt][2] + S[nt][3];
        }
        l0 = l0 * c0 + s0;
        l1 = l1 * c1 + s1;

        #pragma unroll
        for (int nt = 0; nt < 8; nt++) {
            Od[nt][0] *= c0; Od[nt][1] *= c0;
            Od[nt][2] *= c1; Od[nt][3] *= c1;
        }

        const uint32_t vxl = (uint32_t)(b_r * 128 + b_c * 2);
        #pragma unroll
        for (int kc = 0; kc < 4; kc++) {
            uint32_t pa[4], pl[4];
            {
                const float x0 = S[2 * kc][0],     y0 = S[2 * kc][1];
                const float x1 = S[2 * kc][2],     y1 = S[2 * kc][3];
                const float x2 = S[2 * kc + 1][0], y2 = S[2 * kc + 1][1];
                const float x3 = S[2 * kc + 1][2], y3 = S[2 * kc + 1][3];
                pa[0] = pack_bf16(x0, y0); pa[1] = pack_bf16(x1, y1);
                pa[2] = pack_bf16(x2, y2); pa[3] = pack_bf16(x3, y3);
                __nv_bfloat162 h0 = *reinterpret_cast<__nv_bfloat162*>(&pa[0]);
                __nv_bfloat162 h1 = *reinterpret_cast<__nv_bfloat162*>(&pa[1]);
                __nv_bfloat162 h2 = *reinterpret_cast<__nv_bfloat162*>(&pa[2]);
                __nv_bfloat162 h3 = *reinterpret_cast<__nv_bfloat162*>(&pa[3]);
                pl[0] = pack_bf16(x0 - __bfloat162float(h0.x), y0 - __bfloat162float(h0.y));
                pl[1] = pack_bf16(x1 - __bfloat162float(h1.x), y1 - __bfloat162float(h1.y));
                pl[2] = pack_bf16(x2 - __bfloat162float(h2.x), y2 - __bfloat162float(h2.y));
                pl[3] = pack_bf16(x3 - __bfloat162float(h3.x), y3 - __bfloat162float(h3.y));
            }
            #pragma unroll
            for (int g = 0; g < 4; g++) {
                uint32_t vb[4], vl[4];
                const uint32_t x = (uint32_t)(g * 2048) + vxl + kc * 32;
                ldsm_x4(sVh_u + (x ^ vxor), vb[0], vb[1], vb[2], vb[3]);
                ldsm_x4(sVl_u + (x ^ vxor), vl[0], vl[1], vl[2], vl[3]);
                #pragma unroll
                for (int t = 0; t < 2; t++) {
                    const int nt = g * 2 + t, hp = t * 2;
                    mma16816(Od[nt], pa[0], pa[1], pa[2], pa[3], vb[hp], vb[hp + 1]);
                    mma16816(Od[nt], pl[0], pl[1], pl[2], pl[3], vb[hp], vb[hp + 1]);
                    mma16816(Od[nt], pa[0], pa[1], pa[2], pa[3], vl[hp], vl[hp + 1]);
                }
            }
        }
        __syncthreads();
    }

    l0 += __shfl_xor_sync(0xffffffff, l0, 1);
    l0 += __shfl_xor_sync(0xffffffff, l0, 2);
    l1 += __shfl_xor_sync(0xffffffff, l1, 1);
    l1 += __shfl_xor_sync(0xffffffff, l1, 2);
    const float i0 = 1.f / l0, i1 = 1.f / l1;

    const size_t base0 = ((size_t)(b * SEQ + myrow)) * CH + h * HD;
    const size_t base1 = base0 + (size_t)8 * CH;
    #pragma unroll
    for (int nt = 0; nt < 8; nt++) {
        const int d = nt * 8 + (lane & 3) * 2;
        float v;
        __nv_bfloat16 hh;
        v = Od[nt][0] * i0; hh = __float2bfloat16(v);
        g_aoh[base0 + d]     = hh; g_aol[base0 + d]     = __float2bfloat16(v - __bfloat162float(hh));
        v = Od[nt][1] * i0; hh = __float2bfloat16(v);
        g_aoh[base0 + d + 1] = hh; g_aol[base0 + d + 1] = __float2bfloat16(v - __bfloat162float(hh));
        v = Od[nt][2] * i1; hh = __float2bfloat16(v);
        g_aoh[base1 + d]     = hh; g_aol[base1 + d]     = __float2bfloat16(v - __bfloat162float(hh));
        v = Od[nt][3] * i1; hh = __float2bfloat16(v);
        g_aoh[base1 + d + 1] = hh; g_aol[base1 + d + 1] = __float2bfloat16(v - __bfloat162float(hh));
    }
}

// ---------------------------------------------------------------------------
// Launch
// ---------------------------------------------------------------------------
extern "C" void kernel_launch(void* const* d_in, const int* in_sizes, int n_in,
                              void* d_out, int out_size)
{
    const float* x   = (const float*)d_in[0];
    const float* Wq1 = (const float*)d_in[1];
    const float* Wk1 = (const float*)d_in[2];
    const float* Wq2 = (const float*)d_in[3];
    const float* Wk2 = (const float*)d_in[4];
    const float* Wv  = (const float*)d_in[5];
    const float* Wo  = (const float*)d_in[6];
    const float* bo  = (const float*)d_in[7];
    float* out = (float*)d_out;

    cudaFuncSetAttribute(gemm_bf16x3, cudaFuncAttributeMaxDynamicSharedMemorySize,
                         GEMM_SMEM_BYTES);
    cudaFuncSetAttribute(attn_mma_kernel, cudaFuncAttributeMaxDynamicSharedMemorySize,
                         ATTN_SMEM_BYTES);

    __nv_bfloat16 *xh, *xl, *wcvh, *wcvl, *woh, *wol, *aoh, *aol;
    float *projv;
    cudaGetSymbolAddress((void**)&xh,   g_xh);
    cudaGetSymbolAddress((void**)&xl,   g_xl);
    cudaGetSymbolAddress((void**)&wcvh, g_wcvh);
    cudaGetSymbolAddress((void**)&wcvl, g_wcvl);
    cudaGetSymbolAddress((void**)&woh,  g_woh);
    cudaGetSymbolAddress((void**)&wol,  g_wol);
    cudaGetSymbolAddress((void**)&aoh,  g_aoh);
    cudaGetSymbolAddress((void**)&aol,  g_aol);
    cudaGetSymbolAddress((void**)&projv, g_projv);

    const int SB = 256;
    mega_split_kernel<<<(TOTSPLIT/4 + SB-1)/SB, SB>>>(x, Wq1, Wk1, Wq2, Wk2, Wv, Wo);

    gemm_bf16x3<<<dim3(MROWS/TM, PVC/TN), GT, GEMM_SMEM_BYTES>>>(
        xh, xl, wcvh, wcvl, nullptr, projv, PVC, CH);

    form_qkkk_kernel<<<(MROWS*NH + SB-1)/SB, SB>>>();
    vt_convert_kernel<<<dim3(SEQ/64, BH), 256>>>();

    attn_mma_kernel<<<dim3(SEQ/FQ, BH), 128, ATTN_SMEM_BYTES>>>();

    gemm_bf16x3<<<dim3(MROWS/TM, CH/TN), GT, GEMM_SMEM_BYTES>>>(
        aoh, aol, woh, wol, bo, out, CH, CH);
}